// round 1
// baseline (speedup 1.0000x reference)
#include <cuda_runtime.h>
#include <cuda_bf16.h>
#include <math.h>

// ---- problem constants ----
#define BB    16
#define NN    1024          // 4*NTOK tokens
#define NTOK  256
#define HID   64
#define NH    4
#define HD    16
#define MLPH  128
#define FF    256
#define MAXF  512
#define LN_EPS 1e-5f

__constant__ int c_feat[4] = {64, 128, 256, 512};

// ---- scratch (device globals, no allocation) ----
__device__ float g_x[BB * NN * HID];        // token embeddings / residual stream
__device__ float g_q[BB * NH * NN * HD];    // pre-scaled q
__device__ float g_k[BB * NH * NN * HD];
__device__ float g_v[BB * NH * NN * HD];
__device__ float g_o[BB * NH * NN * HD];    // attention out per head
__device__ float g_esum[BB * NN];           // per-token energy partials

__device__ __forceinline__ float dot4(float4 a, float4 b) {
    return a.x * b.x + a.y * b.y + a.z * b.z + a.w * b.w;
}

// ============================================================
// 1. Input MLP per segment: x = tanh(y_seg @ W1^T + b1) @ W2^T + b2
//    one block per token, 128 threads
// ============================================================
__global__ void k_input(const float* __restrict__ y,
                        const float* __restrict__ w1_0, const float* __restrict__ w1_1,
                        const float* __restrict__ w1_2, const float* __restrict__ w1_3,
                        const float* __restrict__ b1,   const float* __restrict__ w2,
                        const float* __restrict__ b2) {
    __shared__ __align__(16) float sy[MAXF];
    __shared__ __align__(16) float sh[MLPH];
    int blk = blockIdx.x;                 // 0..16383 (b*1024 + n)
    int n   = blk & 1023;
    int seg = n >> 8;
    int F   = c_feat[seg];
    const float* w1 = (seg == 0) ? w1_0 : (seg == 1) ? w1_1 : (seg == 2) ? w1_2 : w1_3;
    const float* yrow = y + (size_t)blk * MAXF;
    int t = threadIdx.x;
    for (int f = t; f < F; f += 128) sy[f] = yrow[f];
    __syncthreads();

    // hidden (128 units)
    {
        const float4* wr  = (const float4*)(w1 + t * F);
        const float4* sy4 = (const float4*)sy;
        float acc = b1[seg * MLPH + t];
        int F4 = F >> 2;
        #pragma unroll 4
        for (int f = 0; f < F4; f++) acc += dot4(sy4[f], wr[f]);
        sh[t] = tanhf(acc);
    }
    __syncthreads();

    if (t < HID) {
        const float4* wr  = (const float4*)(w2 + (seg * HID + t) * MLPH);
        const float4* sh4 = (const float4*)sh;
        float acc = b2[seg * HID + t];
        #pragma unroll
        for (int f = 0; f < MLPH / 4; f++) acc += dot4(sh4[f], wr[f]);
        g_x[(size_t)blk * HID + t] = acc;
    }
}

// ============================================================
// 2. QKV projection: one block per token, 192 threads
//    writes q (pre-scaled by 1/sqrt(HD)), k, v in [B][H][N][HD] layout
// ============================================================
__global__ void k_qkv(int l, const float* __restrict__ qkv_w, const float* __restrict__ qkv_b) {
    __shared__ __align__(16) float sx[HID];
    int blk = blockIdx.x;
    int b = blk >> 10, n = blk & 1023;
    int t = threadIdx.x;                   // 0..191
    if (t < HID) sx[t] = g_x[(size_t)blk * HID + t];
    __syncthreads();

    const float4* wr  = (const float4*)(qkv_w + ((size_t)l * 192 + t) * HID);
    const float4* sx4 = (const float4*)sx;
    float acc = qkv_b[l * 192 + t];
    #pragma unroll
    for (int f = 0; f < HID / 4; f++) acc += dot4(sx4[f], wr[f]);

    int kind = t >> 6;                     // 0=q 1=k 2=v
    int w_   = t & 63;
    int h    = w_ >> 4;
    int d    = w_ & 15;
    float* dst = (kind == 0) ? g_q : (kind == 1) ? g_k : g_v;
    if (kind == 0) acc *= 0.25f;           // 1/sqrt(16)
    dst[(((size_t)b * NH + h) * NN + n) * HD + d] = acc;
}

// ============================================================
// 3. Attention: one block per (b,h, 256-query chunk), 256 threads
//    per-thread online softmax, K/V staged in smem (256-key chunks)
// ============================================================
__global__ void k_attn() {
    __shared__ __align__(16) float sk[256 * HD];
    __shared__ __align__(16) float sv[256 * HD];
    int bh = blockIdx.x >> 2;              // 0..63  (b*NH + h)
    int qc = blockIdx.x & 3;
    int t  = threadIdx.x;
    int qi = qc * 256 + t;
    size_t base = (size_t)bh * NN * HD;

    const float4* qp = (const float4*)(g_q + base + (size_t)qi * HD);
    float4 q0 = qp[0], q1 = qp[1], q2 = qp[2], q3 = qp[3];

    float m = -1e30f, l = 0.f;
    float acc[HD];
    #pragma unroll
    for (int d = 0; d < HD; d++) acc[d] = 0.f;

    for (int kc = 0; kc < 4; kc++) {
        const float4* kg = (const float4*)(g_k + base + (size_t)kc * 256 * HD);
        const float4* vg = (const float4*)(g_v + base + (size_t)kc * 256 * HD);
        float4* sk4 = (float4*)sk;
        float4* sv4 = (float4*)sv;
        #pragma unroll
        for (int i = 0; i < 4; i++) {
            sk4[t + i * 256] = kg[t + i * 256];
            sv4[t + i * 256] = vg[t + i * 256];
        }
        __syncthreads();

        for (int j = 0; j < 256; j++) {
            const float4* kr = (const float4*)(sk + j * HD);
            float s = dot4(q0, kr[0]) + dot4(q1, kr[1]) + dot4(q2, kr[2]) + dot4(q3, kr[3]);
            const float* vr = sv + j * HD;
            if (s <= m) {                  // common path after warm-up
                float p = __expf(s - m);
                l += p;
                #pragma unroll
                for (int d = 0; d < HD; d++) acc[d] += p * vr[d];
            } else {
                float corr = __expf(m - s);
                l = l * corr + 1.f;
                #pragma unroll
                for (int d = 0; d < HD; d++) acc[d] = acc[d] * corr + vr[d];
                m = s;
            }
        }
        __syncthreads();
    }

    float inv = 1.f / l;
    float* op = g_o + base + (size_t)qi * HD;
    #pragma unroll
    for (int d = 0; d < HD; d++) op[d] = acc[d] * inv;
}

// ============================================================
// 4. Attn out-proj + residual + LayerNorm1: one block per token, 64 threads
// ============================================================
__global__ void k_projln(int l, const float* __restrict__ W, const float* __restrict__ bias,
                         const float* __restrict__ lnw, const float* __restrict__ lnb) {
    __shared__ __align__(16) float so[HID];
    __shared__ float red[4];
    int blk = blockIdx.x;
    int b = blk >> 10, n = blk & 1023;
    int c = threadIdx.x;                   // 0..63
    so[c] = g_o[(((size_t)b * NH + (c >> 4)) * NN + n) * HD + (c & 15)];
    __syncthreads();

    const float4* wr  = (const float4*)(W + ((size_t)l * HID + c) * HID);
    const float4* so4 = (const float4*)so;
    float acc = bias[l * HID + c];
    #pragma unroll
    for (int f = 0; f < HID / 4; f++) acc += dot4(so4[f], wr[f]);

    float val = g_x[(size_t)blk * HID + c] + acc;

    float s1 = val, s2 = val * val;
    #pragma unroll
    for (int off = 16; off > 0; off >>= 1) {
        s1 += __shfl_xor_sync(0xffffffff, s1, off);
        s2 += __shfl_xor_sync(0xffffffff, s2, off);
    }
    if ((c & 31) == 0) { red[(c >> 5) * 2] = s1; red[(c >> 5) * 2 + 1] = s2; }
    __syncthreads();
    float sum = red[0] + red[2], sumsq = red[1] + red[3];
    float mean = sum * (1.f / 64.f);
    float var  = sumsq * (1.f / 64.f) - mean * mean;
    float r = rsqrtf(var + LN_EPS);
    g_x[(size_t)blk * HID + c] = (val - mean) * r * lnw[l * HID + c] + lnb[l * HID + c];
}

// ============================================================
// 5. FFN + residual + LayerNorm2: one block per token, 256 threads
// ============================================================
__global__ void k_ffnln(int l, const float* __restrict__ w1, const float* __restrict__ b1,
                        const float* __restrict__ w2, const float* __restrict__ b2,
                        const float* __restrict__ lnw, const float* __restrict__ lnb) {
    __shared__ __align__(16) float sx[HID];
    __shared__ __align__(16) float sh[FF];
    __shared__ float r1[8], r2[8];
    int blk = blockIdx.x;
    int t = threadIdx.x;                   // 0..255
    if (t < HID) sx[t] = g_x[(size_t)blk * HID + t];
    __syncthreads();

    {
        const float4* wr  = (const float4*)(w1 + ((size_t)l * FF + t) * HID);
        const float4* sx4 = (const float4*)sx;
        float acc = b1[l * FF + t];
        #pragma unroll
        for (int f = 0; f < HID / 4; f++) acc += dot4(sx4[f], wr[f]);
        sh[t] = fmaxf(acc, 0.f);
    }
    __syncthreads();

    float outval = 0.f;
    if (t < HID) {
        const float4* wr  = (const float4*)(w2 + ((size_t)l * HID + t) * FF);
        const float4* sh4 = (const float4*)sh;
        float acc = b2[l * HID + t];
        #pragma unroll 8
        for (int f = 0; f < FF / 4; f++) acc += dot4(sh4[f], wr[f]);
        outval = sx[t] + acc;
    }

    float s1 = (t < HID) ? outval : 0.f;
    float s2 = s1 * s1;
    #pragma unroll
    for (int off = 16; off > 0; off >>= 1) {
        s1 += __shfl_xor_sync(0xffffffff, s1, off);
        s2 += __shfl_xor_sync(0xffffffff, s2, off);
    }
    if ((t & 31) == 0) { r1[t >> 5] = s1; r2[t >> 5] = s2; }
    __syncthreads();
    if (t < HID) {
        float sum = r1[0] + r1[1], sumsq = r2[0] + r2[1];
        float mean = sum * (1.f / 64.f);
        float var  = sumsq * (1.f / 64.f) - mean * mean;
        float r = rsqrtf(var + LN_EPS);
        g_x[(size_t)blk * HID + t] = (outval - mean) * r * lnw[l * HID + t] + lnb[l * HID + t];
    }
}

// ============================================================
// 6. Output head per segment + per-token energy partial
//    one block per token, 128 threads
// ============================================================
__global__ void k_out(float* __restrict__ out,
                      const float* __restrict__ ow1, const float* __restrict__ ob1,
                      const float* __restrict__ w2_0, const float* __restrict__ w2_1,
                      const float* __restrict__ w2_2, const float* __restrict__ w2_3,
                      const float* __restrict__ b2_0, const float* __restrict__ b2_1,
                      const float* __restrict__ b2_2, const float* __restrict__ b2_3) {
    __shared__ __align__(16) float sx[HID];
    __shared__ __align__(16) float sh[MLPH];
    __shared__ float red[4];
    int blk = blockIdx.x;
    int n = blk & 1023;
    int seg = n >> 8;
    int F = c_feat[seg];
    const float* w2 = (seg == 0) ? w2_0 : (seg == 1) ? w2_1 : (seg == 2) ? w2_2 : w2_3;
    const float* b2 = (seg == 0) ? b2_0 : (seg == 1) ? b2_1 : (seg == 2) ? b2_2 : b2_3;
    int t = threadIdx.x;                   // 0..127
    if (t < HID) sx[t] = g_x[(size_t)blk * HID + t];
    __syncthreads();

    {
        const float4* wr  = (const float4*)(ow1 + ((size_t)seg * MLPH + t) * HID);
        const float4* sx4 = (const float4*)sx;
        float acc = ob1[seg * MLPH + t];
        #pragma unroll
        for (int f = 0; f < HID / 4; f++) acc += dot4(sx4[f], wr[f]);
        sh[t] = tanhf(acc);
    }
    __syncthreads();

    float* orow = out + (size_t)blk * MAXF;
    float sq = 0.f;
    for (int f = t; f < MAXF; f += 128) {
        float vout = 0.f;
        if (f < F) {
            const float4* wr  = (const float4*)(w2 + (size_t)f * MLPH);
            const float4* sh4 = (const float4*)sh;
            float a = b2[f];
            #pragma unroll 8
            for (int i = 0; i < MLPH / 4; i++) a += dot4(sh4[i], wr[i]);
            vout = a;
            sq += a * a;
        }
        orow[f] = vout;
    }

    // deterministic per-token partial
    #pragma unroll
    for (int off = 16; off > 0; off >>= 1) sq += __shfl_xor_sync(0xffffffff, sq, off);
    if ((t & 31) == 0) red[t >> 5] = sq;
    __syncthreads();
    if (t == 0) g_esum[blk] = red[0] + red[1] + red[2] + red[3];
}

// ============================================================
// 7. Energy reduce: one block per batch, 128 threads (deterministic)
// ============================================================
__global__ void k_energy(float* __restrict__ e) {
    __shared__ float red[4];
    int b = blockIdx.x;
    int t = threadIdx.x;
    float s = 0.f;
    for (int i = t; i < NN; i += 128) s += g_esum[b * NN + i];
    #pragma unroll
    for (int off = 16; off > 0; off >>= 1) s += __shfl_xor_sync(0xffffffff, s, off);
    if ((t & 31) == 0) red[t >> 5] = s;
    __syncthreads();
    if (t == 0) e[b] = 0.5f * (red[0] + red[1] + red[2] + red[3]);
}

// ============================================================
extern "C" void kernel_launch(void* const* d_in, const int* in_sizes, int n_in,
                              void* d_out, int out_size) {
    const float* y      = (const float*)d_in[1];
    const float* in_w1_0 = (const float*)d_in[3];
    const float* in_w1_1 = (const float*)d_in[4];
    const float* in_w1_2 = (const float*)d_in[5];
    const float* in_w1_3 = (const float*)d_in[6];
    const float* out_w2_0 = (const float*)d_in[7];
    const float* out_w2_1 = (const float*)d_in[8];
    const float* out_w2_2 = (const float*)d_in[9];
    const float* out_w2_3 = (const float*)d_in[10];
    const float* out_b2_0 = (const float*)d_in[11];
    const float* out_b2_1 = (const float*)d_in[12];
    const float* out_b2_2 = (const float*)d_in[13];
    const float* out_b2_3 = (const float*)d_in[14];
    const float* in_b1  = (const float*)d_in[15];
    const float* in_w2  = (const float*)d_in[16];
    const float* in_b2  = (const float*)d_in[17];
    const float* out_w1 = (const float*)d_in[18];
    const float* out_b1 = (const float*)d_in[19];
    const float* qkv_w  = (const float*)d_in[20];
    const float* qkv_b  = (const float*)d_in[21];
    const float* attn_out_w = (const float*)d_in[22];
    const float* attn_out_b = (const float*)d_in[23];
    const float* ln1_w  = (const float*)d_in[24];
    const float* ln1_b  = (const float*)d_in[25];
    const float* ffn_w1 = (const float*)d_in[26];
    const float* ffn_b1 = (const float*)d_in[27];
    const float* ffn_w2 = (const float*)d_in[28];
    const float* ffn_b2 = (const float*)d_in[29];
    const float* ln2_w  = (const float*)d_in[30];
    const float* ln2_b  = (const float*)d_in[31];

    float* out = (float*)d_out;
    float* energy = out + (size_t)BB * NN * MAXF;

    const int NTOK_TOTAL = BB * NN;   // 16384

    k_input<<<NTOK_TOTAL, 128>>>(y, in_w1_0, in_w1_1, in_w1_2, in_w1_3, in_b1, in_w2, in_b2);

    for (int l = 0; l < 2; l++) {
        k_qkv<<<NTOK_TOTAL, 192>>>(l, qkv_w, qkv_b);
        k_attn<<<BB * NH * 4, 256>>>();
        k_projln<<<NTOK_TOTAL, 64>>>(l, attn_out_w, attn_out_b, ln1_w, ln1_b);
        k_ffnln<<<NTOK_TOTAL, 256>>>(l, ffn_w1, ffn_b1, ffn_w2, ffn_b2, ln2_w, ln2_b);
    }

    k_out<<<NTOK_TOTAL, 128>>>(out, out_w1, out_b1,
                               out_w2_0, out_w2_1, out_w2_2, out_w2_3,
                               out_b2_0, out_b2_1, out_b2_2, out_b2_3);
    k_energy<<<BB, 128>>>(energy);
}

// round 2
// speedup vs baseline: 2.2172x; 2.2172x over previous
#include <cuda_runtime.h>
#include <cuda_bf16.h>
#include <math.h>

#define BB    16
#define NN    1024
#define HID   64
#define NH    4
#define HD    16
#define MLPH  128
#define FF    256
#define MAXF  512
#define LN_EPS 1e-5f

__constant__ int c_feat[4] = {64, 128, 256, 512};

__device__ float g_x[BB * NN * HID];
__device__ float g_q[BB * NH * NN * HD];
__device__ float g_k[BB * NH * NN * HD];
__device__ float g_v[BB * NH * NN * HD];
__device__ float g_o[BB * NH * NN * HD];
__device__ float g_esum[BB * NN];

__device__ __forceinline__ float dot4(float4 a, float4 b) {
    return a.x * b.x + a.y * b.y + a.z * b.z + a.w * b.w;
}
__device__ __forceinline__ float4 ldg4(const float4* p) { return __ldg(p); }

// ============================================================
// 1. Input MLP: 8 tokens per block, 256 threads
// ============================================================
__global__ __launch_bounds__(256) void k_input(
        const float* __restrict__ y,
        const float* __restrict__ w1_0, const float* __restrict__ w1_1,
        const float* __restrict__ w1_2, const float* __restrict__ w1_3,
        const float* __restrict__ b1,   const float* __restrict__ w2,
        const float* __restrict__ b2) {
    __shared__ __align__(16) float sy[8 * MAXF];
    __shared__ __align__(16) float sh[8 * MLPH];
    int tok0 = blockIdx.x * 8;
    int n0   = tok0 & 1023;
    int seg  = n0 >> 8;
    int F    = 64 << seg;
    int F4   = F >> 2;
    int sft  = 4 + seg;               // F4 = 16<<seg
    const float* w1 = (seg == 0) ? w1_0 : (seg == 1) ? w1_1 : (seg == 2) ? w1_2 : w1_3;
    int t = threadIdx.x;

    // stage y[8][F] (compact rows)
    {
        const float4* yg = (const float4*)y;
        float4* sy4 = (float4*)sy;
        for (int idx = t; idx < 8 * F4; idx += 256) {
            int tt = idx >> sft, f4 = idx & (F4 - 1);
            sy4[tt * F4 + f4] = yg[(size_t)(tok0 + tt) * (MAXF / 4) + f4];
        }
    }
    __syncthreads();

    // phase 1: h[8][128] = tanh(y @ w1^T + b1); 2 reps x 128 h, 4 tokens each
    {
        int rep = t >> 7, h = t & 127;
        const float4* wr = (const float4*)(w1 + (size_t)h * F);
        float bi = b1[seg * MLPH + h];
        float acc0 = bi, acc1 = bi, acc2 = bi, acc3 = bi;
        const float4* a0 = (const float4*)sy + (4 * rep + 0) * F4;
        const float4* a1 = (const float4*)sy + (4 * rep + 1) * F4;
        const float4* a2 = (const float4*)sy + (4 * rep + 2) * F4;
        const float4* a3 = (const float4*)sy + (4 * rep + 3) * F4;
        #pragma unroll 4
        for (int k = 0; k < F4; k++) {
            float4 wt = ldg4(wr + k);
            acc0 += dot4(a0[k], wt);
            acc1 += dot4(a1[k], wt);
            acc2 += dot4(a2[k], wt);
            acc3 += dot4(a3[k], wt);
        }
        sh[(4 * rep + 0) * MLPH + h] = tanhf(acc0);
        sh[(4 * rep + 1) * MLPH + h] = tanhf(acc1);
        sh[(4 * rep + 2) * MLPH + h] = tanhf(acc2);
        sh[(4 * rep + 3) * MLPH + h] = tanhf(acc3);
    }
    __syncthreads();

    // phase 2: x[8][64] = h @ w2^T + b2; 4 reps x 64 c, 2 tokens each
    {
        int rep = t >> 6, c = t & 63;
        const float4* wr = (const float4*)(w2 + ((size_t)seg * HID + c) * MLPH);
        float bi = b2[seg * HID + c];
        float acc0 = bi, acc1 = bi;
        const float4* a0 = (const float4*)sh + (2 * rep + 0) * (MLPH / 4);
        const float4* a1 = (const float4*)sh + (2 * rep + 1) * (MLPH / 4);
        #pragma unroll
        for (int k = 0; k < MLPH / 4; k++) {
            float4 wt = ldg4(wr + k);
            acc0 += dot4(a0[k], wt);
            acc1 += dot4(a1[k], wt);
        }
        g_x[(size_t)(tok0 + 2 * rep + 0) * HID + c] = acc0;
        g_x[(size_t)(tok0 + 2 * rep + 1) * HID + c] = acc1;
    }
}

// ============================================================
// 2. QKV: 8 tokens per block, 192 threads (one per output)
// ============================================================
__global__ __launch_bounds__(192) void k_qkv(int l, const float* __restrict__ qkv_w,
                                             const float* __restrict__ qkv_b) {
    __shared__ __align__(16) float sx[8 * HID];
    int tok0 = blockIdx.x * 8;
    int b = tok0 >> 10, n0 = tok0 & 1023;
    int t = threadIdx.x;
    for (int idx = t; idx < 8 * HID; idx += 192)
        sx[idx] = g_x[(size_t)tok0 * HID + idx];
    __syncthreads();

    const float4* wr = (const float4*)(qkv_w + ((size_t)l * 192 + t) * HID);
    float acc[8];
    float bi = qkv_b[l * 192 + t];
    #pragma unroll
    for (int j = 0; j < 8; j++) acc[j] = bi;
    #pragma unroll
    for (int k = 0; k < HID / 4; k++) {
        float4 wt = ldg4(wr + k);
        #pragma unroll
        for (int j = 0; j < 8; j++)
            acc[j] += dot4(((const float4*)sx)[j * (HID / 4) + k], wt);
    }
    int kind = t >> 6, w_ = t & 63, h = w_ >> 4, d = w_ & 15;
    float* dst = (kind == 0) ? g_q : (kind == 1) ? g_k : g_v;
    float scale = (kind == 0) ? 0.25f : 1.0f;
    size_t base = (((size_t)b * NH + h) * NN + n0) * HD + d;
    #pragma unroll
    for (int j = 0; j < 8; j++) dst[base + (size_t)j * HD] = acc[j] * scale;
}

// ============================================================
// 3. Attention: 128 threads, 2 queries each (256 q / block)
// ============================================================
__global__ __launch_bounds__(128) void k_attn() {
    __shared__ __align__(16) float sk[256 * HD];
    __shared__ __align__(16) float sv[256 * HD];
    int bh = blockIdx.x >> 2;
    int qc = blockIdx.x & 3;
    int t  = threadIdx.x;
    size_t base = (size_t)bh * NN * HD;
    int qa = qc * 256 + t, qb = qa + 128;

    const float4* qpa = (const float4*)(g_q + base + (size_t)qa * HD);
    const float4* qpb = (const float4*)(g_q + base + (size_t)qb * HD);
    float4 qa0 = qpa[0], qa1 = qpa[1], qa2 = qpa[2], qa3 = qpa[3];
    float4 qb0 = qpb[0], qb1 = qpb[1], qb2 = qpb[2], qb3 = qpb[3];

    float ma = -1e30f, la = 0.f, mb = -1e30f, lb = 0.f;
    float aa[HD], ab[HD];
    #pragma unroll
    for (int d = 0; d < HD; d++) { aa[d] = 0.f; ab[d] = 0.f; }

    for (int kc = 0; kc < 4; kc++) {
        const float4* kg = (const float4*)(g_k + base + (size_t)kc * 256 * HD);
        const float4* vg = (const float4*)(g_v + base + (size_t)kc * 256 * HD);
        float4* sk4 = (float4*)sk;
        float4* sv4 = (float4*)sv;
        #pragma unroll
        for (int i = 0; i < 8; i++) {
            sk4[t + i * 128] = kg[t + i * 128];
            sv4[t + i * 128] = vg[t + i * 128];
        }
        __syncthreads();

        for (int j = 0; j < 256; j++) {
            const float4* kr = (const float4*)(sk + j * HD);
            float4 k0 = kr[0], k1 = kr[1], k2 = kr[2], k3 = kr[3];
            const float4* vr = (const float4*)(sv + j * HD);
            float4 v0 = vr[0], v1 = vr[1], v2 = vr[2], v3 = vr[3];
            float sa = dot4(qa0, k0) + dot4(qa1, k1) + dot4(qa2, k2) + dot4(qa3, k3);
            float sb = dot4(qb0, k0) + dot4(qb1, k1) + dot4(qb2, k2) + dot4(qb3, k3);
            const float* vf = (const float*)&v0;   // contiguous v0..v3 in regs
            float vv[HD] = {v0.x,v0.y,v0.z,v0.w, v1.x,v1.y,v1.z,v1.w,
                            v2.x,v2.y,v2.z,v2.w, v3.x,v3.y,v3.z,v3.w};
            (void)vf;
            if (sa <= ma) {
                float p = __expf(sa - ma);
                la += p;
                #pragma unroll
                for (int d = 0; d < HD; d++) aa[d] += p * vv[d];
            } else {
                float corr = __expf(ma - sa);
                la = la * corr + 1.f;
                #pragma unroll
                for (int d = 0; d < HD; d++) aa[d] = aa[d] * corr + vv[d];
                ma = sa;
            }
            if (sb <= mb) {
                float p = __expf(sb - mb);
                lb += p;
                #pragma unroll
                for (int d = 0; d < HD; d++) ab[d] += p * vv[d];
            } else {
                float corr = __expf(mb - sb);
                lb = lb * corr + 1.f;
                #pragma unroll
                for (int d = 0; d < HD; d++) ab[d] = ab[d] * corr + vv[d];
                mb = sb;
            }
        }
        __syncthreads();
    }
    float ia = 1.f / la, ib = 1.f / lb;
    float* opa = g_o + base + (size_t)qa * HD;
    float* opb = g_o + base + (size_t)qb * HD;
    #pragma unroll
    for (int d = 0; d < HD; d++) { opa[d] = aa[d] * ia; opb[d] = ab[d] * ib; }
}

// ============================================================
// 4. Out-proj + residual + LN1: 8 tokens / block, 256 threads
// ============================================================
__global__ __launch_bounds__(256) void k_projln(int l, const float* __restrict__ W,
        const float* __restrict__ bias, const float* __restrict__ lnw,
        const float* __restrict__ lnb) {
    __shared__ __align__(16) float so[8 * HID];
    __shared__ float sval[8 * 66];
    int tok0 = blockIdx.x * 8;
    int b = tok0 >> 10, n0 = tok0 & 1023;
    int t = threadIdx.x;

    for (int idx = t; idx < 8 * HID; idx += 256) {
        int tt = idx >> 6, c = idx & 63;
        so[idx] = g_o[(((size_t)b * NH + (c >> 4)) * NN + n0 + tt) * HD + (c & 15)];
    }
    __syncthreads();

    {
        int rep = t >> 6, c = t & 63;
        const float4* wr = (const float4*)(W + ((size_t)l * HID + c) * HID);
        float bi = bias[l * HID + c];
        float acc0 = bi, acc1 = bi;
        const float4* a0 = (const float4*)so + (2 * rep + 0) * (HID / 4);
        const float4* a1 = (const float4*)so + (2 * rep + 1) * (HID / 4);
        #pragma unroll
        for (int k = 0; k < HID / 4; k++) {
            float4 wt = ldg4(wr + k);
            acc0 += dot4(a0[k], wt);
            acc1 += dot4(a1[k], wt);
        }
        sval[(2 * rep + 0) * 66 + c] = g_x[(size_t)(tok0 + 2 * rep + 0) * HID + c] + acc0;
        sval[(2 * rep + 1) * 66 + c] = g_x[(size_t)(tok0 + 2 * rep + 1) * HID + c] + acc1;
    }
    __syncthreads();

    // LN: warp w handles token w
    int wid = t >> 5, lane = t & 31;
    float va = sval[wid * 66 + lane];
    float vb = sval[wid * 66 + lane + 32];
    float s1 = va + vb, s2 = va * va + vb * vb;
    #pragma unroll
    for (int off = 16; off > 0; off >>= 1) {
        s1 += __shfl_xor_sync(0xffffffff, s1, off);
        s2 += __shfl_xor_sync(0xffffffff, s2, off);
    }
    float mean = s1 * (1.f / 64.f);
    float var  = s2 * (1.f / 64.f) - mean * mean;
    float r = rsqrtf(var + LN_EPS);
    size_t ob = (size_t)(tok0 + wid) * HID;
    g_x[ob + lane]      = (va - mean) * r * lnw[l * HID + lane]      + lnb[l * HID + lane];
    g_x[ob + lane + 32] = (vb - mean) * r * lnw[l * HID + lane + 32] + lnb[l * HID + lane + 32];
}

// ============================================================
// 5. FFN + residual + LN2: 8 tokens / block, 256 threads
// ============================================================
__global__ __launch_bounds__(256) void k_ffnln(int l,
        const float* __restrict__ w1, const float* __restrict__ b1,
        const float* __restrict__ w2, const float* __restrict__ b2,
        const float* __restrict__ lnw, const float* __restrict__ lnb) {
    __shared__ __align__(16) float sx[8 * HID];
    __shared__ __align__(16) float sh[8 * FF];
    __shared__ float sval[8 * 66];
    int tok0 = blockIdx.x * 8;
    int t = threadIdx.x;
    for (int idx = t; idx < 8 * HID; idx += 256)
        sx[idx] = g_x[(size_t)tok0 * HID + idx];
    __syncthreads();

    // phase 1: hidden unit = t, 8 tokens
    {
        const float4* wr = (const float4*)(w1 + ((size_t)l * FF + t) * HID);
        float acc[8];
        float bi = b1[l * FF + t];
        #pragma unroll
        for (int j = 0; j < 8; j++) acc[j] = bi;
        #pragma unroll
        for (int k = 0; k < HID / 4; k++) {
            float4 wt = ldg4(wr + k);
            #pragma unroll
            for (int j = 0; j < 8; j++)
                acc[j] += dot4(((const float4*)sx)[j * (HID / 4) + k], wt);
        }
        #pragma unroll
        for (int j = 0; j < 8; j++) sh[j * FF + t] = fmaxf(acc[j], 0.f);
    }
    __syncthreads();

    // phase 2: 4 reps x 64 c, 2 tokens each, K=256
    {
        int rep = t >> 6, c = t & 63;
        const float4* wr = (const float4*)(w2 + ((size_t)l * HID + c) * FF);
        float bi = b2[l * HID + c];
        float acc0 = bi, acc1 = bi;
        const float4* a0 = (const float4*)sh + (2 * rep + 0) * (FF / 4);
        const float4* a1 = (const float4*)sh + (2 * rep + 1) * (FF / 4);
        #pragma unroll 8
        for (int k = 0; k < FF / 4; k++) {
            float4 wt = ldg4(wr + k);
            acc0 += dot4(a0[k], wt);
            acc1 += dot4(a1[k], wt);
        }
        sval[(2 * rep + 0) * 66 + c] = sx[(2 * rep + 0) * HID + c] + acc0;
        sval[(2 * rep + 1) * 66 + c] = sx[(2 * rep + 1) * HID + c] + acc1;
    }
    __syncthreads();

    int wid = t >> 5, lane = t & 31;
    float va = sval[wid * 66 + lane];
    float vb = sval[wid * 66 + lane + 32];
    float s1 = va + vb, s2 = va * va + vb * vb;
    #pragma unroll
    for (int off = 16; off > 0; off >>= 1) {
        s1 += __shfl_xor_sync(0xffffffff, s1, off);
        s2 += __shfl_xor_sync(0xffffffff, s2, off);
    }
    float mean = s1 * (1.f / 64.f);
    float var  = s2 * (1.f / 64.f) - mean * mean;
    float r = rsqrtf(var + LN_EPS);
    size_t ob = (size_t)(tok0 + wid) * HID;
    g_x[ob + lane]      = (va - mean) * r * lnw[l * HID + lane]      + lnb[l * HID + lane];
    g_x[ob + lane + 32] = (vb - mean) * r * lnw[l * HID + lane + 32] + lnb[l * HID + lane + 32];
}

// ============================================================
// 6. Output head + energy partials: 8 tokens / block, 256 threads
// ============================================================
__global__ __launch_bounds__(256) void k_out(float* __restrict__ out,
        const float* __restrict__ ow1, const float* __restrict__ ob1,
        const float* __restrict__ w2_0, const float* __restrict__ w2_1,
        const float* __restrict__ w2_2, const float* __restrict__ w2_3,
        const float* __restrict__ b2_0, const float* __restrict__ b2_1,
        const float* __restrict__ b2_2, const float* __restrict__ b2_3) {
    __shared__ __align__(16) float sx[8 * HID];
    __shared__ __align__(16) float sh[8 * MLPH];
    __shared__ float red[8][9];
    int tok0 = blockIdx.x * 8;
    int n0 = tok0 & 1023;
    int seg = n0 >> 8;
    int F = 64 << seg;
    const float* w2 = (seg == 0) ? w2_0 : (seg == 1) ? w2_1 : (seg == 2) ? w2_2 : w2_3;
    const float* b2 = (seg == 0) ? b2_0 : (seg == 1) ? b2_1 : (seg == 2) ? b2_2 : b2_3;
    int t = threadIdx.x;
    for (int idx = t; idx < 8 * HID; idx += 256)
        sx[idx] = g_x[(size_t)tok0 * HID + idx];
    __syncthreads();

    // phase 1: 2 reps x 128 h, 4 tokens
    {
        int rep = t >> 7, h = t & 127;
        const float4* wr = (const float4*)(ow1 + ((size_t)seg * MLPH + h) * HID);
        float bi = ob1[seg * MLPH + h];
        float acc[4];
        #pragma unroll
        for (int j = 0; j < 4; j++) acc[j] = bi;
        #pragma unroll
        for (int k = 0; k < HID / 4; k++) {
            float4 wt = ldg4(wr + k);
            #pragma unroll
            for (int j = 0; j < 4; j++)
                acc[j] += dot4(((const float4*)sx)[(4 * rep + j) * (HID / 4) + k], wt);
        }
        #pragma unroll
        for (int j = 0; j < 4; j++) sh[(4 * rep + j) * MLPH + h] = tanhf(acc[j]);
    }
    __syncthreads();

    // phase 2: outputs f = t, t+256; 8 tokens each; K=128
    float sq[8];
    #pragma unroll
    for (int j = 0; j < 8; j++) sq[j] = 0.f;
    for (int f = t; f < MAXF; f += 256) {
        if (f < F) {
            const float4* wr = (const float4*)(w2 + (size_t)f * MLPH);
            float bi = b2[f];
            float acc[8];
            #pragma unroll
            for (int j = 0; j < 8; j++) acc[j] = bi;
            #pragma unroll 4
            for (int k = 0; k < MLPH / 4; k++) {
                float4 wt = ldg4(wr + k);
                #pragma unroll
                for (int j = 0; j < 8; j++)
                    acc[j] += dot4(((const float4*)sh)[j * (MLPH / 4) + k], wt);
            }
            #pragma unroll
            for (int j = 0; j < 8; j++) {
                out[(size_t)(tok0 + j) * MAXF + f] = acc[j];
                sq[j] += acc[j] * acc[j];
            }
        } else {
            #pragma unroll
            for (int j = 0; j < 8; j++)
                out[(size_t)(tok0 + j) * MAXF + f] = 0.f;
        }
    }

    // deterministic energy partials: warp-reduce then cross-warp
    int wid = t >> 5;
    #pragma unroll
    for (int j = 0; j < 8; j++) {
        float s = sq[j];
        #pragma unroll
        for (int off = 16; off > 0; off >>= 1) s += __shfl_xor_sync(0xffffffff, s, off);
        if ((t & 31) == 0) red[wid][j] = s;
    }
    __syncthreads();
    if (t < 8) {
        float s = 0.f;
        #pragma unroll
        for (int w = 0; w < 8; w++) s += red[w][t];
        g_esum[tok0 + t] = s;
    }
}

// ============================================================
// 7. Energy reduce
// ============================================================
__global__ void k_energy(float* __restrict__ e) {
    __shared__ float red[4];
    int b = blockIdx.x;
    int t = threadIdx.x;
    float s = 0.f;
    for (int i = t; i < NN; i += 128) s += g_esum[b * NN + i];
    #pragma unroll
    for (int off = 16; off > 0; off >>= 1) s += __shfl_xor_sync(0xffffffff, s, off);
    if ((t & 31) == 0) red[t >> 5] = s;
    __syncthreads();
    if (t == 0) e[b] = 0.5f * (red[0] + red[1] + red[2] + red[3]);
}

// ============================================================
extern "C" void kernel_launch(void* const* d_in, const int* in_sizes, int n_in,
                              void* d_out, int out_size) {
    const float* y      = (const float*)d_in[1];
    const float* in_w1_0 = (const float*)d_in[3];
    const float* in_w1_1 = (const float*)d_in[4];
    const float* in_w1_2 = (const float*)d_in[5];
    const float* in_w1_3 = (const float*)d_in[6];
    const float* out_w2_0 = (const float*)d_in[7];
    const float* out_w2_1 = (const float*)d_in[8];
    const float* out_w2_2 = (const float*)d_in[9];
    const float* out_w2_3 = (const float*)d_in[10];
    const float* out_b2_0 = (const float*)d_in[11];
    const float* out_b2_1 = (const float*)d_in[12];
    const float* out_b2_2 = (const float*)d_in[13];
    const float* out_b2_3 = (const float*)d_in[14];
    const float* in_b1  = (const float*)d_in[15];
    const float* in_w2  = (const float*)d_in[16];
    const float* in_b2  = (const float*)d_in[17];
    const float* out_w1 = (const float*)d_in[18];
    const float* out_b1 = (const float*)d_in[19];
    const float* qkv_w  = (const float*)d_in[20];
    const float* qkv_b  = (const float*)d_in[21];
    const float* attn_out_w = (const float*)d_in[22];
    const float* attn_out_b = (const float*)d_in[23];
    const float* ln1_w  = (const float*)d_in[24];
    const float* ln1_b  = (const float*)d_in[25];
    const float* ffn_w1 = (const float*)d_in[26];
    const float* ffn_b1 = (const float*)d_in[27];
    const float* ffn_w2 = (const float*)d_in[28];
    const float* ffn_b2 = (const float*)d_in[29];
    const float* ln2_w  = (const float*)d_in[30];
    const float* ln2_b  = (const float*)d_in[31];

    float* out = (float*)d_out;
    float* energy = out + (size_t)BB * NN * MAXF;

    const int NB = (BB * NN) / 8;   // 2048 blocks

    k_input<<<NB, 256>>>(y, in_w1_0, in_w1_1, in_w1_2, in_w1_3, in_b1, in_w2, in_b2);

    for (int l = 0; l < 2; l++) {
        k_qkv<<<NB, 192>>>(l, qkv_w, qkv_b);
        k_attn<<<BB * NH * 4, 128>>>();
        k_projln<<<NB, 256>>>(l, attn_out_w, attn_out_b, ln1_w, ln1_b);
        k_ffnln<<<NB, 256>>>(l, ffn_w1, ffn_b1, ffn_w2, ffn_b2, ln2_w, ln2_b);
    }

    k_out<<<NB, 256>>>(out, out_w1, out_b1,
                       out_w2_0, out_w2_1, out_w2_2, out_w2_3,
                       out_b2_0, out_b2_1, out_b2_2, out_b2_3);
    k_energy<<<BB, 128>>>(energy);
}

// round 3
// speedup vs baseline: 3.2574x; 1.4692x over previous
#include <cuda_runtime.h>
#include <cuda_bf16.h>
#include <math.h>

#define BB    16
#define NN    1024
#define HID   64
#define NH    4
#define HD    16
#define MLPH  128
#define FF    256
#define MAXF  512
#define LN_EPS 1e-5f

__device__ float g_x[BB * NN * HID];
__device__ float g_q[BB * NH * NN * HD];
__device__ float g_k[BB * NH * NN * HD];
__device__ float g_v[BB * NH * NN * HD];
__device__ float g_o[BB * NH * NN * HD];
__device__ float g_esum[BB * NN];

__device__ __forceinline__ float dot4(float4 a, float4 b) {
    return a.x * b.x + a.y * b.y + a.z * b.z + a.w * b.w;
}
__device__ __forceinline__ float4 ldg4(const float4* p) { return __ldg(p); }

// ============================================================
// 1. Input MLP + QKV(layer 0): 16 tokens / block, 256 threads
// ============================================================
__global__ __launch_bounds__(256) void k_input_qkv(
        const float* __restrict__ y,
        const float* __restrict__ w1_0, const float* __restrict__ w1_1,
        const float* __restrict__ w1_2, const float* __restrict__ w1_3,
        const float* __restrict__ b1,   const float* __restrict__ w2,
        const float* __restrict__ b2,
        const float* __restrict__ qkv_w, const float* __restrict__ qkv_b) {
    __shared__ __align__(16) float sy[16 * MAXF];   // 32 KB
    __shared__ __align__(16) float sh[16 * MLPH];   // 8 KB
    __shared__ __align__(16) float sx[16 * HID];    // 4 KB
    int tok0 = blockIdx.x * 16;
    int b    = tok0 >> 10;
    int n0   = tok0 & 1023;
    int seg  = n0 >> 8;
    int F    = 64 << seg;
    int F4   = F >> 2;
    const float* w1 = (seg == 0) ? w1_0 : (seg == 1) ? w1_1 : (seg == 2) ? w1_2 : w1_3;
    int t = threadIdx.x;

    // stage y[16][F]
    {
        const float4* yg = (const float4*)y;
        float4* sy4 = (float4*)sy;
        for (int idx = t; idx < 16 * F4; idx += 256) {
            int tt = idx / F4, f4 = idx - tt * F4;
            sy4[tt * F4 + f4] = yg[(size_t)(tok0 + tt) * (MAXF / 4) + f4];
        }
    }
    __syncthreads();

    // phase 1: h = tanh(y @ w1^T + b1); 2 reps x 128 h, 8 tokens each
    {
        int rep = t >> 7, h = t & 127;
        const float4* wr = (const float4*)(w1 + (size_t)h * F);
        float bi = b1[seg * MLPH + h];
        float acc[8];
        #pragma unroll
        for (int j = 0; j < 8; j++) acc[j] = bi;
        const float4* sy4 = (const float4*)sy + (rep * 8) * F4;
        #pragma unroll 4
        for (int k = 0; k < F4; k++) {
            float4 wt = ldg4(wr + k);
            #pragma unroll
            for (int j = 0; j < 8; j++) acc[j] += dot4(sy4[j * F4 + k], wt);
        }
        #pragma unroll
        for (int j = 0; j < 8; j++) sh[(rep * 8 + j) * MLPH + h] = tanhf(acc[j]);
    }
    __syncthreads();

    // phase 2: x = h @ w2^T + b2; 4 reps x 64 c, 4 tokens each
    {
        int rep = t >> 6, c = t & 63;
        const float4* wr = (const float4*)(w2 + ((size_t)seg * HID + c) * MLPH);
        float bi = b2[seg * HID + c];
        float acc[4];
        #pragma unroll
        for (int j = 0; j < 4; j++) acc[j] = bi;
        const float4* a = (const float4*)sh + (rep * 4) * (MLPH / 4);
        #pragma unroll
        for (int k = 0; k < MLPH / 4; k++) {
            float4 wt = ldg4(wr + k);
            #pragma unroll
            for (int j = 0; j < 4; j++) acc[j] += dot4(a[j * (MLPH / 4) + k], wt);
        }
        #pragma unroll
        for (int j = 0; j < 4; j++) {
            int tok = rep * 4 + j;
            sx[tok * HID + c] = acc[j];
            g_x[(size_t)(tok0 + tok) * HID + c] = acc[j];
        }
    }
    __syncthreads();

    // phase 3: qkv (layer 0); 192 threads, 16 tokens each
    if (t < 192) {
        const float4* wr = (const float4*)(qkv_w + (size_t)t * HID);
        float bi = qkv_b[t];
        float acc[16];
        #pragma unroll
        for (int j = 0; j < 16; j++) acc[j] = bi;
        const float4* a = (const float4*)sx;
        #pragma unroll
        for (int k = 0; k < HID / 4; k++) {
            float4 wt = ldg4(wr + k);
            #pragma unroll
            for (int j = 0; j < 16; j++) acc[j] += dot4(a[j * (HID / 4) + k], wt);
        }
        int kind = t >> 6, w_ = t & 63, h = w_ >> 4, d = w_ & 15;
        float* dst = (kind == 0) ? g_q : (kind == 1) ? g_k : g_v;
        float scale = (kind == 0) ? 0.25f : 1.0f;
        size_t base = (((size_t)b * NH + h) * NN + n0) * HD + d;
        #pragma unroll
        for (int j = 0; j < 16; j++) dst[base + (size_t)j * HD] = acc[j] * scale;
    }
}

// ============================================================
// 2. Attention: 256 threads, 1 query each; grid B*NH*4
// ============================================================
__global__ __launch_bounds__(256) void k_attn() {
    __shared__ __align__(16) float sk[256 * HD];
    __shared__ __align__(16) float sv[256 * HD];
    int bh = blockIdx.x >> 2;
    int qc = blockIdx.x & 3;
    int t  = threadIdx.x;
    size_t base = (size_t)bh * NN * HD;
    int qi = qc * 256 + t;

    const float4* qp = (const float4*)(g_q + base + (size_t)qi * HD);
    float4 q0 = qp[0], q1 = qp[1], q2 = qp[2], q3 = qp[3];

    float m = -1e30f, l = 0.f;
    float acc[HD];
    #pragma unroll
    for (int d = 0; d < HD; d++) acc[d] = 0.f;

    for (int kc = 0; kc < 4; kc++) {
        const float4* kg = (const float4*)(g_k + base + (size_t)kc * 256 * HD);
        const float4* vg = (const float4*)(g_v + base + (size_t)kc * 256 * HD);
        float4* sk4 = (float4*)sk;
        float4* sv4 = (float4*)sv;
        #pragma unroll
        for (int i = 0; i < 4; i++) {
            sk4[t + i * 256] = kg[t + i * 256];
            sv4[t + i * 256] = vg[t + i * 256];
        }
        __syncthreads();

        for (int j = 0; j < 256; j++) {
            const float4* kr = (const float4*)(sk + j * HD);
            float s = dot4(q0, kr[0]) + dot4(q1, kr[1]) + dot4(q2, kr[2]) + dot4(q3, kr[3]);
            const float4* vr = (const float4*)(sv + j * HD);
            float4 v0 = vr[0], v1 = vr[1], v2 = vr[2], v3 = vr[3];
            float vv[HD] = {v0.x,v0.y,v0.z,v0.w, v1.x,v1.y,v1.z,v1.w,
                            v2.x,v2.y,v2.z,v2.w, v3.x,v3.y,v3.z,v3.w};
            if (s <= m) {
                float p = __expf(s - m);
                l += p;
                #pragma unroll
                for (int d = 0; d < HD; d++) acc[d] += p * vv[d];
            } else {
                float corr = __expf(m - s);
                l = l * corr + 1.f;
                #pragma unroll
                for (int d = 0; d < HD; d++) acc[d] = acc[d] * corr + vv[d];
                m = s;
            }
        }
        __syncthreads();
    }
    float inv = 1.f / l;
    float* op = g_o + base + (size_t)qi * HD;
    #pragma unroll
    for (int d = 0; d < HD; d++) op[d] = acc[d] * inv;
}

// ============================================================
// 3. Proj + LN1 + FFN + LN2 (+ optional QKV of next layer)
//    16 tokens / block, 256 threads
// ============================================================
__global__ __launch_bounds__(256) void k_pfq(int l, int do_qkv,
        const float* __restrict__ W,   const float* __restrict__ bias,
        const float* __restrict__ ln1w, const float* __restrict__ ln1b,
        const float* __restrict__ fw1, const float* __restrict__ fb1,
        const float* __restrict__ fw2, const float* __restrict__ fb2,
        const float* __restrict__ ln2w, const float* __restrict__ ln2b,
        const float* __restrict__ qkv_w, const float* __restrict__ qkv_b) {
    __shared__ __align__(16) float so[16 * HID];     // 4 KB  attn out (merged heads)
    __shared__ __align__(16) float sx1[16 * HID];    // 4 KB  LN1 output
    __shared__ __align__(16) float sh[16 * FF];      // 16 KB ffn hidden
    __shared__ float sval[16 * 66];                  // pre-LN values
    int tok0 = blockIdx.x * 16;
    int b = tok0 >> 10, n0 = tok0 & 1023;
    int t = threadIdx.x;
    int wid = t >> 5, lane = t & 31;

    for (int idx = t; idx < 16 * HID; idx += 256) {
        int tt = idx >> 6, c = idx & 63;
        so[idx] = g_o[(((size_t)b * NH + (c >> 4)) * NN + n0 + tt) * HD + (c & 15)];
    }
    __syncthreads();

    // out-proj + residual
    {
        int rep = t >> 6, c = t & 63;
        const float4* wr = (const float4*)(W + ((size_t)l * HID + c) * HID);
        float bi = bias[l * HID + c];
        float acc[4];
        #pragma unroll
        for (int j = 0; j < 4; j++) acc[j] = bi;
        const float4* a = (const float4*)so + (rep * 4) * (HID / 4);
        #pragma unroll
        for (int k = 0; k < HID / 4; k++) {
            float4 wt = ldg4(wr + k);
            #pragma unroll
            for (int j = 0; j < 4; j++) acc[j] += dot4(a[j * (HID / 4) + k], wt);
        }
        #pragma unroll
        for (int j = 0; j < 4; j++) {
            int tok = rep * 4 + j;
            sval[tok * 66 + c] = g_x[(size_t)(tok0 + tok) * HID + c] + acc[j];
        }
    }
    __syncthreads();

    // LN1: warp w handles tokens 2w, 2w+1
    {
        int tA = 2 * wid, tB = 2 * wid + 1;
        float a0 = sval[tA * 66 + lane],      a1 = sval[tA * 66 + lane + 32];
        float b0 = sval[tB * 66 + lane],      b1 = sval[tB * 66 + lane + 32];
        float sA1 = a0 + a1, sA2 = a0 * a0 + a1 * a1;
        float sB1 = b0 + b1, sB2 = b0 * b0 + b1 * b1;
        #pragma unroll
        for (int off = 16; off > 0; off >>= 1) {
            sA1 += __shfl_xor_sync(0xffffffff, sA1, off);
            sA2 += __shfl_xor_sync(0xffffffff, sA2, off);
            sB1 += __shfl_xor_sync(0xffffffff, sB1, off);
            sB2 += __shfl_xor_sync(0xffffffff, sB2, off);
        }
        float mA = sA1 * (1.f / 64.f), vA = sA2 * (1.f / 64.f) - mA * mA;
        float mB = sB1 * (1.f / 64.f), vB = sB2 * (1.f / 64.f) - mB * mB;
        float rA = rsqrtf(vA + LN_EPS), rB = rsqrtf(vB + LN_EPS);
        float w0 = ln1w[l * HID + lane],      w1v = ln1w[l * HID + lane + 32];
        float bb0 = ln1b[l * HID + lane],     bb1 = ln1b[l * HID + lane + 32];
        sx1[tA * HID + lane]      = (a0 - mA) * rA * w0  + bb0;
        sx1[tA * HID + lane + 32] = (a1 - mA) * rA * w1v + bb1;
        sx1[tB * HID + lane]      = (b0 - mB) * rB * w0  + bb0;
        sx1[tB * HID + lane + 32] = (b1 - mB) * rB * w1v + bb1;
    }
    __syncthreads();

    // FFN phase 1: 256 hidden units, 16 tokens each
    {
        const float4* wr = (const float4*)(fw1 + ((size_t)l * FF + t) * HID);
        float bi = fb1[l * FF + t];
        float acc[16];
        #pragma unroll
        for (int j = 0; j < 16; j++) acc[j] = bi;
        const float4* a = (const float4*)sx1;
        #pragma unroll
        for (int k = 0; k < HID / 4; k++) {
            float4 wt = ldg4(wr + k);
            #pragma unroll
            for (int j = 0; j < 16; j++) acc[j] += dot4(a[j * (HID / 4) + k], wt);
        }
        #pragma unroll
        for (int j = 0; j < 16; j++) sh[j * FF + t] = fmaxf(acc[j], 0.f);
    }
    __syncthreads();

    // FFN phase 2 + residual
    {
        int rep = t >> 6, c = t & 63;
        const float4* wr = (const float4*)(fw2 + ((size_t)l * HID + c) * FF);
        float bi = fb2[l * HID + c];
        float acc[4];
        #pragma unroll
        for (int j = 0; j < 4; j++) acc[j] = bi;
        const float4* a = (const float4*)sh + (rep * 4) * (FF / 4);
        #pragma unroll 8
        for (int k = 0; k < FF / 4; k++) {
            float4 wt = ldg4(wr + k);
            #pragma unroll
            for (int j = 0; j < 4; j++) acc[j] += dot4(a[j * (FF / 4) + k], wt);
        }
        #pragma unroll
        for (int j = 0; j < 4; j++) {
            int tok = rep * 4 + j;
            sval[tok * 66 + c] = sx1[tok * HID + c] + acc[j];
        }
    }
    __syncthreads();

    // LN2 -> g_x and sx1 (reuse as normalized x)
    {
        int tA = 2 * wid, tB = 2 * wid + 1;
        float a0 = sval[tA * 66 + lane],      a1 = sval[tA * 66 + lane + 32];
        float b0 = sval[tB * 66 + lane],      b1 = sval[tB * 66 + lane + 32];
        float sA1 = a0 + a1, sA2 = a0 * a0 + a1 * a1;
        float sB1 = b0 + b1, sB2 = b0 * b0 + b1 * b1;
        #pragma unroll
        for (int off = 16; off > 0; off >>= 1) {
            sA1 += __shfl_xor_sync(0xffffffff, sA1, off);
            sA2 += __shfl_xor_sync(0xffffffff, sA2, off);
            sB1 += __shfl_xor_sync(0xffffffff, sB1, off);
            sB2 += __shfl_xor_sync(0xffffffff, sB2, off);
        }
        float mA = sA1 * (1.f / 64.f), vA = sA2 * (1.f / 64.f) - mA * mA;
        float mB = sB1 * (1.f / 64.f), vB = sB2 * (1.f / 64.f) - mB * mB;
        float rA = rsqrtf(vA + LN_EPS), rB = rsqrtf(vB + LN_EPS);
        float w0 = ln2w[l * HID + lane],      w1v = ln2w[l * HID + lane + 32];
        float bb0 = ln2b[l * HID + lane],     bb1 = ln2b[l * HID + lane + 32];
        float oA0 = (a0 - mA) * rA * w0  + bb0;
        float oA1 = (a1 - mA) * rA * w1v + bb1;
        float oB0 = (b0 - mB) * rB * w0  + bb0;
        float oB1 = (b1 - mB) * rB * w1v + bb1;
        sx1[tA * HID + lane]      = oA0;
        sx1[tA * HID + lane + 32] = oA1;
        sx1[tB * HID + lane]      = oB0;
        sx1[tB * HID + lane + 32] = oB1;
        size_t gb = (size_t)(tok0 + tA) * HID;
        g_x[gb + lane]            = oA0;
        g_x[gb + lane + 32]       = oA1;
        g_x[gb + HID + lane]      = oB0;
        g_x[gb + HID + lane + 32] = oB1;
    }
    __syncthreads();

    // optional QKV for next layer
    if (do_qkv && t < 192) {
        const float4* wr = (const float4*)(qkv_w + ((size_t)(l + 1) * 192 + t) * HID);
        float bi = qkv_b[(l + 1) * 192 + t];
        float acc[16];
        #pragma unroll
        for (int j = 0; j < 16; j++) acc[j] = bi;
        const float4* a = (const float4*)sx1;
        #pragma unroll
        for (int k = 0; k < HID / 4; k++) {
            float4 wt = ldg4(wr + k);
            #pragma unroll
            for (int j = 0; j < 16; j++) acc[j] += dot4(a[j * (HID / 4) + k], wt);
        }
        int kind = t >> 6, w_ = t & 63, h = w_ >> 4, d = w_ & 15;
        float* dst = (kind == 0) ? g_q : (kind == 1) ? g_k : g_v;
        float scale = (kind == 0) ? 0.25f : 1.0f;
        size_t base = (((size_t)b * NH + h) * NN + n0) * HD + d;
        #pragma unroll
        for (int j = 0; j < 16; j++) dst[base + (size_t)j * HD] = acc[j] * scale;
    }
}

// ============================================================
// 4. Output head + energy partials: 16 tokens / block, 256 threads
// ============================================================
__global__ __launch_bounds__(256) void k_out(float* __restrict__ out,
        const float* __restrict__ ow1, const float* __restrict__ ob1,
        const float* __restrict__ w2_0, const float* __restrict__ w2_1,
        const float* __restrict__ w2_2, const float* __restrict__ w2_3,
        const float* __restrict__ b2_0, const float* __restrict__ b2_1,
        const float* __restrict__ b2_2, const float* __restrict__ b2_3) {
    __shared__ __align__(16) float sx[16 * HID];
    __shared__ __align__(16) float sh[16 * MLPH];
    __shared__ float red[8][16];
    int tok0 = blockIdx.x * 16;
    int n0 = tok0 & 1023;
    int seg = n0 >> 8;
    int F = 64 << seg;
    const float* w2 = (seg == 0) ? w2_0 : (seg == 1) ? w2_1 : (seg == 2) ? w2_2 : w2_3;
    const float* b2 = (seg == 0) ? b2_0 : (seg == 1) ? b2_1 : (seg == 2) ? b2_2 : b2_3;
    int t = threadIdx.x;
    for (int idx = t; idx < 16 * HID; idx += 256)
        sx[idx] = g_x[(size_t)tok0 * HID + idx];
    __syncthreads();

    // phase 1: 2 reps x 128 h, 8 tokens each
    {
        int rep = t >> 7, h = t & 127;
        const float4* wr = (const float4*)(ow1 + ((size_t)seg * MLPH + h) * HID);
        float bi = ob1[seg * MLPH + h];
        float acc[8];
        #pragma unroll
        for (int j = 0; j < 8; j++) acc[j] = bi;
        const float4* a = (const float4*)sx + (rep * 8) * (HID / 4);
        #pragma unroll
        for (int k = 0; k < HID / 4; k++) {
            float4 wt = ldg4(wr + k);
            #pragma unroll
            for (int j = 0; j < 8; j++) acc[j] += dot4(a[j * (HID / 4) + k], wt);
        }
        #pragma unroll
        for (int j = 0; j < 8; j++) sh[(rep * 8 + j) * MLPH + h] = tanhf(acc[j]);
    }
    __syncthreads();

    // phase 2: outputs; 16 tokens per thread per f
    float sq[16];
    #pragma unroll
    for (int j = 0; j < 16; j++) sq[j] = 0.f;
    for (int f = t; f < MAXF; f += 256) {
        if (f < F) {
            const float4* wr = (const float4*)(w2 + (size_t)f * MLPH);
            float bi = b2[f];
            float acc[16];
            #pragma unroll
            for (int j = 0; j < 16; j++) acc[j] = bi;
            const float4* a = (const float4*)sh;
            #pragma unroll 4
            for (int k = 0; k < MLPH / 4; k++) {
                float4 wt = ldg4(wr + k);
                #pragma unroll
                for (int j = 0; j < 16; j++) acc[j] += dot4(a[j * (MLPH / 4) + k], wt);
            }
            #pragma unroll
            for (int j = 0; j < 16; j++) {
                out[(size_t)(tok0 + j) * MAXF + f] = acc[j];
                sq[j] += acc[j] * acc[j];
            }
        } else {
            #pragma unroll
            for (int j = 0; j < 16; j++)
                out[(size_t)(tok0 + j) * MAXF + f] = 0.f;
        }
    }

    int wid = t >> 5;
    #pragma unroll
    for (int j = 0; j < 16; j++) {
        float s = sq[j];
        #pragma unroll
        for (int off = 16; off > 0; off >>= 1) s += __shfl_xor_sync(0xffffffff, s, off);
        if ((t & 31) == 0) red[wid][j] = s;
    }
    __syncthreads();
    if (t < 16) {
        float s = 0.f;
        #pragma unroll
        for (int w = 0; w < 8; w++) s += red[w][t];
        g_esum[tok0 + t] = s;
    }
}

// ============================================================
// 5. Energy reduce
// ============================================================
__global__ void k_energy(float* __restrict__ e) {
    __shared__ float red[4];
    int b = blockIdx.x;
    int t = threadIdx.x;
    float s = 0.f;
    for (int i = t; i < NN; i += 128) s += g_esum[b * NN + i];
    #pragma unroll
    for (int off = 16; off > 0; off >>= 1) s += __shfl_xor_sync(0xffffffff, s, off);
    if ((t & 31) == 0) red[t >> 5] = s;
    __syncthreads();
    if (t == 0) e[b] = 0.5f * (red[0] + red[1] + red[2] + red[3]);
}

// ============================================================
extern "C" void kernel_launch(void* const* d_in, const int* in_sizes, int n_in,
                              void* d_out, int out_size) {
    const float* y      = (const float*)d_in[1];
    const float* in_w1_0 = (const float*)d_in[3];
    const float* in_w1_1 = (const float*)d_in[4];
    const float* in_w1_2 = (const float*)d_in[5];
    const float* in_w1_3 = (const float*)d_in[6];
    const float* out_w2_0 = (const float*)d_in[7];
    const float* out_w2_1 = (const float*)d_in[8];
    const float* out_w2_2 = (const float*)d_in[9];
    const float* out_w2_3 = (const float*)d_in[10];
    const float* out_b2_0 = (const float*)d_in[11];
    const float* out_b2_1 = (const float*)d_in[12];
    const float* out_b2_2 = (const float*)d_in[13];
    const float* out_b2_3 = (const float*)d_in[14];
    const float* in_b1  = (const float*)d_in[15];
    const float* in_w2  = (const float*)d_in[16];
    const float* in_b2  = (const float*)d_in[17];
    const float* out_w1 = (const float*)d_in[18];
    const float* out_b1 = (const float*)d_in[19];
    const float* qkv_w  = (const float*)d_in[20];
    const float* qkv_b  = (const float*)d_in[21];
    const float* attn_out_w = (const float*)d_in[22];
    const float* attn_out_b = (const float*)d_in[23];
    const float* ln1_w  = (const float*)d_in[24];
    const float* ln1_b  = (const float*)d_in[25];
    const float* ffn_w1 = (const float*)d_in[26];
    const float* ffn_b1 = (const float*)d_in[27];
    const float* ffn_w2 = (const float*)d_in[28];
    const float* ffn_b2 = (const float*)d_in[29];
    const float* ln2_w  = (const float*)d_in[30];
    const float* ln2_b  = (const float*)d_in[31];

    float* out = (float*)d_out;
    float* energy = out + (size_t)BB * NN * MAXF;

    const int NB = (BB * NN) / 16;   // 1024 blocks

    k_input_qkv<<<NB, 256>>>(y, in_w1_0, in_w1_1, in_w1_2, in_w1_3,
                             in_b1, in_w2, in_b2, qkv_w, qkv_b);
    k_attn<<<BB * NH * 4, 256>>>();
    k_pfq<<<NB, 256>>>(0, 1, attn_out_w, attn_out_b, ln1_w, ln1_b,
                       ffn_w1, ffn_b1, ffn_w2, ffn_b2, ln2_w, ln2_b, qkv_w, qkv_b);
    k_attn<<<BB * NH * 4, 256>>>();
    k_pfq<<<NB, 256>>>(1, 0, attn_out_w, attn_out_b, ln1_w, ln1_b,
                       ffn_w1, ffn_b1, ffn_w2, ffn_b2, ln2_w, ln2_b, qkv_w, qkv_b);
    k_out<<<NB, 256>>>(out, out_w1, out_b1,
                       out_w2_0, out_w2_1, out_w2_2, out_w2_3,
                       out_b2_0, out_b2_1, out_b2_2, out_b2_3);
    k_energy<<<BB, 128>>>(energy);
}

// round 4
// speedup vs baseline: 3.7069x; 1.1380x over previous
#include <cuda_runtime.h>
#include <cuda_bf16.h>
#include <math.h>

#define BB    16
#define NN    1024
#define HID   64
#define NH    4
#define HD    16
#define MLPH  128
#define FF    256
#define MAXF  512
#define LN_EPS 1e-5f

__device__ float g_x[BB * NN * HID];
__device__ float g_q[BB * NH * NN * HD];
__device__ float g_k[BB * NH * NN * HD];
__device__ float g_v[BB * NH * NN * HD];
__device__ float g_o2[2][BB * NH * NN * HD];   // split-K unnormalized partials
__device__ float g_l2[2][BB * NH * NN];        // split-K partial denominators
__device__ float g_esum[BB * NN];

__device__ __forceinline__ float dot4(float4 a, float4 b) {
    return a.x * b.x + a.y * b.y + a.z * b.z + a.w * b.w;
}
__device__ __forceinline__ float4 ldg4(const float4* p) { return __ldg(p); }

// ============================================================
// 1. Input MLP + QKV(layer 0): 16 tokens / block, 256 threads
// ============================================================
__global__ __launch_bounds__(256) void k_input_qkv(
        const float* __restrict__ y,
        const float* __restrict__ w1_0, const float* __restrict__ w1_1,
        const float* __restrict__ w1_2, const float* __restrict__ w1_3,
        const float* __restrict__ b1,   const float* __restrict__ w2,
        const float* __restrict__ b2,
        const float* __restrict__ qkv_w, const float* __restrict__ qkv_b) {
    __shared__ __align__(16) float sy[16 * MAXF];   // 32 KB
    __shared__ __align__(16) float sh[16 * MLPH];   // 8 KB
    __shared__ __align__(16) float sx[16 * HID];    // 4 KB
    int tok0 = blockIdx.x * 16;
    int b    = tok0 >> 10;
    int n0   = tok0 & 1023;
    int seg  = n0 >> 8;
    int F    = 64 << seg;
    int F4   = F >> 2;
    const float* w1 = (seg == 0) ? w1_0 : (seg == 1) ? w1_1 : (seg == 2) ? w1_2 : w1_3;
    int t = threadIdx.x;

    {
        const float4* yg = (const float4*)y;
        float4* sy4 = (float4*)sy;
        for (int idx = t; idx < 16 * F4; idx += 256) {
            int tt = idx / F4, f4 = idx - tt * F4;
            sy4[tt * F4 + f4] = yg[(size_t)(tok0 + tt) * (MAXF / 4) + f4];
        }
    }
    __syncthreads();

    {
        int rep = t >> 7, h = t & 127;
        const float4* wr = (const float4*)(w1 + (size_t)h * F);
        float bi = b1[seg * MLPH + h];
        float acc[8];
        #pragma unroll
        for (int j = 0; j < 8; j++) acc[j] = bi;
        const float4* sy4 = (const float4*)sy + (rep * 8) * F4;
        #pragma unroll 4
        for (int k = 0; k < F4; k++) {
            float4 wt = ldg4(wr + k);
            #pragma unroll
            for (int j = 0; j < 8; j++) acc[j] += dot4(sy4[j * F4 + k], wt);
        }
        #pragma unroll
        for (int j = 0; j < 8; j++) sh[(rep * 8 + j) * MLPH + h] = tanhf(acc[j]);
    }
    __syncthreads();

    {
        int rep = t >> 6, c = t & 63;
        const float4* wr = (const float4*)(w2 + ((size_t)seg * HID + c) * MLPH);
        float bi = b2[seg * HID + c];
        float acc[4];
        #pragma unroll
        for (int j = 0; j < 4; j++) acc[j] = bi;
        const float4* a = (const float4*)sh + (rep * 4) * (MLPH / 4);
        #pragma unroll
        for (int k = 0; k < MLPH / 4; k++) {
            float4 wt = ldg4(wr + k);
            #pragma unroll
            for (int j = 0; j < 4; j++) acc[j] += dot4(a[j * (MLPH / 4) + k], wt);
        }
        #pragma unroll
        for (int j = 0; j < 4; j++) {
            int tok = rep * 4 + j;
            sx[tok * HID + c] = acc[j];
            g_x[(size_t)(tok0 + tok) * HID + c] = acc[j];
        }
    }
    __syncthreads();

    if (t < 192) {
        const float4* wr = (const float4*)(qkv_w + (size_t)t * HID);
        float bi = qkv_b[t];
        float acc[16];
        #pragma unroll
        for (int j = 0; j < 16; j++) acc[j] = bi;
        const float4* a = (const float4*)sx;
        #pragma unroll
        for (int k = 0; k < HID / 4; k++) {
            float4 wt = ldg4(wr + k);
            #pragma unroll
            for (int j = 0; j < 16; j++) acc[j] += dot4(a[j * (HID / 4) + k], wt);
        }
        int kind = t >> 6, w_ = t & 63, h = w_ >> 4, d = w_ & 15;
        float* dst = (kind == 0) ? g_q : (kind == 1) ? g_k : g_v;
        float scale = (kind == 0) ? 0.25f : 1.0f;
        size_t base = (((size_t)b * NH + h) * NN + n0) * HD + d;
        #pragma unroll
        for (int j = 0; j < 16; j++) dst[base + (size_t)j * HD] = acc[j] * scale;
    }
}

// ============================================================
// 2. Attention split-K: grid = bh(64) x qc(4) x kc(2) = 512 blocks
//    128 threads, 2 queries each, 512 keys per block.
//    Branch-free exp (scores are small; clamp guards overflow).
//    Writes unnormalized partial acc + partial denominator.
// ============================================================
__global__ __launch_bounds__(128) void k_attn() {
    __shared__ __align__(16) float sk[256 * HD];   // 16 KB
    __shared__ __align__(16) float sv[256 * HD];   // 16 KB
    int blk = blockIdx.x;
    int kc  = blk & 1;
    int qc  = (blk >> 1) & 3;
    int bh  = blk >> 3;
    int t   = threadIdx.x;
    size_t base = (size_t)bh * NN * HD;
    int qa = qc * 256 + t, qb = qa + 128;

    const float4* qpa = (const float4*)(g_q + base + (size_t)qa * HD);
    const float4* qpb = (const float4*)(g_q + base + (size_t)qb * HD);
    float4 qa0 = qpa[0], qa1 = qpa[1], qa2 = qpa[2], qa3 = qpa[3];
    float4 qb0 = qpb[0], qb1 = qpb[1], qb2 = qpb[2], qb3 = qpb[3];

    float la = 0.f, lb = 0.f;
    float aa[HD], ab[HD];
    #pragma unroll
    for (int d = 0; d < HD; d++) { aa[d] = 0.f; ab[d] = 0.f; }

    for (int cc = 0; cc < 2; cc++) {
        int k0 = kc * 512 + cc * 256;
        const float4* kg = (const float4*)(g_k + base + (size_t)k0 * HD);
        const float4* vg = (const float4*)(g_v + base + (size_t)k0 * HD);
        float4* sk4 = (float4*)sk;
        float4* sv4 = (float4*)sv;
        #pragma unroll
        for (int i = 0; i < 8; i++) {
            sk4[t + i * 128] = kg[t + i * 128];
            sv4[t + i * 128] = vg[t + i * 128];
        }
        __syncthreads();

        for (int j = 0; j < 256; j++) {
            const float4* kr = (const float4*)(sk + j * HD);
            float4 k0v = kr[0], k1v = kr[1], k2v = kr[2], k3v = kr[3];
            const float4* vr = (const float4*)(sv + j * HD);
            float4 v0 = vr[0], v1 = vr[1], v2 = vr[2], v3 = vr[3];
            float vv[HD] = {v0.x,v0.y,v0.z,v0.w, v1.x,v1.y,v1.z,v1.w,
                            v2.x,v2.y,v2.z,v2.w, v3.x,v3.y,v3.z,v3.w};
            float sa = dot4(qa0, k0v) + dot4(qa1, k1v) + dot4(qa2, k2v) + dot4(qa3, k3v);
            float sb = dot4(qb0, k0v) + dot4(qb1, k1v) + dot4(qb2, k2v) + dot4(qb3, k3v);
            float pa = __expf(fminf(sa, 75.f));
            float pb = __expf(fminf(sb, 75.f));
            la += pa; lb += pb;
            #pragma unroll
            for (int d = 0; d < HD; d++) {
                aa[d] += pa * vv[d];
                ab[d] += pb * vv[d];
            }
        }
        __syncthreads();
    }

    float* opa = g_o2[kc] + base + (size_t)qa * HD;
    float* opb = g_o2[kc] + base + (size_t)qb * HD;
    #pragma unroll
    for (int d = 0; d < HD; d++) { opa[d] = aa[d]; opb[d] = ab[d]; }
    g_l2[kc][(size_t)bh * NN + qa] = la;
    g_l2[kc][(size_t)bh * NN + qb] = lb;
}

// ============================================================
// 3. Combine split-K + Proj + LN1 + FFN + LN2 (+ next-layer QKV)
// ============================================================
__global__ __launch_bounds__(256) void k_pfq(int l, int do_qkv,
        const float* __restrict__ W,   const float* __restrict__ bias,
        const float* __restrict__ ln1w, const float* __restrict__ ln1b,
        const float* __restrict__ fw1, const float* __restrict__ fb1,
        const float* __restrict__ fw2, const float* __restrict__ fb2,
        const float* __restrict__ ln2w, const float* __restrict__ ln2b,
        const float* __restrict__ qkv_w, const float* __restrict__ qkv_b) {
    __shared__ __align__(16) float so[16 * HID];
    __shared__ __align__(16) float sx1[16 * HID];
    __shared__ __align__(16) float sh[16 * FF];
    __shared__ float sval[16 * 66];
    int tok0 = blockIdx.x * 16;
    int b = tok0 >> 10, n0 = tok0 & 1023;
    int t = threadIdx.x;
    int wid = t >> 5, lane = t & 31;

    // combine split-K partials: o = (oA+oB)/(lA+lB), merge heads
    for (int idx = t; idx < 16 * HID; idx += 256) {
        int tt = idx >> 6, c = idx & 63;
        size_t pl = ((size_t)b * NH + (c >> 4)) * NN + n0 + tt;
        size_t p  = pl * HD + (c & 15);
        float lsum = g_l2[0][pl] + g_l2[1][pl];
        so[idx] = (g_o2[0][p] + g_o2[1][p]) * (1.f / lsum);
    }
    __syncthreads();

    {
        int rep = t >> 6, c = t & 63;
        const float4* wr = (const float4*)(W + ((size_t)l * HID + c) * HID);
        float bi = bias[l * HID + c];
        float acc[4];
        #pragma unroll
        for (int j = 0; j < 4; j++) acc[j] = bi;
        const float4* a = (const float4*)so + (rep * 4) * (HID / 4);
        #pragma unroll
        for (int k = 0; k < HID / 4; k++) {
            float4 wt = ldg4(wr + k);
            #pragma unroll
            for (int j = 0; j < 4; j++) acc[j] += dot4(a[j * (HID / 4) + k], wt);
        }
        #pragma unroll
        for (int j = 0; j < 4; j++) {
            int tok = rep * 4 + j;
            sval[tok * 66 + c] = g_x[(size_t)(tok0 + tok) * HID + c] + acc[j];
        }
    }
    __syncthreads();

    {
        int tA = 2 * wid, tB = 2 * wid + 1;
        float a0 = sval[tA * 66 + lane],      a1 = sval[tA * 66 + lane + 32];
        float b0 = sval[tB * 66 + lane],      b1 = sval[tB * 66 + lane + 32];
        float sA1 = a0 + a1, sA2 = a0 * a0 + a1 * a1;
        float sB1 = b0 + b1, sB2 = b0 * b0 + b1 * b1;
        #pragma unroll
        for (int off = 16; off > 0; off >>= 1) {
            sA1 += __shfl_xor_sync(0xffffffff, sA1, off);
            sA2 += __shfl_xor_sync(0xffffffff, sA2, off);
            sB1 += __shfl_xor_sync(0xffffffff, sB1, off);
            sB2 += __shfl_xor_sync(0xffffffff, sB2, off);
        }
        float mA = sA1 * (1.f / 64.f), vA = sA2 * (1.f / 64.f) - mA * mA;
        float mB = sB1 * (1.f / 64.f), vB = sB2 * (1.f / 64.f) - mB * mB;
        float rA = rsqrtf(vA + LN_EPS), rB = rsqrtf(vB + LN_EPS);
        float w0 = ln1w[l * HID + lane],      w1v = ln1w[l * HID + lane + 32];
        float bb0 = ln1b[l * HID + lane],     bb1 = ln1b[l * HID + lane + 32];
        sx1[tA * HID + lane]      = (a0 - mA) * rA * w0  + bb0;
        sx1[tA * HID + lane + 32] = (a1 - mA) * rA * w1v + bb1;
        sx1[tB * HID + lane]      = (b0 - mB) * rB * w0  + bb0;
        sx1[tB * HID + lane + 32] = (b1 - mB) * rB * w1v + bb1;
    }
    __syncthreads();

    {
        const float4* wr = (const float4*)(fw1 + ((size_t)l * FF + t) * HID);
        float bi = fb1[l * FF + t];
        float acc[16];
        #pragma unroll
        for (int j = 0; j < 16; j++) acc[j] = bi;
        const float4* a = (const float4*)sx1;
        #pragma unroll
        for (int k = 0; k < HID / 4; k++) {
            float4 wt = ldg4(wr + k);
            #pragma unroll
            for (int j = 0; j < 16; j++) acc[j] += dot4(a[j * (HID / 4) + k], wt);
        }
        #pragma unroll
        for (int j = 0; j < 16; j++) sh[j * FF + t] = fmaxf(acc[j], 0.f);
    }
    __syncthreads();

    {
        int rep = t >> 6, c = t & 63;
        const float4* wr = (const float4*)(fw2 + ((size_t)l * HID + c) * FF);
        float bi = fb2[l * HID + c];
        float acc[4];
        #pragma unroll
        for (int j = 0; j < 4; j++) acc[j] = bi;
        const float4* a = (const float4*)sh + (rep * 4) * (FF / 4);
        #pragma unroll 8
        for (int k = 0; k < FF / 4; k++) {
            float4 wt = ldg4(wr + k);
            #pragma unroll
            for (int j = 0; j < 4; j++) acc[j] += dot4(a[j * (FF / 4) + k], wt);
        }
        #pragma unroll
        for (int j = 0; j < 4; j++) {
            int tok = rep * 4 + j;
            sval[tok * 66 + c] = sx1[tok * HID + c] + acc[j];
        }
    }
    __syncthreads();

    {
        int tA = 2 * wid, tB = 2 * wid + 1;
        float a0 = sval[tA * 66 + lane],      a1 = sval[tA * 66 + lane + 32];
        float b0 = sval[tB * 66 + lane],      b1 = sval[tB * 66 + lane + 32];
        float sA1 = a0 + a1, sA2 = a0 * a0 + a1 * a1;
        float sB1 = b0 + b1, sB2 = b0 * b0 + b1 * b1;
        #pragma unroll
        for (int off = 16; off > 0; off >>= 1) {
            sA1 += __shfl_xor_sync(0xffffffff, sA1, off);
            sA2 += __shfl_xor_sync(0xffffffff, sA2, off);
            sB1 += __shfl_xor_sync(0xffffffff, sB1, off);
            sB2 += __shfl_xor_sync(0xffffffff, sB2, off);
        }
        float mA = sA1 * (1.f / 64.f), vA = sA2 * (1.f / 64.f) - mA * mA;
        float mB = sB1 * (1.f / 64.f), vB = sB2 * (1.f / 64.f) - mB * mB;
        float rA = rsqrtf(vA + LN_EPS), rB = rsqrtf(vB + LN_EPS);
        float w0 = ln2w[l * HID + lane],      w1v = ln2w[l * HID + lane + 32];
        float bb0 = ln2b[l * HID + lane],     bb1 = ln2b[l * HID + lane + 32];
        float oA0 = (a0 - mA) * rA * w0  + bb0;
        float oA1 = (a1 - mA) * rA * w1v + bb1;
        float oB0 = (b0 - mB) * rB * w0  + bb0;
        float oB1 = (b1 - mB) * rB * w1v + bb1;
        sx1[tA * HID + lane]      = oA0;
        sx1[tA * HID + lane + 32] = oA1;
        sx1[tB * HID + lane]      = oB0;
        sx1[tB * HID + lane + 32] = oB1;
        size_t gb = (size_t)(tok0 + tA) * HID;
        g_x[gb + lane]            = oA0;
        g_x[gb + lane + 32]       = oA1;
        g_x[gb + HID + lane]      = oB0;
        g_x[gb + HID + lane + 32] = oB1;
    }
    __syncthreads();

    if (do_qkv && t < 192) {
        const float4* wr = (const float4*)(qkv_w + ((size_t)(l + 1) * 192 + t) * HID);
        float bi = qkv_b[(l + 1) * 192 + t];
        float acc[16];
        #pragma unroll
        for (int j = 0; j < 16; j++) acc[j] = bi;
        const float4* a = (const float4*)sx1;
        #pragma unroll
        for (int k = 0; k < HID / 4; k++) {
            float4 wt = ldg4(wr + k);
            #pragma unroll
            for (int j = 0; j < 16; j++) acc[j] += dot4(a[j * (HID / 4) + k], wt);
        }
        int kind = t >> 6, w_ = t & 63, h = w_ >> 4, d = w_ & 15;
        float* dst = (kind == 0) ? g_q : (kind == 1) ? g_k : g_v;
        float scale = (kind == 0) ? 0.25f : 1.0f;
        size_t base = (((size_t)b * NH + h) * NN + n0) * HD + d;
        #pragma unroll
        for (int j = 0; j < 16; j++) dst[base + (size_t)j * HD] = acc[j] * scale;
    }
}

// ============================================================
// 4. Output head + energy partials: 16 tokens / block, 256 threads
// ============================================================
__global__ __launch_bounds__(256) void k_out(float* __restrict__ out,
        const float* __restrict__ ow1, const float* __restrict__ ob1,
        const float* __restrict__ w2_0, const float* __restrict__ w2_1,
        const float* __restrict__ w2_2, const float* __restrict__ w2_3,
        const float* __restrict__ b2_0, const float* __restrict__ b2_1,
        const float* __restrict__ b2_2, const float* __restrict__ b2_3) {
    __shared__ __align__(16) float sx[16 * HID];
    __shared__ __align__(16) float sh[16 * MLPH];
    __shared__ float red[8][16];
    int tok0 = blockIdx.x * 16;
    int n0 = tok0 & 1023;
    int seg = n0 >> 8;
    int F = 64 << seg;
    const float* w2 = (seg == 0) ? w2_0 : (seg == 1) ? w2_1 : (seg == 2) ? w2_2 : w2_3;
    const float* b2 = (seg == 0) ? b2_0 : (seg == 1) ? b2_1 : (seg == 2) ? b2_2 : b2_3;
    int t = threadIdx.x;
    for (int idx = t; idx < 16 * HID; idx += 256)
        sx[idx] = g_x[(size_t)tok0 * HID + idx];
    __syncthreads();

    {
        int rep = t >> 7, h = t & 127;
        const float4* wr = (const float4*)(ow1 + ((size_t)seg * MLPH + h) * HID);
        float bi = ob1[seg * MLPH + h];
        float acc[8];
        #pragma unroll
        for (int j = 0; j < 8; j++) acc[j] = bi;
        const float4* a = (const float4*)sx + (rep * 8) * (HID / 4);
        #pragma unroll
        for (int k = 0; k < HID / 4; k++) {
            float4 wt = ldg4(wr + k);
            #pragma unroll
            for (int j = 0; j < 8; j++) acc[j] += dot4(a[j * (HID / 4) + k], wt);
        }
        #pragma unroll
        for (int j = 0; j < 8; j++) sh[(rep * 8 + j) * MLPH + h] = tanhf(acc[j]);
    }
    __syncthreads();

    float sq[16];
    #pragma unroll
    for (int j = 0; j < 16; j++) sq[j] = 0.f;
    for (int f = t; f < MAXF; f += 256) {
        if (f < F) {
            const float4* wr = (const float4*)(w2 + (size_t)f * MLPH);
            float bi = b2[f];
            float acc[16];
            #pragma unroll
            for (int j = 0; j < 16; j++) acc[j] = bi;
            const float4* a = (const float4*)sh;
            #pragma unroll 4
            for (int k = 0; k < MLPH / 4; k++) {
                float4 wt = ldg4(wr + k);
                #pragma unroll
                for (int j = 0; j < 16; j++) acc[j] += dot4(a[j * (MLPH / 4) + k], wt);
            }
            #pragma unroll
            for (int j = 0; j < 16; j++) {
                out[(size_t)(tok0 + j) * MAXF + f] = acc[j];
                sq[j] += acc[j] * acc[j];
            }
        } else {
            #pragma unroll
            for (int j = 0; j < 16; j++)
                out[(size_t)(tok0 + j) * MAXF + f] = 0.f;
        }
    }

    int wid = t >> 5;
    #pragma unroll
    for (int j = 0; j < 16; j++) {
        float s = sq[j];
        #pragma unroll
        for (int off = 16; off > 0; off >>= 1) s += __shfl_xor_sync(0xffffffff, s, off);
        if ((t & 31) == 0) red[wid][j] = s;
    }
    __syncthreads();
    if (t < 16) {
        float s = 0.f;
        #pragma unroll
        for (int w = 0; w < 8; w++) s += red[w][t];
        g_esum[tok0 + t] = s;
    }
}

// ============================================================
// 5. Energy reduce
// ============================================================
__global__ void k_energy(float* __restrict__ e) {
    __shared__ float red[4];
    int b = blockIdx.x;
    int t = threadIdx.x;
    float s = 0.f;
    for (int i = t; i < NN; i += 128) s += g_esum[b * NN + i];
    #pragma unroll
    for (int off = 16; off > 0; off >>= 1) s += __shfl_xor_sync(0xffffffff, s, off);
    if ((t & 31) == 0) red[t >> 5] = s;
    __syncthreads();
    if (t == 0) e[b] = 0.5f * (red[0] + red[1] + red[2] + red[3]);
}

// ============================================================
extern "C" void kernel_launch(void* const* d_in, const int* in_sizes, int n_in,
                              void* d_out, int out_size) {
    const float* y      = (const float*)d_in[1];
    const float* in_w1_0 = (const float*)d_in[3];
    const float* in_w1_1 = (const float*)d_in[4];
    const float* in_w1_2 = (const float*)d_in[5];
    const float* in_w1_3 = (const float*)d_in[6];
    const float* out_w2_0 = (const float*)d_in[7];
    const float* out_w2_1 = (const float*)d_in[8];
    const float* out_w2_2 = (const float*)d_in[9];
    const float* out_w2_3 = (const float*)d_in[10];
    const float* out_b2_0 = (const float*)d_in[11];
    const float* out_b2_1 = (const float*)d_in[12];
    const float* out_b2_2 = (const float*)d_in[13];
    const float* out_b2_3 = (const float*)d_in[14];
    const float* in_b1  = (const float*)d_in[15];
    const float* in_w2  = (const float*)d_in[16];
    const float* in_b2  = (const float*)d_in[17];
    const float* out_w1 = (const float*)d_in[18];
    const float* out_b1 = (const float*)d_in[19];
    const float* qkv_w  = (const float*)d_in[20];
    const float* qkv_b  = (const float*)d_in[21];
    const float* attn_out_w = (const float*)d_in[22];
    const float* attn_out_b = (const float*)d_in[23];
    const float* ln1_w  = (const float*)d_in[24];
    const float* ln1_b  = (const float*)d_in[25];
    const float* ffn_w1 = (const float*)d_in[26];
    const float* ffn_b1 = (const float*)d_in[27];
    const float* ffn_w2 = (const float*)d_in[28];
    const float* ffn_b2 = (const float*)d_in[29];
    const float* ln2_w  = (const float*)d_in[30];
    const float* ln2_b  = (const float*)d_in[31];

    float* out = (float*)d_out;
    float* energy = out + (size_t)BB * NN * MAXF;

    const int NB = (BB * NN) / 16;   // 1024 blocks

    k_input_qkv<<<NB, 256>>>(y, in_w1_0, in_w1_1, in_w1_2, in_w1_3,
                             in_b1, in_w2, in_b2, qkv_w, qkv_b);
    k_attn<<<BB * NH * 4 * 2, 128>>>();
    k_pfq<<<NB, 256>>>(0, 1, attn_out_w, attn_out_b, ln1_w, ln1_b,
                       ffn_w1, ffn_b1, ffn_w2, ffn_b2, ln2_w, ln2_b, qkv_w, qkv_b);
    k_attn<<<BB * NH * 4 * 2, 128>>>();
    k_pfq<<<NB, 256>>>(1, 0, attn_out_w, attn_out_b, ln1_w, ln1_b,
                       ffn_w1, ffn_b1, ffn_w2, ffn_b2, ln2_w, ln2_b, qkv_w, qkv_b);
    k_out<<<NB, 256>>>(out, out_w1, out_b1,
                       out_w2_0, out_w2_1, out_w2_2, out_w2_3,
                       out_b2_0, out_b2_1, out_b2_2, out_b2_3);
    k_energy<<<BB, 128>>>(energy);
}

// round 7
// speedup vs baseline: 3.9052x; 1.0535x over previous
#include <cuda_runtime.h>
#include <cuda_bf16.h>
#include <math.h>
#include <stdint.h>

#define BB    16
#define NN    1024
#define HID   64
#define NH    4
#define HD    16
#define MLPH  128
#define FF    256
#define MAXF  512
#define LN_EPS 1e-5f

__device__ float g_x[BB * NN * HID];
__device__ float g_q[BB * NH * NN * HD];
__device__ float g_k[BB * NH * NN * HD];
__device__ float g_v[BB * NH * NN * HD];
__device__ float g_o[BB * NH * NN * HD];
__device__ float g_esum[BB * NN];

__device__ __forceinline__ float dot4(float4 a, float4 b) {
    return a.x * b.x + a.y * b.y + a.z * b.z + a.w * b.w;
}
__device__ __forceinline__ float4 ldg4(const float4* p) { return __ldg(p); }

// ---- tf32 helpers ----
__device__ __forceinline__ unsigned f2tf32(float x) {
    unsigned r;
    asm("cvt.rna.tf32.f32 %0, %1;" : "=r"(r) : "f"(x));
    return r;
}
__device__ __forceinline__ void tf32split(float x, unsigned& hi, unsigned& lo) {
    unsigned h = f2tf32(x);
    float r = x - __uint_as_float(h);
    lo = f2tf32(r);
    hi = h;
}
__device__ __forceinline__ void mma_tf32(float* c, const unsigned* a, unsigned b0, unsigned b1) {
    asm volatile(
        "mma.sync.aligned.m16n8k8.row.col.f32.tf32.tf32.f32 "
        "{%0,%1,%2,%3}, {%4,%5,%6,%7}, {%8,%9}, {%0,%1,%2,%3};"
        : "+f"(c[0]), "+f"(c[1]), "+f"(c[2]), "+f"(c[3])
        : "r"(a[0]), "r"(a[1]), "r"(a[2]), "r"(a[3]), "r"(b0), "r"(b1));
}

// ============================================================
// 1. Input MLP + QKV(layer 0): 16 tokens / block, 256 threads
// ============================================================
__global__ __launch_bounds__(256) void k_input_qkv(
        const float* __restrict__ y,
        const float* __restrict__ w1_0, const float* __restrict__ w1_1,
        const float* __restrict__ w1_2, const float* __restrict__ w1_3,
        const float* __restrict__ b1,   const float* __restrict__ w2,
        const float* __restrict__ b2,
        const float* __restrict__ qkv_w, const float* __restrict__ qkv_b) {
    __shared__ __align__(16) float sy[16 * MAXF];
    __shared__ __align__(16) float sh[16 * MLPH];
    __shared__ __align__(16) float sx[16 * HID];
    int tok0 = blockIdx.x * 16;
    int b    = tok0 >> 10;
    int n0   = tok0 & 1023;
    int seg  = n0 >> 8;
    int F    = 64 << seg;
    int F4   = F >> 2;
    const float* w1 = (seg == 0) ? w1_0 : (seg == 1) ? w1_1 : (seg == 2) ? w1_2 : w1_3;
    int t = threadIdx.x;

    {
        const float4* yg = (const float4*)y;
        float4* sy4 = (float4*)sy;
        for (int idx = t; idx < 16 * F4; idx += 256) {
            int tt = idx / F4, f4 = idx - tt * F4;
            sy4[tt * F4 + f4] = yg[(size_t)(tok0 + tt) * (MAXF / 4) + f4];
        }
    }
    __syncthreads();

    {
        int rep = t >> 7, h = t & 127;
        const float4* wr = (const float4*)(w1 + (size_t)h * F);
        float bi = b1[seg * MLPH + h];
        float acc[8];
        #pragma unroll
        for (int j = 0; j < 8; j++) acc[j] = bi;
        const float4* sy4 = (const float4*)sy + (rep * 8) * F4;
        #pragma unroll 4
        for (int k = 0; k < F4; k++) {
            float4 wt = ldg4(wr + k);
            #pragma unroll
            for (int j = 0; j < 8; j++) acc[j] += dot4(sy4[j * F4 + k], wt);
        }
        #pragma unroll
        for (int j = 0; j < 8; j++) sh[(rep * 8 + j) * MLPH + h] = tanhf(acc[j]);
    }
    __syncthreads();

    {
        int rep = t >> 6, c = t & 63;
        const float4* wr = (const float4*)(w2 + ((size_t)seg * HID + c) * MLPH);
        float bi = b2[seg * HID + c];
        float acc[4];
        #pragma unroll
        for (int j = 0; j < 4; j++) acc[j] = bi;
        const float4* a = (const float4*)sh + (rep * 4) * (MLPH / 4);
        #pragma unroll
        for (int k = 0; k < MLPH / 4; k++) {
            float4 wt = ldg4(wr + k);
            #pragma unroll
            for (int j = 0; j < 4; j++) acc[j] += dot4(a[j * (MLPH / 4) + k], wt);
        }
        #pragma unroll
        for (int j = 0; j < 4; j++) {
            int tok = rep * 4 + j;
            sx[tok * HID + c] = acc[j];
            g_x[(size_t)(tok0 + tok) * HID + c] = acc[j];
        }
    }
    __syncthreads();

    if (t < 192) {
        const float4* wr = (const float4*)(qkv_w + (size_t)t * HID);
        float bi = qkv_b[t];
        float acc[16];
        #pragma unroll
        for (int j = 0; j < 16; j++) acc[j] = bi;
        const float4* a = (const float4*)sx;
        #pragma unroll
        for (int k = 0; k < HID / 4; k++) {
            float4 wt = ldg4(wr + k);
            #pragma unroll
            for (int j = 0; j < 16; j++) acc[j] += dot4(a[j * (HID / 4) + k], wt);
        }
        int kind = t >> 6, w_ = t & 63, h = w_ >> 4, d = w_ & 15;
        float* dst = (kind == 0) ? g_q : (kind == 1) ? g_k : g_v;
        float scale = (kind == 0) ? 0.25f : 1.0f;
        size_t base = (((size_t)b * NH + h) * NN + n0) * HD + d;
        #pragma unroll
        for (int j = 0; j < 16; j++) dst[base + (size_t)j * HD] = acc[j] * scale;
    }
}

// ============================================================
// 2. Tensor-core attention (3xTF32): grid = bh(64) x qc(16) = 1024
//    128 threads = 4 warps, each warp owns 16 queries x all 1024 keys.
// ============================================================
#define KST 17                    // K/V smem row stride (floats)
#define PST 72                    // P smem row stride (floats)
__global__ __launch_bounds__(128) void k_attn() {
    __shared__ __align__(16) float sk[64 * KST];
    __shared__ __align__(16) float sv[64 * KST];
    __shared__ __align__(16) float sp[4 * 16 * PST];   // per-warp P tiles
    int bh = blockIdx.x >> 4;
    int qc = blockIdx.x & 15;
    int t  = threadIdx.x;
    int w  = t >> 5, lane = t & 31;
    int gid = lane >> 2, tig = lane & 3;
    size_t base = (size_t)bh * NN * HD;
    int q0 = qc * 64 + w * 16;
    float* spw = sp + w * 16 * PST;

    // Q fragments (big/small), reused across all chunks
    unsigned qb[8], qs[8];
    {
        const float* Qp = g_q + base + (size_t)q0 * HD;
        #pragma unroll
        for (int s = 0; s < 2; s++) {
            float a0 = Qp[(gid)     * HD + 8 * s + tig];
            float a1 = Qp[(gid + 8) * HD + 8 * s + tig];
            float a2 = Qp[(gid)     * HD + 8 * s + tig + 4];
            float a3 = Qp[(gid + 8) * HD + 8 * s + tig + 4];
            tf32split(a0, qb[s * 4 + 0], qs[s * 4 + 0]);
            tf32split(a1, qb[s * 4 + 1], qs[s * 4 + 1]);
            tf32split(a2, qb[s * 4 + 2], qs[s * 4 + 2]);
            tf32split(a3, qb[s * 4 + 3], qs[s * 4 + 3]);
        }
    }

    float O[2][4] = {{0.f,0.f,0.f,0.f},{0.f,0.f,0.f,0.f}};
    float ls1 = 0.f, ls2 = 0.f;

    for (int chunk = 0; chunk < 16; chunk++) {
        // stage K, V chunk (64 x 16)
        {
            const float4* kg = (const float4*)(g_k + base + (size_t)chunk * 64 * HD);
            const float4* vg = (const float4*)(g_v + base + (size_t)chunk * 64 * HD);
            #pragma unroll
            for (int i = 0; i < 2; i++) {
                int idx = t + i * 128;           // 0..255
                int row = idx >> 2, c4 = (idx & 3) * 4;
                float4 kk = kg[idx];
                float4 vvv = vg[idx];
                sk[row * KST + c4 + 0] = kk.x; sk[row * KST + c4 + 1] = kk.y;
                sk[row * KST + c4 + 2] = kk.z; sk[row * KST + c4 + 3] = kk.w;
                sv[row * KST + c4 + 0] = vvv.x; sv[row * KST + c4 + 1] = vvv.y;
                sv[row * KST + c4 + 2] = vvv.z; sv[row * KST + c4 + 3] = vvv.w;
            }
        }
        __syncthreads();

        // S = Q K^T  (16 x 64), 3xTF32
        float S[8][4];
        #pragma unroll
        for (int nt = 0; nt < 8; nt++) {
            S[nt][0] = S[nt][1] = S[nt][2] = S[nt][3] = 0.f;
            #pragma unroll
            for (int s = 0; s < 2; s++) {
                float b0f = sk[(8 * nt + gid) * KST + 8 * s + tig];
                float b1f = sk[(8 * nt + gid) * KST + 8 * s + tig + 4];
                unsigned bb0, bs0, bb1, bs1;
                tf32split(b0f, bb0, bs0);
                tf32split(b1f, bb1, bs1);
                mma_tf32(S[nt], qb + s * 4, bb0, bb1);
                mma_tf32(S[nt], qb + s * 4, bs0, bs1);
                mma_tf32(S[nt], qs + s * 4, bb0, bb1);
            }
        }

        // exp, row sums, store P tile to per-warp smem
        #pragma unroll
        for (int nt = 0; nt < 8; nt++) {
            float p0 = __expf(fminf(S[nt][0], 75.f));
            float p1 = __expf(fminf(S[nt][1], 75.f));
            float p2 = __expf(fminf(S[nt][2], 75.f));
            float p3 = __expf(fminf(S[nt][3], 75.f));
            ls1 += p0 + p1;
            ls2 += p2 + p3;
            int col = 8 * nt + 2 * tig;
            *(float2*)(spw + (gid)     * PST + col) = make_float2(p0, p1);
            *(float2*)(spw + (gid + 8) * PST + col) = make_float2(p2, p3);
        }
        __syncwarp();

        // O += P V  (16 x 16), 3xTF32
        #pragma unroll
        for (int s = 0; s < 8; s++) {
            float a0f = spw[(gid)     * PST + 8 * s + tig];
            float a1f = spw[(gid + 8) * PST + 8 * s + tig];
            float a2f = spw[(gid)     * PST + 8 * s + tig + 4];
            float a3f = spw[(gid + 8) * PST + 8 * s + tig + 4];
            unsigned ab[4], as[4];
            tf32split(a0f, ab[0], as[0]);
            tf32split(a1f, ab[1], as[1]);
            tf32split(a2f, ab[2], as[2]);
            tf32split(a3f, ab[3], as[3]);
            #pragma unroll
            for (int nt2 = 0; nt2 < 2; nt2++) {
                float v0f = sv[(8 * s + tig)     * KST + 8 * nt2 + gid];
                float v1f = sv[(8 * s + tig + 4) * KST + 8 * nt2 + gid];
                unsigned vb0, vs0, vb1, vs1;
                tf32split(v0f, vb0, vs0);
                tf32split(v1f, vb1, vs1);
                mma_tf32(O[nt2], ab, vb0, vb1);
                mma_tf32(O[nt2], ab, vs0, vs1);
                mma_tf32(O[nt2], as, vb0, vb1);
            }
        }
        __syncthreads();
    }

    // reduce row sums across the 4 lanes sharing a row
    ls1 += __shfl_xor_sync(0xffffffff, ls1, 1);
    ls1 += __shfl_xor_sync(0xffffffff, ls1, 2);
    ls2 += __shfl_xor_sync(0xffffffff, ls2, 1);
    ls2 += __shfl_xor_sync(0xffffffff, ls2, 2);
    float i1 = 1.f / ls1, i2 = 1.f / ls2;

    // store normalized O
    #pragma unroll
    for (int nt2 = 0; nt2 < 2; nt2++) {
        int col = 8 * nt2 + 2 * tig;
        *(float2*)(g_o + base + (size_t)(q0 + gid)     * HD + col) =
            make_float2(O[nt2][0] * i1, O[nt2][1] * i1);
        *(float2*)(g_o + base + (size_t)(q0 + gid + 8) * HD + col) =
            make_float2(O[nt2][2] * i2, O[nt2][3] * i2);
    }
}

// ============================================================
// 3. Proj + LN1 + FFN + LN2 (+ next-layer QKV)
// ============================================================
__global__ __launch_bounds__(256) void k_pfq(int l, int do_qkv,
        const float* __restrict__ W,   const float* __restrict__ bias,
        const float* __restrict__ ln1w, const float* __restrict__ ln1b,
        const float* __restrict__ fw1, const float* __restrict__ fb1,
        const float* __restrict__ fw2, const float* __restrict__ fb2,
        const float* __restrict__ ln2w, const float* __restrict__ ln2b,
        const float* __restrict__ qkv_w, const float* __restrict__ qkv_b) {
    __shared__ __align__(16) float so[16 * HID];
    __shared__ __align__(16) float sx1[16 * HID];
    __shared__ __align__(16) float sh[16 * FF];
    __shared__ float sval[16 * 66];
    int tok0 = blockIdx.x * 16;
    int b = tok0 >> 10, n0 = tok0 & 1023;
    int t = threadIdx.x;
    int wid = t >> 5, lane = t & 31;

    for (int idx = t; idx < 16 * HID; idx += 256) {
        int tt = idx >> 6, c = idx & 63;
        so[idx] = g_o[(((size_t)b * NH + (c >> 4)) * NN + n0 + tt) * HD + (c & 15)];
    }
    __syncthreads();

    {
        int rep = t >> 6, c = t & 63;
        const float4* wr = (const float4*)(W + ((size_t)l * HID + c) * HID);
        float bi = bias[l * HID + c];
        float acc[4];
        #pragma unroll
        for (int j = 0; j < 4; j++) acc[j] = bi;
        const float4* a = (const float4*)so + (rep * 4) * (HID / 4);
        #pragma unroll
        for (int k = 0; k < HID / 4; k++) {
            float4 wt = ldg4(wr + k);
            #pragma unroll
            for (int j = 0; j < 4; j++) acc[j] += dot4(a[j * (HID / 4) + k], wt);
        }
        #pragma unroll
        for (int j = 0; j < 4; j++) {
            int tok = rep * 4 + j;
            sval[tok * 66 + c] = g_x[(size_t)(tok0 + tok) * HID + c] + acc[j];
        }
    }
    __syncthreads();

    {
        int tA = 2 * wid, tB = 2 * wid + 1;
        float a0 = sval[tA * 66 + lane],      a1 = sval[tA * 66 + lane + 32];
        float b0 = sval[tB * 66 + lane],      b1 = sval[tB * 66 + lane + 32];
        float sA1 = a0 + a1, sA2 = a0 * a0 + a1 * a1;
        float sB1 = b0 + b1, sB2 = b0 * b0 + b1 * b1;
        #pragma unroll
        for (int off = 16; off > 0; off >>= 1) {
            sA1 += __shfl_xor_sync(0xffffffff, sA1, off);
            sA2 += __shfl_xor_sync(0xffffffff, sA2, off);
            sB1 += __shfl_xor_sync(0xffffffff, sB1, off);
            sB2 += __shfl_xor_sync(0xffffffff, sB2, off);
        }
        float mA = sA1 * (1.f / 64.f), vA = sA2 * (1.f / 64.f) - mA * mA;
        float mB = sB1 * (1.f / 64.f), vB = sB2 * (1.f / 64.f) - mB * mB;
        float rA = rsqrtf(vA + LN_EPS), rB = rsqrtf(vB + LN_EPS);
        float w0 = ln1w[l * HID + lane],      w1v = ln1w[l * HID + lane + 32];
        float bb0 = ln1b[l * HID + lane],     bb1 = ln1b[l * HID + lane + 32];
        sx1[tA * HID + lane]      = (a0 - mA) * rA * w0  + bb0;
        sx1[tA * HID + lane + 32] = (a1 - mA) * rA * w1v + bb1;
        sx1[tB * HID + lane]      = (b0 - mB) * rB * w0  + bb0;
        sx1[tB * HID + lane + 32] = (b1 - mB) * rB * w1v + bb1;
    }
    __syncthreads();

    {
        const float4* wr = (const float4*)(fw1 + ((size_t)l * FF + t) * HID);
        float bi = fb1[l * FF + t];
        float acc[16];
        #pragma unroll
        for (int j = 0; j < 16; j++) acc[j] = bi;
        const float4* a = (const float4*)sx1;
        #pragma unroll
        for (int k = 0; k < HID / 4; k++) {
            float4 wt = ldg4(wr + k);
            #pragma unroll
            for (int j = 0; j < 16; j++) acc[j] += dot4(a[j * (HID / 4) + k], wt);
        }
        #pragma unroll
        for (int j = 0; j < 16; j++) sh[j * FF + t] = fmaxf(acc[j], 0.f);
    }
    __syncthreads();

    {
        int rep = t >> 6, c = t & 63;
        const float4* wr = (const float4*)(fw2 + ((size_t)l * HID + c) * FF);
        float bi = fb2[l * HID + c];
        float acc[4];
        #pragma unroll
        for (int j = 0; j < 4; j++) acc[j] = bi;
        const float4* a = (const float4*)sh + (rep * 4) * (FF / 4);
        #pragma unroll 8
        for (int k = 0; k < FF / 4; k++) {
            float4 wt = ldg4(wr + k);
            #pragma unroll
            for (int j = 0; j < 4; j++) acc[j] += dot4(a[j * (FF / 4) + k], wt);
        }
        #pragma unroll
        for (int j = 0; j < 4; j++) {
            int tok = rep * 4 + j;
            sval[tok * 66 + c] = sx1[tok * HID + c] + acc[j];
        }
    }
    __syncthreads();

    {
        int tA = 2 * wid, tB = 2 * wid + 1;
        float a0 = sval[tA * 66 + lane],      a1 = sval[tA * 66 + lane + 32];
        float b0 = sval[tB * 66 + lane],      b1 = sval[tB * 66 + lane + 32];
        float sA1 = a0 + a1, sA2 = a0 * a0 + a1 * a1;
        float sB1 = b0 + b1, sB2 = b0 * b0 + b1 * b1;
        #pragma unroll
        for (int off = 16; off > 0; off >>= 1) {
            sA1 += __shfl_xor_sync(0xffffffff, sA1, off);
            sA2 += __shfl_xor_sync(0xffffffff, sA2, off);
            sB1 += __shfl_xor_sync(0xffffffff, sB1, off);
            sB2 += __shfl_xor_sync(0xffffffff, sB2, off);
        }
        float mA = sA1 * (1.f / 64.f), vA = sA2 * (1.f / 64.f) - mA * mA;
        float mB = sB1 * (1.f / 64.f), vB = sB2 * (1.f / 64.f) - mB * mB;
        float rA = rsqrtf(vA + LN_EPS), rB = rsqrtf(vB + LN_EPS);
        float w0 = ln2w[l * HID + lane],      w1v = ln2w[l * HID + lane + 32];
        float bb0 = ln2b[l * HID + lane],     bb1 = ln2b[l * HID + lane + 32];
        float oA0 = (a0 - mA) * rA * w0  + bb0;
        float oA1 = (a1 - mA) * rA * w1v + bb1;
        float oB0 = (b0 - mB) * rB * w0  + bb0;
        float oB1 = (b1 - mB) * rB * w1v + bb1;
        sx1[tA * HID + lane]      = oA0;
        sx1[tA * HID + lane + 32] = oA1;
        sx1[tB * HID + lane]      = oB0;
        sx1[tB * HID + lane + 32] = oB1;
        size_t gb = (size_t)(tok0 + tA) * HID;
        g_x[gb + lane]            = oA0;
        g_x[gb + lane + 32]       = oA1;
        g_x[gb + HID + lane]      = oB0;
        g_x[gb + HID + lane + 32] = oB1;
    }
    __syncthreads();

    if (do_qkv && t < 192) {
        const float4* wr = (const float4*)(qkv_w + ((size_t)(l + 1) * 192 + t) * HID);
        float bi = qkv_b[(l + 1) * 192 + t];
        float acc[16];
        #pragma unroll
        for (int j = 0; j < 16; j++) acc[j] = bi;
        const float4* a = (const float4*)sx1;
        #pragma unroll
        for (int k = 0; k < HID / 4; k++) {
            float4 wt = ldg4(wr + k);
            #pragma unroll
            for (int j = 0; j < 16; j++) acc[j] += dot4(a[j * (HID / 4) + k], wt);
        }
        int kind = t >> 6, w_ = t & 63, h = w_ >> 4, d = w_ & 15;
        float* dst = (kind == 0) ? g_q : (kind == 1) ? g_k : g_v;
        float scale = (kind == 0) ? 0.25f : 1.0f;
        size_t base = (((size_t)b * NH + h) * NN + n0) * HD + d;
        #pragma unroll
        for (int j = 0; j < 16; j++) dst[base + (size_t)j * HD] = acc[j] * scale;
    }
}

// ============================================================
// 4. Output head + energy partials: 16 tokens / block, 256 threads
// ============================================================
__global__ __launch_bounds__(256) void k_out(float* __restrict__ out,
        const float* __restrict__ ow1, const float* __restrict__ ob1,
        const float* __restrict__ w2_0, const float* __restrict__ w2_1,
        const float* __restrict__ w2_2, const float* __restrict__ w2_3,
        const float* __restrict__ b2_0, const float* __restrict__ b2_1,
        const float* __restrict__ b2_2, const float* __restrict__ b2_3) {
    __shared__ __align__(16) float sx[16 * HID];
    __shared__ __align__(16) float sh[16 * MLPH];
    __shared__ float red[8][16];
    int tok0 = blockIdx.x * 16;
    int n0 = tok0 & 1023;
    int seg = n0 >> 8;
    int F = 64 << seg;
    const float* w2 = (seg == 0) ? w2_0 : (seg == 1) ? w2_1 : (seg == 2) ? w2_2 : w2_3;
    const float* b2 = (seg == 0) ? b2_0 : (seg == 1) ? b2_1 : (seg == 2) ? b2_2 : b2_3;
    int t = threadIdx.x;
    for (int idx = t; idx < 16 * HID; idx += 256)
        sx[idx] = g_x[(size_t)tok0 * HID + idx];
    __syncthreads();

    {
        int rep = t >> 7, h = t & 127;
        const float4* wr = (const float4*)(ow1 + ((size_t)seg * MLPH + h) * HID);
        float bi = ob1[seg * MLPH + h];
        float acc[8];
        #pragma unroll
        for (int j = 0; j < 8; j++) acc[j] = bi;
        const float4* a = (const float4*)sx + (rep * 8) * (HID / 4);
        #pragma unroll
        for (int k = 0; k < HID / 4; k++) {
            float4 wt = ldg4(wr + k);
            #pragma unroll
            for (int j = 0; j < 8; j++) acc[j] += dot4(a[j * (HID / 4) + k], wt);
        }
        #pragma unroll
        for (int j = 0; j < 8; j++) sh[(rep * 8 + j) * MLPH + h] = tanhf(acc[j]);
    }
    __syncthreads();

    float sq[16];
    #pragma unroll
    for (int j = 0; j < 16; j++) sq[j] = 0.f;
    for (int f = t; f < MAXF; f += 256) {
        if (f < F) {
            const float4* wr = (const float4*)(w2 + (size_t)f * MLPH);
            float bi = b2[f];
            float acc[16];
            #pragma unroll
            for (int j = 0; j < 16; j++) acc[j] = bi;
            const float4* a = (const float4*)sh;
            #pragma unroll 4
            for (int k = 0; k < MLPH / 4; k++) {
                float4 wt = ldg4(wr + k);
                #pragma unroll
                for (int j = 0; j < 16; j++) acc[j] += dot4(a[j * (MLPH / 4) + k], wt);
            }
            #pragma unroll
            for (int j = 0; j < 16; j++) {
                out[(size_t)(tok0 + j) * MAXF + f] = acc[j];
                sq[j] += acc[j] * acc[j];
            }
        } else {
            #pragma unroll
            for (int j = 0; j < 16; j++)
                out[(size_t)(tok0 + j) * MAXF + f] = 0.f;
        }
    }

    int wid = t >> 5;
    #pragma unroll
    for (int j = 0; j < 16; j++) {
        float s = sq[j];
        #pragma unroll
        for (int off = 16; off > 0; off >>= 1) s += __shfl_xor_sync(0xffffffff, s, off);
        if ((t & 31) == 0) red[wid][j] = s;
    }
    __syncthreads();
    if (t < 16) {
        float s = 0.f;
        #pragma unroll
        for (int w = 0; w < 8; w++) s += red[w][t];
        g_esum[tok0 + t] = s;
    }
}

// ============================================================
// 5. Energy reduce
// ============================================================
__global__ void k_energy(float* __restrict__ e) {
    __shared__ float red[4];
    int b = blockIdx.x;
    int t = threadIdx.x;
    float s = 0.f;
    for (int i = t; i < NN; i += 128) s += g_esum[b * NN + i];
    #pragma unroll
    for (int off = 16; off > 0; off >>= 1) s += __shfl_xor_sync(0xffffffff, s, off);
    if ((t & 31) == 0) red[t >> 5] = s;
    __syncthreads();
    if (t == 0) e[b] = 0.5f * (red[0] + red[1] + red[2] + red[3]);
}

// ============================================================
extern "C" void kernel_launch(void* const* d_in, const int* in_sizes, int n_in,
                              void* d_out, int out_size) {
    const float* y      = (const float*)d_in[1];
    const float* in_w1_0 = (const float*)d_in[3];
    const float* in_w1_1 = (const float*)d_in[4];
    const float* in_w1_2 = (const float*)d_in[5];
    const float* in_w1_3 = (const float*)d_in[6];
    const float* out_w2_0 = (const float*)d_in[7];
    const float* out_w2_1 = (const float*)d_in[8];
    const float* out_w2_2 = (const float*)d_in[9];
    const float* out_w2_3 = (const float*)d_in[10];
    const float* out_b2_0 = (const float*)d_in[11];
    const float* out_b2_1 = (const float*)d_in[12];
    const float* out_b2_2 = (const float*)d_in[13];
    const float* out_b2_3 = (const float*)d_in[14];
    const float* in_b1  = (const float*)d_in[15];
    const float* in_w2  = (const float*)d_in[16];
    const float* in_b2  = (const float*)d_in[17];
    const float* out_w1 = (const float*)d_in[18];
    const float* out_b1 = (const float*)d_in[19];
    const float* qkv_w  = (const float*)d_in[20];
    const float* qkv_b  = (const float*)d_in[21];
    const float* attn_out_w = (const float*)d_in[22];
    const float* attn_out_b = (const float*)d_in[23];
    const float* ln1_w  = (const float*)d_in[24];
    const float* ln1_b  = (const float*)d_in[25];
    const float* ffn_w1 = (const float*)d_in[26];
    const float* ffn_b1 = (const float*)d_in[27];
    const float* ffn_w2 = (const float*)d_in[28];
    const float* ffn_b2 = (const float*)d_in[29];
    const float* ln2_w  = (const float*)d_in[30];
    const float* ln2_b  = (const float*)d_in[31];

    float* out = (float*)d_out;
    float* energy = out + (size_t)BB * NN * MAXF;

    const int NB = (BB * NN) / 16;   // 1024 blocks

    k_input_qkv<<<NB, 256>>>(y, in_w1_0, in_w1_1, in_w1_2, in_w1_3,
                             in_b1, in_w2, in_b2, qkv_w, qkv_b);
    k_attn<<<BB * NH * 16, 128>>>();
    k_pfq<<<NB, 256>>>(0, 1, attn_out_w, attn_out_b, ln1_w, ln1_b,
                       ffn_w1, ffn_b1, ffn_w2, ffn_b2, ln2_w, ln2_b, qkv_w, qkv_b);
    k_attn<<<BB * NH * 16, 128>>>();
    k_pfq<<<NB, 256>>>(1, 0, attn_out_w, attn_out_b, ln1_w, ln1_b,
                       ffn_w1, ffn_b1, ffn_w2, ffn_b2, ln2_w, ln2_b, qkv_w, qkv_b);
    k_out<<<NB, 256>>>(out, out_w1, out_b1,
                       out_w2_0, out_w2_1, out_w2_2, out_w2_3,
                       out_b2_0, out_b2_1, out_b2_2, out_b2_3);
    k_energy<<<BB, 128>>>(energy);
}

// round 8
// speedup vs baseline: 4.0239x; 1.0304x over previous
#include <cuda_runtime.h>
#include <cuda_bf16.h>
#include <math.h>
#include <stdint.h>

#define BB    16
#define NN    1024
#define HID   64
#define NH    4
#define HD    16
#define MLPH  128
#define FF    256
#define MAXF  512
#define LN_EPS 1e-5f

__device__ float g_x[BB * NN * HID];
__device__ float g_q[BB * NH * NN * HD];
__device__ float g_k[BB * NH * NN * HD];
__device__ float g_v[BB * NH * NN * HD];
__device__ float g_o[BB * NH * NN * HD];
__device__ float g_esum[BB * NN];

__device__ __forceinline__ float dot4(float4 a, float4 b) {
    return a.x * b.x + a.y * b.y + a.z * b.z + a.w * b.w;
}
__device__ __forceinline__ float4 ldg4(const float4* p) { return __ldg(p); }

// ---- tf32 helpers ----
__device__ __forceinline__ unsigned f2tf32(float x) {
    unsigned r;
    asm("cvt.rna.tf32.f32 %0, %1;" : "=r"(r) : "f"(x));
    return r;
}
__device__ __forceinline__ void tf32split(float x, unsigned& hi, unsigned& lo) {
    unsigned h = f2tf32(x);
    float r = x - __uint_as_float(h);
    lo = f2tf32(r);
    hi = h;
}
__device__ __forceinline__ void mma_tf32(float* c, const unsigned* a, unsigned b0, unsigned b1) {
    asm volatile(
        "mma.sync.aligned.m16n8k8.row.col.f32.tf32.tf32.f32 "
        "{%0,%1,%2,%3}, {%4,%5,%6,%7}, {%8,%9}, {%0,%1,%2,%3};"
        : "+f"(c[0]), "+f"(c[1]), "+f"(c[2]), "+f"(c[3])
        : "r"(a[0]), "r"(a[1]), "r"(a[2]), "r"(a[3]), "r"(b0), "r"(b1));
}

// ============================================================
// 1. Input MLP + QKV(layer 0): 16 tokens / block, 256 threads
// ============================================================
__global__ __launch_bounds__(256) void k_input_qkv(
        const float* __restrict__ y,
        const float* __restrict__ w1_0, const float* __restrict__ w1_1,
        const float* __restrict__ w1_2, const float* __restrict__ w1_3,
        const float* __restrict__ b1,   const float* __restrict__ w2,
        const float* __restrict__ b2,
        const float* __restrict__ qkv_w, const float* __restrict__ qkv_b) {
    __shared__ __align__(16) float sy[16 * MAXF];
    __shared__ __align__(16) float sh[16 * MLPH];
    __shared__ __align__(16) float sx[16 * HID];
    int tok0 = blockIdx.x * 16;
    int b    = tok0 >> 10;
    int n0   = tok0 & 1023;
    int seg  = n0 >> 8;
    int F    = 64 << seg;
    int F4   = F >> 2;
    const float* w1 = (seg == 0) ? w1_0 : (seg == 1) ? w1_1 : (seg == 2) ? w1_2 : w1_3;
    int t = threadIdx.x;

    {
        const float4* yg = (const float4*)y;
        float4* sy4 = (float4*)sy;
        for (int idx = t; idx < 16 * F4; idx += 256) {
            int tt = idx / F4, f4 = idx - tt * F4;
            sy4[tt * F4 + f4] = yg[(size_t)(tok0 + tt) * (MAXF / 4) + f4];
        }
    }
    __syncthreads();

    {
        int rep = t >> 7, h = t & 127;
        const float4* wr = (const float4*)(w1 + (size_t)h * F);
        float bi = b1[seg * MLPH + h];
        float acc[8];
        #pragma unroll
        for (int j = 0; j < 8; j++) acc[j] = bi;
        const float4* sy4 = (const float4*)sy + (rep * 8) * F4;
        #pragma unroll 4
        for (int k = 0; k < F4; k++) {
            float4 wt = ldg4(wr + k);
            #pragma unroll
            for (int j = 0; j < 8; j++) acc[j] += dot4(sy4[j * F4 + k], wt);
        }
        #pragma unroll
        for (int j = 0; j < 8; j++) sh[(rep * 8 + j) * MLPH + h] = tanhf(acc[j]);
    }
    __syncthreads();

    {
        int rep = t >> 6, c = t & 63;
        const float4* wr = (const float4*)(w2 + ((size_t)seg * HID + c) * MLPH);
        float bi = b2[seg * HID + c];
        float acc[4];
        #pragma unroll
        for (int j = 0; j < 4; j++) acc[j] = bi;
        const float4* a = (const float4*)sh + (rep * 4) * (MLPH / 4);
        #pragma unroll
        for (int k = 0; k < MLPH / 4; k++) {
            float4 wt = ldg4(wr + k);
            #pragma unroll
            for (int j = 0; j < 4; j++) acc[j] += dot4(a[j * (MLPH / 4) + k], wt);
        }
        #pragma unroll
        for (int j = 0; j < 4; j++) {
            int tok = rep * 4 + j;
            sx[tok * HID + c] = acc[j];
            g_x[(size_t)(tok0 + tok) * HID + c] = acc[j];
        }
    }
    __syncthreads();

    if (t < 192) {
        const float4* wr = (const float4*)(qkv_w + (size_t)t * HID);
        float bi = qkv_b[t];
        float acc[16];
        #pragma unroll
        for (int j = 0; j < 16; j++) acc[j] = bi;
        const float4* a = (const float4*)sx;
        #pragma unroll
        for (int k = 0; k < HID / 4; k++) {
            float4 wt = ldg4(wr + k);
            #pragma unroll
            for (int j = 0; j < 16; j++) acc[j] += dot4(a[j * (HID / 4) + k], wt);
        }
        int kind = t >> 6, w_ = t & 63, h = w_ >> 4, d = w_ & 15;
        float* dst = (kind == 0) ? g_q : (kind == 1) ? g_k : g_v;
        float scale = (kind == 0) ? 0.25f : 1.0f;
        size_t base = (((size_t)b * NH + h) * NN + n0) * HD + d;
        #pragma unroll
        for (int j = 0; j < 16; j++) dst[base + (size_t)j * HD] = acc[j] * scale;
    }
}

// ============================================================
// 2. Tensor-core attention: pre-split K/V (hi,lo) in smem,
//    P stored pre-converted tf32, 5 MMAs per (8x8x8)-equiv step.
// ============================================================
#define KVS 20                    // K/V smem row stride (uint2 elems)
#define PS  68                    // P smem row stride (unsigned elems)
__global__ __launch_bounds__(128) void k_attn() {
    __shared__ uint2    skhl[64 * KVS];          // 10.2 KB
    __shared__ uint2    svhl[64 * KVS];          // 10.2 KB
    __shared__ unsigned sp[4 * 16 * PS];         // 17.4 KB (per-warp P tiles)
    int bh = blockIdx.x >> 4;
    int qc = blockIdx.x & 15;
    int t  = threadIdx.x;
    int w  = t >> 5, lane = t & 31;
    int gid = lane >> 2, tig = lane & 3;
    size_t base = (size_t)bh * NN * HD;
    int q0 = qc * 64 + w * 16;
    unsigned* spw = sp + w * 16 * PS;

    // Q fragments (big/small), reused across all chunks
    unsigned qb[8], qs[8];
    {
        const float* Qp = g_q + base + (size_t)q0 * HD;
        #pragma unroll
        for (int s = 0; s < 2; s++) {
            float a0 = Qp[(gid)     * HD + 8 * s + tig];
            float a1 = Qp[(gid + 8) * HD + 8 * s + tig];
            float a2 = Qp[(gid)     * HD + 8 * s + tig + 4];
            float a3 = Qp[(gid + 8) * HD + 8 * s + tig + 4];
            tf32split(a0, qb[s * 4 + 0], qs[s * 4 + 0]);
            tf32split(a1, qb[s * 4 + 1], qs[s * 4 + 1]);
            tf32split(a2, qb[s * 4 + 2], qs[s * 4 + 2]);
            tf32split(a3, qb[s * 4 + 3], qs[s * 4 + 3]);
        }
    }

    float O[2][4] = {{0.f,0.f,0.f,0.f},{0.f,0.f,0.f,0.f}};
    float ls1 = 0.f, ls2 = 0.f;

    for (int chunk = 0; chunk < 16; chunk++) {
        // stage K, V chunk (64 x 16), splitting into (hi, lo) once per block
        {
            const float4* kg = (const float4*)(g_k + base + (size_t)chunk * 64 * HD);
            const float4* vg = (const float4*)(g_v + base + (size_t)chunk * 64 * HD);
            #pragma unroll
            for (int i = 0; i < 2; i++) {
                int idx = t + i * 128;           // 0..255
                int row = idx >> 2, c4 = (idx & 3) * 4;
                float4 kk = kg[idx];
                float4 vv = vg[idx];
                unsigned h0, l0, h1, l1, h2, l2, h3, l3;
                tf32split(kk.x, h0, l0); tf32split(kk.y, h1, l1);
                tf32split(kk.z, h2, l2); tf32split(kk.w, h3, l3);
                skhl[row * KVS + c4 + 0] = make_uint2(h0, l0);
                skhl[row * KVS + c4 + 1] = make_uint2(h1, l1);
                skhl[row * KVS + c4 + 2] = make_uint2(h2, l2);
                skhl[row * KVS + c4 + 3] = make_uint2(h3, l3);
                tf32split(vv.x, h0, l0); tf32split(vv.y, h1, l1);
                tf32split(vv.z, h2, l2); tf32split(vv.w, h3, l3);
                svhl[row * KVS + c4 + 0] = make_uint2(h0, l0);
                svhl[row * KVS + c4 + 1] = make_uint2(h1, l1);
                svhl[row * KVS + c4 + 2] = make_uint2(h2, l2);
                svhl[row * KVS + c4 + 3] = make_uint2(h3, l3);
            }
        }
        __syncthreads();

        // S = Q K^T  (16 x 64), 3xTF32
        float S[8][4];
        #pragma unroll
        for (int nt = 0; nt < 8; nt++) {
            S[nt][0] = S[nt][1] = S[nt][2] = S[nt][3] = 0.f;
            #pragma unroll
            for (int s = 0; s < 2; s++) {
                uint2 b0 = skhl[(8 * nt + gid) * KVS + 8 * s + tig];
                uint2 b1 = skhl[(8 * nt + gid) * KVS + 8 * s + tig + 4];
                mma_tf32(S[nt], qb + s * 4, b0.x, b1.x);  // Qhi*Khi
                mma_tf32(S[nt], qb + s * 4, b0.y, b1.y);  // Qhi*Klo
                mma_tf32(S[nt], qs + s * 4, b0.x, b1.x);  // Qlo*Khi
            }
        }

        // exp, row sums, store P (pre-converted tf32) to per-warp smem
        #pragma unroll
        for (int nt = 0; nt < 8; nt++) {
            float p0 = __expf(fminf(S[nt][0], 75.f));
            float p1 = __expf(fminf(S[nt][1], 75.f));
            float p2 = __expf(fminf(S[nt][2], 75.f));
            float p3 = __expf(fminf(S[nt][3], 75.f));
            ls1 += p0 + p1;
            ls2 += p2 + p3;
            int col = 8 * nt + 2 * tig;          // even -> 8B aligned
            *(uint2*)(spw + (gid)     * PS + col) = make_uint2(f2tf32(p0), f2tf32(p1));
            *(uint2*)(spw + (gid + 8) * PS + col) = make_uint2(f2tf32(p2), f2tf32(p3));
        }
        __syncwarp();

        // O += P V  (16 x 16): Phi*Vhi + Phi*Vlo
        #pragma unroll
        for (int s = 0; s < 8; s++) {
            unsigned a[4];
            a[0] = spw[(gid)     * PS + 8 * s + tig];
            a[1] = spw[(gid + 8) * PS + 8 * s + tig];
            a[2] = spw[(gid)     * PS + 8 * s + tig + 4];
            a[3] = spw[(gid + 8) * PS + 8 * s + tig + 4];
            #pragma unroll
            for (int nt2 = 0; nt2 < 2; nt2++) {
                uint2 v0 = svhl[(8 * s + tig)     * KVS + 8 * nt2 + gid];
                uint2 v1 = svhl[(8 * s + tig + 4) * KVS + 8 * nt2 + gid];
                mma_tf32(O[nt2], a, v0.x, v1.x);  // Phi*Vhi
                mma_tf32(O[nt2], a, v0.y, v1.y);  // Phi*Vlo
            }
        }
        __syncthreads();
    }

    // reduce row sums across the 4 lanes sharing a row
    ls1 += __shfl_xor_sync(0xffffffff, ls1, 1);
    ls1 += __shfl_xor_sync(0xffffffff, ls1, 2);
    ls2 += __shfl_xor_sync(0xffffffff, ls2, 1);
    ls2 += __shfl_xor_sync(0xffffffff, ls2, 2);
    float i1 = 1.f / ls1, i2 = 1.f / ls2;

    #pragma unroll
    for (int nt2 = 0; nt2 < 2; nt2++) {
        int col = 8 * nt2 + 2 * tig;
        *(float2*)(g_o + base + (size_t)(q0 + gid)     * HD + col) =
            make_float2(O[nt2][0] * i1, O[nt2][1] * i1);
        *(float2*)(g_o + base + (size_t)(q0 + gid + 8) * HD + col) =
            make_float2(O[nt2][2] * i2, O[nt2][3] * i2);
    }
}

// ============================================================
// 3. Proj + LN1 + FFN + LN2 (+ next-layer QKV)
// ============================================================
__global__ __launch_bounds__(256) void k_pfq(int l, int do_qkv,
        const float* __restrict__ W,   const float* __restrict__ bias,
        const float* __restrict__ ln1w, const float* __restrict__ ln1b,
        const float* __restrict__ fw1, const float* __restrict__ fb1,
        const float* __restrict__ fw2, const float* __restrict__ fb2,
        const float* __restrict__ ln2w, const float* __restrict__ ln2b,
        const float* __restrict__ qkv_w, const float* __restrict__ qkv_b) {
    __shared__ __align__(16) float so[16 * HID];
    __shared__ __align__(16) float sx1[16 * HID];
    __shared__ __align__(16) float sh[16 * FF];
    __shared__ float sval[16 * 66];
    int tok0 = blockIdx.x * 16;
    int b = tok0 >> 10, n0 = tok0 & 1023;
    int t = threadIdx.x;
    int wid = t >> 5, lane = t & 31;

    for (int idx = t; idx < 16 * HID; idx += 256) {
        int tt = idx >> 6, c = idx & 63;
        so[idx] = g_o[(((size_t)b * NH + (c >> 4)) * NN + n0 + tt) * HD + (c & 15)];
    }
    __syncthreads();

    {
        int rep = t >> 6, c = t & 63;
        const float4* wr = (const float4*)(W + ((size_t)l * HID + c) * HID);
        float bi = bias[l * HID + c];
        float acc[4];
        #pragma unroll
        for (int j = 0; j < 4; j++) acc[j] = bi;
        const float4* a = (const float4*)so + (rep * 4) * (HID / 4);
        #pragma unroll
        for (int k = 0; k < HID / 4; k++) {
            float4 wt = ldg4(wr + k);
            #pragma unroll
            for (int j = 0; j < 4; j++) acc[j] += dot4(a[j * (HID / 4) + k], wt);
        }
        #pragma unroll
        for (int j = 0; j < 4; j++) {
            int tok = rep * 4 + j;
            sval[tok * 66 + c] = g_x[(size_t)(tok0 + tok) * HID + c] + acc[j];
        }
    }
    __syncthreads();

    {
        int tA = 2 * wid, tB = 2 * wid + 1;
        float a0 = sval[tA * 66 + lane],      a1 = sval[tA * 66 + lane + 32];
        float b0 = sval[tB * 66 + lane],      b1 = sval[tB * 66 + lane + 32];
        float sA1 = a0 + a1, sA2 = a0 * a0 + a1 * a1;
        float sB1 = b0 + b1, sB2 = b0 * b0 + b1 * b1;
        #pragma unroll
        for (int off = 16; off > 0; off >>= 1) {
            sA1 += __shfl_xor_sync(0xffffffff, sA1, off);
            sA2 += __shfl_xor_sync(0xffffffff, sA2, off);
            sB1 += __shfl_xor_sync(0xffffffff, sB1, off);
            sB2 += __shfl_xor_sync(0xffffffff, sB2, off);
        }
        float mA = sA1 * (1.f / 64.f), vA = sA2 * (1.f / 64.f) - mA * mA;
        float mB = sB1 * (1.f / 64.f), vB = sB2 * (1.f / 64.f) - mB * mB;
        float rA = rsqrtf(vA + LN_EPS), rB = rsqrtf(vB + LN_EPS);
        float w0 = ln1w[l * HID + lane],      w1v = ln1w[l * HID + lane + 32];
        float bb0 = ln1b[l * HID + lane],     bb1 = ln1b[l * HID + lane + 32];
        sx1[tA * HID + lane]      = (a0 - mA) * rA * w0  + bb0;
        sx1[tA * HID + lane + 32] = (a1 - mA) * rA * w1v + bb1;
        sx1[tB * HID + lane]      = (b0 - mB) * rB * w0  + bb0;
        sx1[tB * HID + lane + 32] = (b1 - mB) * rB * w1v + bb1;
    }
    __syncthreads();

    {
        const float4* wr = (const float4*)(fw1 + ((size_t)l * FF + t) * HID);
        float bi = fb1[l * FF + t];
        float acc[16];
        #pragma unroll
        for (int j = 0; j < 16; j++) acc[j] = bi;
        const float4* a = (const float4*)sx1;
        #pragma unroll
        for (int k = 0; k < HID / 4; k++) {
            float4 wt = ldg4(wr + k);
            #pragma unroll
            for (int j = 0; j < 16; j++) acc[j] += dot4(a[j * (HID / 4) + k], wt);
        }
        #pragma unroll
        for (int j = 0; j < 16; j++) sh[j * FF + t] = fmaxf(acc[j], 0.f);
    }
    __syncthreads();

    {
        int rep = t >> 6, c = t & 63;
        const float4* wr = (const float4*)(fw2 + ((size_t)l * HID + c) * FF);
        float bi = fb2[l * HID + c];
        float acc[4];
        #pragma unroll
        for (int j = 0; j < 4; j++) acc[j] = bi;
        const float4* a = (const float4*)sh + (rep * 4) * (FF / 4);
        #pragma unroll 8
        for (int k = 0; k < FF / 4; k++) {
            float4 wt = ldg4(wr + k);
            #pragma unroll
            for (int j = 0; j < 4; j++) acc[j] += dot4(a[j * (FF / 4) + k], wt);
        }
        #pragma unroll
        for (int j = 0; j < 4; j++) {
            int tok = rep * 4 + j;
            sval[tok * 66 + c] = sx1[tok * HID + c] + acc[j];
        }
    }
    __syncthreads();

    {
        int tA = 2 * wid, tB = 2 * wid + 1;
        float a0 = sval[tA * 66 + lane],      a1 = sval[tA * 66 + lane + 32];
        float b0 = sval[tB * 66 + lane],      b1 = sval[tB * 66 + lane + 32];
        float sA1 = a0 + a1, sA2 = a0 * a0 + a1 * a1;
        float sB1 = b0 + b1, sB2 = b0 * b0 + b1 * b1;
        #pragma unroll
        for (int off = 16; off > 0; off >>= 1) {
            sA1 += __shfl_xor_sync(0xffffffff, sA1, off);
            sA2 += __shfl_xor_sync(0xffffffff, sA2, off);
            sB1 += __shfl_xor_sync(0xffffffff, sB1, off);
            sB2 += __shfl_xor_sync(0xffffffff, sB2, off);
        }
        float mA = sA1 * (1.f / 64.f), vA = sA2 * (1.f / 64.f) - mA * mA;
        float mB = sB1 * (1.f / 64.f), vB = sB2 * (1.f / 64.f) - mB * mB;
        float rA = rsqrtf(vA + LN_EPS), rB = rsqrtf(vB + LN_EPS);
        float w0 = ln2w[l * HID + lane],      w1v = ln2w[l * HID + lane + 32];
        float bb0 = ln2b[l * HID + lane],     bb1 = ln2b[l * HID + lane + 32];
        float oA0 = (a0 - mA) * rA * w0  + bb0;
        float oA1 = (a1 - mA) * rA * w1v + bb1;
        float oB0 = (b0 - mB) * rB * w0  + bb0;
        float oB1 = (b1 - mB) * rB * w1v + bb1;
        sx1[tA * HID + lane]      = oA0;
        sx1[tA * HID + lane + 32] = oA1;
        sx1[tB * HID + lane]      = oB0;
        sx1[tB * HID + lane + 32] = oB1;
        size_t gb = (size_t)(tok0 + tA) * HID;
        g_x[gb + lane]            = oA0;
        g_x[gb + lane + 32]       = oA1;
        g_x[gb + HID + lane]      = oB0;
        g_x[gb + HID + lane + 32] = oB1;
    }
    __syncthreads();

    if (do_qkv && t < 192) {
        const float4* wr = (const float4*)(qkv_w + ((size_t)(l + 1) * 192 + t) * HID);
        float bi = qkv_b[(l + 1) * 192 + t];
        float acc[16];
        #pragma unroll
        for (int j = 0; j < 16; j++) acc[j] = bi;
        const float4* a = (const float4*)sx1;
        #pragma unroll
        for (int k = 0; k < HID / 4; k++) {
            float4 wt = ldg4(wr + k);
            #pragma unroll
            for (int j = 0; j < 16; j++) acc[j] += dot4(a[j * (HID / 4) + k], wt);
        }
        int kind = t >> 6, w_ = t & 63, h = w_ >> 4, d = w_ & 15;
        float* dst = (kind == 0) ? g_q : (kind == 1) ? g_k : g_v;
        float scale = (kind == 0) ? 0.25f : 1.0f;
        size_t base = (((size_t)b * NH + h) * NN + n0) * HD + d;
        #pragma unroll
        for (int j = 0; j < 16; j++) dst[base + (size_t)j * HD] = acc[j] * scale;
    }
}

// ============================================================
// 4. Output head + energy partials: 16 tokens / block, 256 threads
// ============================================================
__global__ __launch_bounds__(256) void k_out(float* __restrict__ out,
        const float* __restrict__ ow1, const float* __restrict__ ob1,
        const float* __restrict__ w2_0, const float* __restrict__ w2_1,
        const float* __restrict__ w2_2, const float* __restrict__ w2_3,
        const float* __restrict__ b2_0, const float* __restrict__ b2_1,
        const float* __restrict__ b2_2, const float* __restrict__ b2_3) {
    __shared__ __align__(16) float sx[16 * HID];
    __shared__ __align__(16) float sh[16 * MLPH];
    __shared__ float red[8][16];
    int tok0 = blockIdx.x * 16;
    int n0 = tok0 & 1023;
    int seg = n0 >> 8;
    int F = 64 << seg;
    const float* w2 = (seg == 0) ? w2_0 : (seg == 1) ? w2_1 : (seg == 2) ? w2_2 : w2_3;
    const float* b2 = (seg == 0) ? b2_0 : (seg == 1) ? b2_1 : (seg == 2) ? b2_2 : b2_3;
    int t = threadIdx.x;
    for (int idx = t; idx < 16 * HID; idx += 256)
        sx[idx] = g_x[(size_t)tok0 * HID + idx];
    __syncthreads();

    {
        int rep = t >> 7, h = t & 127;
        const float4* wr = (const float4*)(ow1 + ((size_t)seg * MLPH + h) * HID);
        float bi = ob1[seg * MLPH + h];
        float acc[8];
        #pragma unroll
        for (int j = 0; j < 8; j++) acc[j] = bi;
        const float4* a = (const float4*)sx + (rep * 8) * (HID / 4);
        #pragma unroll
        for (int k = 0; k < HID / 4; k++) {
            float4 wt = ldg4(wr + k);
            #pragma unroll
            for (int j = 0; j < 8; j++) acc[j] += dot4(a[j * (HID / 4) + k], wt);
        }
        #pragma unroll
        for (int j = 0; j < 8; j++) sh[(rep * 8 + j) * MLPH + h] = tanhf(acc[j]);
    }
    __syncthreads();

    float sq[16];
    #pragma unroll
    for (int j = 0; j < 16; j++) sq[j] = 0.f;
    for (int f = t; f < MAXF; f += 256) {
        if (f < F) {
            const float4* wr = (const float4*)(w2 + (size_t)f * MLPH);
            float bi = b2[f];
            float acc[16];
            #pragma unroll
            for (int j = 0; j < 16; j++) acc[j] = bi;
            const float4* a = (const float4*)sh;
            #pragma unroll 4
            for (int k = 0; k < MLPH / 4; k++) {
                float4 wt = ldg4(wr + k);
                #pragma unroll
                for (int j = 0; j < 16; j++) acc[j] += dot4(a[j * (MLPH / 4) + k], wt);
            }
            #pragma unroll
            for (int j = 0; j < 16; j++) {
                out[(size_t)(tok0 + j) * MAXF + f] = acc[j];
                sq[j] += acc[j] * acc[j];
            }
        } else {
            #pragma unroll
            for (int j = 0; j < 16; j++)
                out[(size_t)(tok0 + j) * MAXF + f] = 0.f;
        }
    }

    int wid = t >> 5;
    #pragma unroll
    for (int j = 0; j < 16; j++) {
        float s = sq[j];
        #pragma unroll
        for (int off = 16; off > 0; off >>= 1) s += __shfl_xor_sync(0xffffffff, s, off);
        if ((t & 31) == 0) red[wid][j] = s;
    }
    __syncthreads();
    if (t < 16) {
        float s = 0.f;
        #pragma unroll
        for (int w = 0; w < 8; w++) s += red[w][t];
        g_esum[tok0 + t] = s;
    }
}

// ============================================================
// 5. Energy reduce
// ============================================================
__global__ void k_energy(float* __restrict__ e) {
    __shared__ float red[4];
    int b = blockIdx.x;
    int t = threadIdx.x;
    float s = 0.f;
    for (int i = t; i < NN; i += 128) s += g_esum[b * NN + i];
    #pragma unroll
    for (int off = 16; off > 0; off >>= 1) s += __shfl_xor_sync(0xffffffff, s, off);
    if ((t & 31) == 0) red[t >> 5] = s;
    __syncthreads();
    if (t == 0) e[b] = 0.5f * (red[0] + red[1] + red[2] + red[3]);
}

// ============================================================
extern "C" void kernel_launch(void* const* d_in, const int* in_sizes, int n_in,
                              void* d_out, int out_size) {
    const float* y      = (const float*)d_in[1];
    const float* in_w1_0 = (const float*)d_in[3];
    const float* in_w1_1 = (const float*)d_in[4];
    const float* in_w1_2 = (const float*)d_in[5];
    const float* in_w1_3 = (const float*)d_in[6];
    const float* out_w2_0 = (const float*)d_in[7];
    const float* out_w2_1 = (const float*)d_in[8];
    const float* out_w2_2 = (const float*)d_in[9];
    const float* out_w2_3 = (const float*)d_in[10];
    const float* out_b2_0 = (const float*)d_in[11];
    const float* out_b2_1 = (const float*)d_in[12];
    const float* out_b2_2 = (const float*)d_in[13];
    const float* out_b2_3 = (const float*)d_in[14];
    const float* in_b1  = (const float*)d_in[15];
    const float* in_w2  = (const float*)d_in[16];
    const float* in_b2  = (const float*)d_in[17];
    const float* out_w1 = (const float*)d_in[18];
    const float* out_b1 = (const float*)d_in[19];
    const float* qkv_w  = (const float*)d_in[20];
    const float* qkv_b  = (const float*)d_in[21];
    const float* attn_out_w = (const float*)d_in[22];
    const float* attn_out_b = (const float*)d_in[23];
    const float* ln1_w  = (const float*)d_in[24];
    const float* ln1_b  = (const float*)d_in[25];
    const float* ffn_w1 = (const float*)d_in[26];
    const float* ffn_b1 = (const float*)d_in[27];
    const float* ffn_w2 = (const float*)d_in[28];
    const float* ffn_b2 = (const float*)d_in[29];
    const float* ln2_w  = (const float*)d_in[30];
    const float* ln2_b  = (const float*)d_in[31];

    float* out = (float*)d_out;
    float* energy = out + (size_t)BB * NN * MAXF;

    const int NB = (BB * NN) / 16;   // 1024 blocks

    k_input_qkv<<<NB, 256>>>(y, in_w1_0, in_w1_1, in_w1_2, in_w1_3,
                             in_b1, in_w2, in_b2, qkv_w, qkv_b);
    k_attn<<<BB * NH * 16, 128>>>();
    k_pfq<<<NB, 256>>>(0, 1, attn_out_w, attn_out_b, ln1_w, ln1_b,
                       ffn_w1, ffn_b1, ffn_w2, ffn_b2, ln2_w, ln2_b, qkv_w, qkv_b);
    k_attn<<<BB * NH * 16, 128>>>();
    k_pfq<<<NB, 256>>>(1, 0, attn_out_w, attn_out_b, ln1_w, ln1_b,
                       ffn_w1, ffn_b1, ffn_w2, ffn_b2, ln2_w, ln2_b, qkv_w, qkv_b);
    k_out<<<NB, 256>>>(out, out_w1, out_b1,
                       out_w2_0, out_w2_1, out_w2_2, out_w2_3,
                       out_b2_0, out_b2_1, out_b2_2, out_b2_3);
    k_energy<<<BB, 128>>>(energy);
}

// round 9
// speedup vs baseline: 4.6522x; 1.1561x over previous
#include <cuda_runtime.h>
#include <cuda_bf16.h>
#include <math.h>
#include <stdint.h>

#define BB    16
#define NN    1024
#define HID   64
#define NH    4
#define HD    16
#define MLPH  128
#define FF    256
#define MAXF  512
#define LN_EPS 1e-5f
#define SHP   132                 // padded stride for 128-wide smem tiles

__device__ float g_x[BB * NN * HID];
__device__ float g_q[BB * NH * NN * HD];
__device__ uint2 g_khl[BB * NH * NN * HD];
__device__ uint2 g_vhl[BB * NH * NN * HD];
__device__ float g_o[BB * NH * NN * HD];
__device__ float g_esum[BB * NN];
__device__ uint2 g_w1hl[122880];   // in_w1 segs: offsets 0,8192,24576,57344
__device__ uint2 g_w2hl[122880];   // out_w2 segs: same offsets

__device__ __forceinline__ float dot4(float4 a, float4 b) {
    return a.x * b.x + a.y * b.y + a.z * b.z + a.w * b.w;
}
__device__ __forceinline__ float4 ldg4(const float4* p) { return __ldg(p); }

__device__ __forceinline__ unsigned f2tf32(float x) {
    unsigned r;
    asm("cvt.rna.tf32.f32 %0, %1;" : "=r"(r) : "f"(x));
    return r;
}
__device__ __forceinline__ void tf32split(float x, unsigned& hi, unsigned& lo) {
    unsigned h = f2tf32(x);
    float r = x - __uint_as_float(h);
    lo = f2tf32(r);
    hi = h;
}
__device__ __forceinline__ void mma_tf32(float* c, const unsigned* a, unsigned b0, unsigned b1) {
    asm volatile(
        "mma.sync.aligned.m16n8k8.row.col.f32.tf32.tf32.f32 "
        "{%0,%1,%2,%3}, {%4,%5,%6,%7}, {%8,%9}, {%0,%1,%2,%3};"
        : "+f"(c[0]), "+f"(c[1]), "+f"(c[2]), "+f"(c[3])
        : "r"(a[0]), "r"(a[1]), "r"(a[2]), "r"(a[3]), "r"(b0), "r"(b1));
}

// ============================================================
// 0. Weight pre-split: in_w1_* and out_w2_* -> (hi,lo) uint2
// ============================================================
__global__ __launch_bounds__(256) void k_presplit(
        const float* __restrict__ w1_0, const float* __restrict__ w1_1,
        const float* __restrict__ w1_2, const float* __restrict__ w1_3,
        const float* __restrict__ w2_0, const float* __restrict__ w2_1,
        const float* __restrict__ w2_2, const float* __restrict__ w2_3) {
    int i = blockIdx.x * 256 + threadIdx.x;
    if (i >= 122880) return;
    const float *s1, *s2;
    int off;
    if (i < 8192)       { s1 = w1_0; s2 = w2_0; off = i; }
    else if (i < 24576) { s1 = w1_1; s2 = w2_1; off = i - 8192; }
    else if (i < 57344) { s1 = w1_2; s2 = w2_2; off = i - 24576; }
    else                { s1 = w1_3; s2 = w2_3; off = i - 57344; }
    unsigned hi, lo;
    tf32split(s1[off], hi, lo);
    g_w1hl[i] = make_uint2(hi, lo);
    tf32split(s2[off], hi, lo);
    g_w2hl[i] = make_uint2(hi, lo);
}

// ============================================================
// 1. Input MLP (phase1 MMA) + QKV(layer 0): templated by segment
//    16 tokens / block, 256 threads; grid 256 per segment
// ============================================================
template<int SEG>
__global__ __launch_bounds__(256) void k_input_qkv(
        const float* __restrict__ y,
        const float* __restrict__ b1,   const float* __restrict__ w2,
        const float* __restrict__ b2,
        const float* __restrict__ qkv_w, const float* __restrict__ qkv_b) {
    constexpr int F   = 64 << SEG;
    constexpr int FP  = F + 4;
    constexpr int KS  = F / 8;
    constexpr int WOFF = (SEG == 0) ? 0 : (SEG == 1) ? 8192 : (SEG == 2) ? 24576 : 57344;
    __shared__ __align__(16) float sy[16 * FP];
    __shared__ __align__(16) float sh[16 * SHP];
    __shared__ __align__(16) float sx[16 * HID];
    int blk = blockIdx.x;
    int b   = blk >> 4, ti = blk & 15;
    int tok0 = b * 1024 + SEG * 256 + ti * 16;
    int n0   = tok0 & 1023;
    int t = threadIdx.x;
    int w = t >> 5, lane = t & 31;
    int gid = lane >> 2, tig = lane & 3;

    // stage y[16][F]
    {
        const float4* yg = (const float4*)y;
        float4* sy4 = (float4*)sy;
        for (int idx = t; idx < 16 * (F / 4); idx += 256) {
            int tt = idx / (F / 4), f4 = idx - tt * (F / 4);
            sy4[tt * (FP / 4) + f4] = yg[(size_t)(tok0 + tt) * (MAXF / 4) + f4];
        }
    }
    __syncthreads();

    // phase 1 (MMA): h = tanh(y @ w1^T + b1); warp w covers cols [8w..8w+7] and [8(w+8)..]
    {
        int colA = w * 8 + 2 * tig;
        int colB = (w + 8) * 8 + 2 * tig;
        float C0[4], C1[4];
        C0[0] = C0[2] = b1[SEG * MLPH + colA]; C0[1] = C0[3] = b1[SEG * MLPH + colA + 1];
        C1[0] = C1[2] = b1[SEG * MLPH + colB]; C1[1] = C1[3] = b1[SEG * MLPH + colB + 1];
        const uint2* w1a = g_w1hl + WOFF;
        #pragma unroll 2
        for (int ks = 0; ks < KS; ks++) {
            int k0 = ks * 8;
            unsigned ab[4], as[4];
            tf32split(sy[(gid)     * FP + k0 + tig],     ab[0], as[0]);
            tf32split(sy[(gid + 8) * FP + k0 + tig],     ab[1], as[1]);
            tf32split(sy[(gid)     * FP + k0 + tig + 4], ab[2], as[2]);
            tf32split(sy[(gid + 8) * FP + k0 + tig + 4], ab[3], as[3]);
            uint2 b0 = w1a[(w * 8 + gid) * F + k0 + tig];
            uint2 b1v = w1a[(w * 8 + gid) * F + k0 + tig + 4];
            mma_tf32(C0, ab, b0.x, b1v.x);
            mma_tf32(C0, ab, b0.y, b1v.y);
            mma_tf32(C0, as, b0.x, b1v.x);
            b0  = w1a[((w + 8) * 8 + gid) * F + k0 + tig];
            b1v = w1a[((w + 8) * 8 + gid) * F + k0 + tig + 4];
            mma_tf32(C1, ab, b0.x, b1v.x);
            mma_tf32(C1, ab, b0.y, b1v.y);
            mma_tf32(C1, as, b0.x, b1v.x);
        }
        sh[(gid)     * SHP + colA]     = tanhf(C0[0]);
        sh[(gid)     * SHP + colA + 1] = tanhf(C0[1]);
        sh[(gid + 8) * SHP + colA]     = tanhf(C0[2]);
        sh[(gid + 8) * SHP + colA + 1] = tanhf(C0[3]);
        sh[(gid)     * SHP + colB]     = tanhf(C1[0]);
        sh[(gid)     * SHP + colB + 1] = tanhf(C1[1]);
        sh[(gid + 8) * SHP + colB]     = tanhf(C1[2]);
        sh[(gid + 8) * SHP + colB + 1] = tanhf(C1[3]);
    }
    __syncthreads();

    // phase 2: x = h @ w2^T + b2; 4 reps x 64 c, 4 tokens each
    {
        int rep = t >> 6, c = t & 63;
        const float4* wr = (const float4*)(w2 + ((size_t)SEG * HID + c) * MLPH);
        float bi = b2[SEG * HID + c];
        float acc[4];
        #pragma unroll
        for (int j = 0; j < 4; j++) acc[j] = bi;
        const float4* a = (const float4*)sh + (rep * 4) * (SHP / 4);
        #pragma unroll
        for (int k = 0; k < MLPH / 4; k++) {
            float4 wt = ldg4(wr + k);
            #pragma unroll
            for (int j = 0; j < 4; j++) acc[j] += dot4(a[j * (SHP / 4) + k], wt);
        }
        #pragma unroll
        for (int j = 0; j < 4; j++) {
            int tok = rep * 4 + j;
            sx[tok * HID + c] = acc[j];
            g_x[(size_t)(tok0 + tok) * HID + c] = acc[j];
        }
    }
    __syncthreads();

    // phase 3: qkv (layer 0)
    if (t < 192) {
        const float4* wr = (const float4*)(qkv_w + (size_t)t * HID);
        float bi = qkv_b[t];
        float acc[16];
        #pragma unroll
        for (int j = 0; j < 16; j++) acc[j] = bi;
        const float4* a = (const float4*)sx;
        #pragma unroll
        for (int k = 0; k < HID / 4; k++) {
            float4 wt = ldg4(wr + k);
            #pragma unroll
            for (int j = 0; j < 16; j++) acc[j] += dot4(a[j * (HID / 4) + k], wt);
        }
        int kind = t >> 6, w_ = t & 63, h = w_ >> 4, d = w_ & 15;
        size_t base = (((size_t)b * NH + h) * NN + n0) * HD + d;
        if (kind == 0) {
            #pragma unroll
            for (int j = 0; j < 16; j++) g_q[base + (size_t)j * HD] = acc[j] * 0.25f;
        } else {
            uint2* dst = (kind == 1) ? g_khl : g_vhl;
            #pragma unroll
            for (int j = 0; j < 16; j++) {
                unsigned hi, lo;
                tf32split(acc[j], hi, lo);
                dst[base + (size_t)j * HD] = make_uint2(hi, lo);
            }
        }
    }
}

// ============================================================
// 2. Tensor-core attention: K/V pre-split by producers
// ============================================================
#define KVS 20
#define PS  68
__global__ __launch_bounds__(128) void k_attn() {
    __shared__ uint2    skhl[64 * KVS];
    __shared__ uint2    svhl[64 * KVS];
    __shared__ unsigned sp[4 * 16 * PS];
    int bh = blockIdx.x >> 4;
    int qc = blockIdx.x & 15;
    int t  = threadIdx.x;
    int w  = t >> 5, lane = t & 31;
    int gid = lane >> 2, tig = lane & 3;
    size_t base = (size_t)bh * NN * HD;
    int q0 = qc * 64 + w * 16;
    unsigned* spw = sp + w * 16 * PS;

    unsigned qb[8], qs[8];
    {
        const float* Qp = g_q + base + (size_t)q0 * HD;
        #pragma unroll
        for (int s = 0; s < 2; s++) {
            tf32split(Qp[(gid)     * HD + 8 * s + tig],     qb[s * 4 + 0], qs[s * 4 + 0]);
            tf32split(Qp[(gid + 8) * HD + 8 * s + tig],     qb[s * 4 + 1], qs[s * 4 + 1]);
            tf32split(Qp[(gid)     * HD + 8 * s + tig + 4], qb[s * 4 + 2], qs[s * 4 + 2]);
            tf32split(Qp[(gid + 8) * HD + 8 * s + tig + 4], qb[s * 4 + 3], qs[s * 4 + 3]);
        }
    }

    float O[2][4] = {{0.f,0.f,0.f,0.f},{0.f,0.f,0.f,0.f}};
    float ls1 = 0.f, ls2 = 0.f;

    for (int chunk = 0; chunk < 16; chunk++) {
        // stage K/V chunk: pure uint4 copy (already split)
        {
            const uint4* kg = (const uint4*)(g_khl + base + (size_t)chunk * 64 * HD);
            const uint4* vg = (const uint4*)(g_vhl + base + (size_t)chunk * 64 * HD);
            #pragma unroll
            for (int i = 0; i < 4; i++) {
                int idx4 = t + i * 128;           // 0..511
                int row = idx4 >> 3;
                int c = (idx4 & 7) * 2;
                *(uint4*)&skhl[row * KVS + c] = kg[idx4];
                *(uint4*)&svhl[row * KVS + c] = vg[idx4];
            }
        }
        __syncthreads();

        // S = Q K^T (16 x 64)
        float S[8][4];
        #pragma unroll
        for (int nt = 0; nt < 8; nt++) {
            S[nt][0] = S[nt][1] = S[nt][2] = S[nt][3] = 0.f;
            #pragma unroll
            for (int s = 0; s < 2; s++) {
                uint2 b0 = skhl[(8 * nt + gid) * KVS + 8 * s + tig];
                uint2 b1 = skhl[(8 * nt + gid) * KVS + 8 * s + tig + 4];
                mma_tf32(S[nt], qb + s * 4, b0.x, b1.x);
                mma_tf32(S[nt], qb + s * 4, b0.y, b1.y);
                mma_tf32(S[nt], qs + s * 4, b0.x, b1.x);
            }
        }

        // exp + row sums + store P (tf32)
        #pragma unroll
        for (int nt = 0; nt < 8; nt++) {
            float p0 = __expf(fminf(S[nt][0], 75.f));
            float p1 = __expf(fminf(S[nt][1], 75.f));
            float p2 = __expf(fminf(S[nt][2], 75.f));
            float p3 = __expf(fminf(S[nt][3], 75.f));
            ls1 += p0 + p1;
            ls2 += p2 + p3;
            int col = 8 * nt + 2 * tig;
            *(uint2*)(spw + (gid)     * PS + col) = make_uint2(f2tf32(p0), f2tf32(p1));
            *(uint2*)(spw + (gid + 8) * PS + col) = make_uint2(f2tf32(p2), f2tf32(p3));
        }
        __syncwarp();

        // O += P V
        #pragma unroll
        for (int s = 0; s < 8; s++) {
            unsigned a[4];
            a[0] = spw[(gid)     * PS + 8 * s + tig];
            a[1] = spw[(gid + 8) * PS + 8 * s + tig];
            a[2] = spw[(gid)     * PS + 8 * s + tig + 4];
            a[3] = spw[(gid + 8) * PS + 8 * s + tig + 4];
            #pragma unroll
            for (int nt2 = 0; nt2 < 2; nt2++) {
                uint2 v0 = svhl[(8 * s + tig)     * KVS + 8 * nt2 + gid];
                uint2 v1 = svhl[(8 * s + tig + 4) * KVS + 8 * nt2 + gid];
                mma_tf32(O[nt2], a, v0.x, v1.x);
                mma_tf32(O[nt2], a, v0.y, v1.y);
            }
        }
        __syncthreads();
    }

    ls1 += __shfl_xor_sync(0xffffffff, ls1, 1);
    ls1 += __shfl_xor_sync(0xffffffff, ls1, 2);
    ls2 += __shfl_xor_sync(0xffffffff, ls2, 1);
    ls2 += __shfl_xor_sync(0xffffffff, ls2, 2);
    float i1 = 1.f / ls1, i2 = 1.f / ls2;

    #pragma unroll
    for (int nt2 = 0; nt2 < 2; nt2++) {
        int col = 8 * nt2 + 2 * tig;
        *(float2*)(g_o + base + (size_t)(q0 + gid)     * HD + col) =
            make_float2(O[nt2][0] * i1, O[nt2][1] * i1);
        *(float2*)(g_o + base + (size_t)(q0 + gid + 8) * HD + col) =
            make_float2(O[nt2][2] * i2, O[nt2][3] * i2);
    }
}

// ============================================================
// 3. Proj + LN1 + FFN + LN2 (+ next-layer QKV)
// ============================================================
__global__ __launch_bounds__(256) void k_pfq(int l, int do_qkv,
        const float* __restrict__ W,   const float* __restrict__ bias,
        const float* __restrict__ ln1w, const float* __restrict__ ln1b,
        const float* __restrict__ fw1, const float* __restrict__ fb1,
        const float* __restrict__ fw2, const float* __restrict__ fb2,
        const float* __restrict__ ln2w, const float* __restrict__ ln2b,
        const float* __restrict__ qkv_w, const float* __restrict__ qkv_b) {
    __shared__ __align__(16) float so[16 * HID];
    __shared__ __align__(16) float sx1[16 * HID];
    __shared__ __align__(16) float sh[16 * FF];
    __shared__ float sval[16 * 66];
    int tok0 = blockIdx.x * 16;
    int b = tok0 >> 10, n0 = tok0 & 1023;
    int t = threadIdx.x;
    int wid = t >> 5, lane = t & 31;

    for (int idx = t; idx < 16 * HID; idx += 256) {
        int tt = idx >> 6, c = idx & 63;
        so[idx] = g_o[(((size_t)b * NH + (c >> 4)) * NN + n0 + tt) * HD + (c & 15)];
    }
    __syncthreads();

    {
        int rep = t >> 6, c = t & 63;
        const float4* wr = (const float4*)(W + ((size_t)l * HID + c) * HID);
        float bi = bias[l * HID + c];
        float acc[4];
        #pragma unroll
        for (int j = 0; j < 4; j++) acc[j] = bi;
        const float4* a = (const float4*)so + (rep * 4) * (HID / 4);
        #pragma unroll
        for (int k = 0; k < HID / 4; k++) {
            float4 wt = ldg4(wr + k);
            #pragma unroll
            for (int j = 0; j < 4; j++) acc[j] += dot4(a[j * (HID / 4) + k], wt);
        }
        #pragma unroll
        for (int j = 0; j < 4; j++) {
            int tok = rep * 4 + j;
            sval[tok * 66 + c] = g_x[(size_t)(tok0 + tok) * HID + c] + acc[j];
        }
    }
    __syncthreads();

    {
        int tA = 2 * wid, tB = 2 * wid + 1;
        float a0 = sval[tA * 66 + lane],      a1 = sval[tA * 66 + lane + 32];
        float b0 = sval[tB * 66 + lane],      b1 = sval[tB * 66 + lane + 32];
        float sA1 = a0 + a1, sA2 = a0 * a0 + a1 * a1;
        float sB1 = b0 + b1, sB2 = b0 * b0 + b1 * b1;
        #pragma unroll
        for (int off = 16; off > 0; off >>= 1) {
            sA1 += __shfl_xor_sync(0xffffffff, sA1, off);
            sA2 += __shfl_xor_sync(0xffffffff, sA2, off);
            sB1 += __shfl_xor_sync(0xffffffff, sB1, off);
            sB2 += __shfl_xor_sync(0xffffffff, sB2, off);
        }
        float mA = sA1 * (1.f / 64.f), vA = sA2 * (1.f / 64.f) - mA * mA;
        float mB = sB1 * (1.f / 64.f), vB = sB2 * (1.f / 64.f) - mB * mB;
        float rA = rsqrtf(vA + LN_EPS), rB = rsqrtf(vB + LN_EPS);
        float w0 = ln1w[l * HID + lane],      w1v = ln1w[l * HID + lane + 32];
        float bb0 = ln1b[l * HID + lane],     bb1 = ln1b[l * HID + lane + 32];
        sx1[tA * HID + lane]      = (a0 - mA) * rA * w0  + bb0;
        sx1[tA * HID + lane + 32] = (a1 - mA) * rA * w1v + bb1;
        sx1[tB * HID + lane]      = (b0 - mB) * rB * w0  + bb0;
        sx1[tB * HID + lane + 32] = (b1 - mB) * rB * w1v + bb1;
    }
    __syncthreads();

    {
        const float4* wr = (const float4*)(fw1 + ((size_t)l * FF + t) * HID);
        float bi = fb1[l * FF + t];
        float acc[16];
        #pragma unroll
        for (int j = 0; j < 16; j++) acc[j] = bi;
        const float4* a = (const float4*)sx1;
        #pragma unroll
        for (int k = 0; k < HID / 4; k++) {
            float4 wt = ldg4(wr + k);
            #pragma unroll
            for (int j = 0; j < 16; j++) acc[j] += dot4(a[j * (HID / 4) + k], wt);
        }
        #pragma unroll
        for (int j = 0; j < 16; j++) sh[j * FF + t] = fmaxf(acc[j], 0.f);
    }
    __syncthreads();

    {
        int rep = t >> 6, c = t & 63;
        const float4* wr = (const float4*)(fw2 + ((size_t)l * HID + c) * FF);
        float bi = fb2[l * HID + c];
        float acc[4];
        #pragma unroll
        for (int j = 0; j < 4; j++) acc[j] = bi;
        const float4* a = (const float4*)sh + (rep * 4) * (FF / 4);
        #pragma unroll 8
        for (int k = 0; k < FF / 4; k++) {
            float4 wt = ldg4(wr + k);
            #pragma unroll
            for (int j = 0; j < 4; j++) acc[j] += dot4(a[j * (FF / 4) + k], wt);
        }
        #pragma unroll
        for (int j = 0; j < 4; j++) {
            int tok = rep * 4 + j;
            sval[tok * 66 + c] = sx1[tok * HID + c] + acc[j];
        }
    }
    __syncthreads();

    {
        int tA = 2 * wid, tB = 2 * wid + 1;
        float a0 = sval[tA * 66 + lane],      a1 = sval[tA * 66 + lane + 32];
        float b0 = sval[tB * 66 + lane],      b1 = sval[tB * 66 + lane + 32];
        float sA1 = a0 + a1, sA2 = a0 * a0 + a1 * a1;
        float sB1 = b0 + b1, sB2 = b0 * b0 + b1 * b1;
        #pragma unroll
        for (int off = 16; off > 0; off >>= 1) {
            sA1 += __shfl_xor_sync(0xffffffff, sA1, off);
            sA2 += __shfl_xor_sync(0xffffffff, sA2, off);
            sB1 += __shfl_xor_sync(0xffffffff, sB1, off);
            sB2 += __shfl_xor_sync(0xffffffff, sB2, off);
        }
        float mA = sA1 * (1.f / 64.f), vA = sA2 * (1.f / 64.f) - mA * mA;
        float mB = sB1 * (1.f / 64.f), vB = sB2 * (1.f / 64.f) - mB * mB;
        float rA = rsqrtf(vA + LN_EPS), rB = rsqrtf(vB + LN_EPS);
        float w0 = ln2w[l * HID + lane],      w1v = ln2w[l * HID + lane + 32];
        float bb0 = ln2b[l * HID + lane],     bb1 = ln2b[l * HID + lane + 32];
        float oA0 = (a0 - mA) * rA * w0  + bb0;
        float oA1 = (a1 - mA) * rA * w1v + bb1;
        float oB0 = (b0 - mB) * rB * w0  + bb0;
        float oB1 = (b1 - mB) * rB * w1v + bb1;
        sx1[tA * HID + lane]      = oA0;
        sx1[tA * HID + lane + 32] = oA1;
        sx1[tB * HID + lane]      = oB0;
        sx1[tB * HID + lane + 32] = oB1;
        size_t gb = (size_t)(tok0 + tA) * HID;
        g_x[gb + lane]            = oA0;
        g_x[gb + lane + 32]       = oA1;
        g_x[gb + HID + lane]      = oB0;
        g_x[gb + HID + lane + 32] = oB1;
    }
    __syncthreads();

    if (do_qkv && t < 192) {
        const float4* wr = (const float4*)(qkv_w + ((size_t)(l + 1) * 192 + t) * HID);
        float bi = qkv_b[(l + 1) * 192 + t];
        float acc[16];
        #pragma unroll
        for (int j = 0; j < 16; j++) acc[j] = bi;
        const float4* a = (const float4*)sx1;
        #pragma unroll
        for (int k = 0; k < HID / 4; k++) {
            float4 wt = ldg4(wr + k);
            #pragma unroll
            for (int j = 0; j < 16; j++) acc[j] += dot4(a[j * (HID / 4) + k], wt);
        }
        int kind = t >> 6, w_ = t & 63, h = w_ >> 4, d = w_ & 15;
        size_t base = (((size_t)b * NH + h) * NN + n0) * HD + d;
        if (kind == 0) {
            #pragma unroll
            for (int j = 0; j < 16; j++) g_q[base + (size_t)j * HD] = acc[j] * 0.25f;
        } else {
            uint2* dst = (kind == 1) ? g_khl : g_vhl;
            #pragma unroll
            for (int j = 0; j < 16; j++) {
                unsigned hi, lo;
                tf32split(acc[j], hi, lo);
                dst[base + (size_t)j * HD] = make_uint2(hi, lo);
            }
        }
    }
}

// ============================================================
// 4. Output head (phase2 MMA) + energy: templated by segment
// ============================================================
template<int SEG>
__global__ __launch_bounds__(256) void k_out(float* __restrict__ out,
        const float* __restrict__ ow1, const float* __restrict__ ob1,
        const float* __restrict__ b2) {
    constexpr int F  = 64 << SEG;
    constexpr int NT = F / 64;                // n-tiles per warp
    constexpr int WOFF = (SEG == 0) ? 0 : (SEG == 1) ? 8192 : (SEG == 2) ? 24576 : 57344;
    __shared__ __align__(16) float sx[16 * HID];
    __shared__ __align__(16) float sh[16 * SHP];
    __shared__ float red[8][16];
    int blk = blockIdx.x;
    int b   = blk >> 4, ti = blk & 15;
    int tok0 = b * 1024 + SEG * 256 + ti * 16;
    int t = threadIdx.x;
    int w = t >> 5, lane = t & 31;
    int gid = lane >> 2, tig = lane & 3;

    for (int idx = t; idx < 16 * HID; idx += 256)
        sx[idx] = g_x[(size_t)tok0 * HID + idx];
    __syncthreads();

    // phase 1 (FFMA): tanh hidden
    {
        int rep = t >> 7, h = t & 127;
        const float4* wr = (const float4*)(ow1 + ((size_t)SEG * MLPH + h) * HID);
        float bi = ob1[SEG * MLPH + h];
        float acc[8];
        #pragma unroll
        for (int j = 0; j < 8; j++) acc[j] = bi;
        const float4* a = (const float4*)sx + (rep * 8) * (HID / 4);
        #pragma unroll
        for (int k = 0; k < HID / 4; k++) {
            float4 wt = ldg4(wr + k);
            #pragma unroll
            for (int j = 0; j < 8; j++) acc[j] += dot4(a[j * (HID / 4) + k], wt);
        }
        #pragma unroll
        for (int j = 0; j < 8; j++) sh[(rep * 8 + j) * SHP + h] = tanhf(acc[j]);
    }
    __syncthreads();

    // phase 2 (MMA): d = h @ w2^T + b2; warp w covers tiles w, w+8, ...
    {
        float C[NT][4];
        #pragma unroll
        for (int j = 0; j < NT; j++) {
            int col0 = (w + j * 8) * 8 + 2 * tig;
            C[j][0] = C[j][2] = b2[col0];
            C[j][1] = C[j][3] = b2[col0 + 1];
        }
        const uint2* w2a = g_w2hl + WOFF;
        #pragma unroll 2
        for (int ks = 0; ks < 16; ks++) {
            int k0 = ks * 8;
            unsigned ab[4], as[4];
            tf32split(sh[(gid)     * SHP + k0 + tig],     ab[0], as[0]);
            tf32split(sh[(gid + 8) * SHP + k0 + tig],     ab[1], as[1]);
            tf32split(sh[(gid)     * SHP + k0 + tig + 4], ab[2], as[2]);
            tf32split(sh[(gid + 8) * SHP + k0 + tig + 4], ab[3], as[3]);
            #pragma unroll
            for (int j = 0; j < NT; j++) {
                int nb = (w + j * 8) * 8 + gid;
                uint2 b0 = w2a[nb * MLPH + k0 + tig];
                uint2 b1 = w2a[nb * MLPH + k0 + tig + 4];
                mma_tf32(C[j], ab, b0.x, b1.x);
                mma_tf32(C[j], ab, b0.y, b1.y);
                mma_tf32(C[j], as, b0.x, b1.x);
            }
        }

        float sqA = 0.f, sqB = 0.f;
        #pragma unroll
        for (int j = 0; j < NT; j++) {
            int col0 = (w + j * 8) * 8 + 2 * tig;
            *(float2*)&out[(size_t)(tok0 + gid)     * MAXF + col0] = make_float2(C[j][0], C[j][1]);
            *(float2*)&out[(size_t)(tok0 + gid + 8) * MAXF + col0] = make_float2(C[j][2], C[j][3]);
            sqA += C[j][0] * C[j][0] + C[j][1] * C[j][1];
            sqB += C[j][2] * C[j][2] + C[j][3] * C[j][3];
        }
        sqA += __shfl_xor_sync(0xffffffff, sqA, 1);
        sqA += __shfl_xor_sync(0xffffffff, sqA, 2);
        sqB += __shfl_xor_sync(0xffffffff, sqB, 1);
        sqB += __shfl_xor_sync(0xffffffff, sqB, 2);
        if (tig == 0) { red[w][gid] = sqA; red[w][gid + 8] = sqB; }
    }

    // zero padding cols F..MAXF
    if (SEG < 3) {
        constexpr int PADW = (MAXF - F) / 4;
        float4 z = make_float4(0.f, 0.f, 0.f, 0.f);
        for (int i = t; i < 16 * PADW; i += 256) {
            int r = i / PADW, c = i - r * PADW;
            *((float4*)&out[(size_t)(tok0 + r) * MAXF + F] + c) = z;
        }
    }
    __syncthreads();
    if (t < 16) {
        float s = 0.f;
        #pragma unroll
        for (int ww = 0; ww < 8; ww++) s += red[ww][t];
        g_esum[tok0 + t] = s;
    }
}

// ============================================================
// 5. Energy reduce
// ============================================================
__global__ void k_energy(float* __restrict__ e) {
    __shared__ float red[4];
    int b = blockIdx.x;
    int t = threadIdx.x;
    float s = 0.f;
    for (int i = t; i < NN; i += 128) s += g_esum[b * NN + i];
    #pragma unroll
    for (int off = 16; off > 0; off >>= 1) s += __shfl_xor_sync(0xffffffff, s, off);
    if ((t & 31) == 0) red[t >> 5] = s;
    __syncthreads();
    if (t == 0) e[b] = 0.5f * (red[0] + red[1] + red[2] + red[3]);
}

// ============================================================
extern "C" void kernel_launch(void* const* d_in, const int* in_sizes, int n_in,
                              void* d_out, int out_size) {
    const float* y      = (const float*)d_in[1];
    const float* in_w1_0 = (const float*)d_in[3];
    const float* in_w1_1 = (const float*)d_in[4];
    const float* in_w1_2 = (const float*)d_in[5];
    const float* in_w1_3 = (const float*)d_in[6];
    const float* out_w2_0 = (const float*)d_in[7];
    const float* out_w2_1 = (const float*)d_in[8];
    const float* out_w2_2 = (const float*)d_in[9];
    const float* out_w2_3 = (const float*)d_in[10];
    const float* out_b2_0 = (const float*)d_in[11];
    const float* out_b2_1 = (const float*)d_in[12];
    const float* out_b2_2 = (const float*)d_in[13];
    const float* out_b2_3 = (const float*)d_in[14];
    const float* in_b1  = (const float*)d_in[15];
    const float* in_w2  = (const float*)d_in[16];
    const float* in_b2  = (const float*)d_in[17];
    const float* out_w1 = (const float*)d_in[18];
    const float* out_b1 = (const float*)d_in[19];
    const float* qkv_w  = (const float*)d_in[20];
    const float* qkv_b  = (const float*)d_in[21];
    const float* attn_out_w = (const float*)d_in[22];
    const float* attn_out_b = (const float*)d_in[23];
    const float* ln1_w  = (const float*)d_in[24];
    const float* ln1_b  = (const float*)d_in[25];
    const float* ffn_w1 = (const float*)d_in[26];
    const float* ffn_b1 = (const float*)d_in[27];
    const float* ffn_w2 = (const float*)d_in[28];
    const float* ffn_b2 = (const float*)d_in[29];
    const float* ln2_w  = (const float*)d_in[30];
    const float* ln2_b  = (const float*)d_in[31];

    float* out = (float*)d_out;
    float* energy = out + (size_t)BB * NN * MAXF;

    const int NB  = (BB * NN) / 16;   // 1024
    const int NBS = BB * 16;          // 256 per segment

    k_presplit<<<480, 256>>>(in_w1_0, in_w1_1, in_w1_2, in_w1_3,
                             out_w2_0, out_w2_1, out_w2_2, out_w2_3);

    k_input_qkv<0><<<NBS, 256>>>(y, in_b1, in_w2, in_b2, qkv_w, qkv_b);
    k_input_qkv<1><<<NBS, 256>>>(y, in_b1, in_w2, in_b2, qkv_w, qkv_b);
    k_input_qkv<2><<<NBS, 256>>>(y, in_b1, in_w2, in_b2, qkv_w, qkv_b);
    k_input_qkv<3><<<NBS, 256>>>(y, in_b1, in_w2, in_b2, qkv_w, qkv_b);

    k_attn<<<BB * NH * 16, 128>>>();
    k_pfq<<<NB, 256>>>(0, 1, attn_out_w, attn_out_b, ln1_w, ln1_b,
                       ffn_w1, ffn_b1, ffn_w2, ffn_b2, ln2_w, ln2_b, qkv_w, qkv_b);
    k_attn<<<BB * NH * 16, 128>>>();
    k_pfq<<<NB, 256>>>(1, 0, attn_out_w, attn_out_b, ln1_w, ln1_b,
                       ffn_w1, ffn_b1, ffn_w2, ffn_b2, ln2_w, ln2_b, qkv_w, qkv_b);

    k_out<0><<<NBS, 256>>>(out, out_w1, out_b1, out_b2_0);
    k_out<1><<<NBS, 256>>>(out, out_w1, out_b1, out_b2_1);
    k_out<2><<<NBS, 256>>>(out, out_w1, out_b1, out_b2_2);
    k_out<3><<<NBS, 256>>>(out, out_w1, out_b1, out_b2_3);

    k_energy<<<BB, 128>>>(energy);
}

// round 10
// speedup vs baseline: 4.7151x; 1.0135x over previous
#include <cuda_runtime.h>
#include <cuda_bf16.h>
#include <math.h>
#include <stdint.h>

#define BB    16
#define NN    1024
#define HID   64
#define NH    4
#define HD    16
#define MLPH  128
#define FF    256
#define MAXF  512
#define LN_EPS 1e-5f
#define SHP   132

__device__ float g_x[BB * NN * HID];
__device__ float g_q[BB * NH * NN * HD];
__device__ uint2 g_khl[BB * NH * NN * HD];
__device__ uint2 g_vhl[BB * NH * NN * HD];
__device__ float g_o[BB * NH * NN * HD];
__device__ float g_esum[BB * NN];
__device__ uint2 g_w1hl[122880];
__device__ uint2 g_w2hl[122880];

__device__ __forceinline__ float dot4(float4 a, float4 b) {
    return a.x * b.x + a.y * b.y + a.z * b.z + a.w * b.w;
}
__device__ __forceinline__ float4 ldg4(const float4* p) { return __ldg(p); }

__device__ __forceinline__ unsigned f2tf32(float x) {
    unsigned r;
    asm("cvt.rna.tf32.f32 %0, %1;" : "=r"(r) : "f"(x));
    return r;
}
__device__ __forceinline__ void tf32split(float x, unsigned& hi, unsigned& lo) {
    unsigned h = f2tf32(x);
    float r = x - __uint_as_float(h);
    lo = f2tf32(r);
    hi = h;
}
__device__ __forceinline__ void mma_tf32(float* c, const unsigned* a, unsigned b0, unsigned b1) {
    asm volatile(
        "mma.sync.aligned.m16n8k8.row.col.f32.tf32.tf32.f32 "
        "{%0,%1,%2,%3}, {%4,%5,%6,%7}, {%8,%9}, {%0,%1,%2,%3};"
        : "+f"(c[0]), "+f"(c[1]), "+f"(c[2]), "+f"(c[3])
        : "r"(a[0]), "r"(a[1]), "r"(a[2]), "r"(a[3]), "r"(b0), "r"(b1));
}

// ============================================================
// 0. Weight pre-split
// ============================================================
__global__ __launch_bounds__(256) void k_presplit(
        const float* __restrict__ w1_0, const float* __restrict__ w1_1,
        const float* __restrict__ w1_2, const float* __restrict__ w1_3,
        const float* __restrict__ w2_0, const float* __restrict__ w2_1,
        const float* __restrict__ w2_2, const float* __restrict__ w2_3) {
    int i = blockIdx.x * 256 + threadIdx.x;
    if (i >= 122880) return;
    const float *s1, *s2;
    int off;
    if (i < 8192)       { s1 = w1_0; s2 = w2_0; off = i; }
    else if (i < 24576) { s1 = w1_1; s2 = w2_1; off = i - 8192; }
    else if (i < 57344) { s1 = w1_2; s2 = w2_2; off = i - 24576; }
    else                { s1 = w1_3; s2 = w2_3; off = i - 57344; }
    unsigned hi, lo;
    tf32split(s1[off], hi, lo);
    g_w1hl[i] = make_uint2(hi, lo);
    tf32split(s2[off], hi, lo);
    g_w2hl[i] = make_uint2(hi, lo);
}

// ============================================================
// 1. Input MLP + QKV(layer 0) body (templated), merged kernel
// ============================================================
template<int SEG>
__device__ __forceinline__ void input_body(
        float* sy, float* sh, float* sx,
        int tok0, int b, int n0,
        const float* __restrict__ y,
        const float* __restrict__ b1, const float* __restrict__ w2,
        const float* __restrict__ b2,
        const float* __restrict__ qkv_w, const float* __restrict__ qkv_b) {
    constexpr int F   = 64 << SEG;
    constexpr int FP  = F + 4;
    constexpr int KS  = F / 8;
    constexpr int WOFF = (SEG == 0) ? 0 : (SEG == 1) ? 8192 : (SEG == 2) ? 24576 : 57344;
    int t = threadIdx.x;
    int w = t >> 5, lane = t & 31;
    int gid = lane >> 2, tig = lane & 3;

    {
        const float4* yg = (const float4*)y;
        float4* sy4 = (float4*)sy;
        for (int idx = t; idx < 16 * (F / 4); idx += 256) {
            int tt = idx / (F / 4), f4 = idx - tt * (F / 4);
            sy4[tt * (FP / 4) + f4] = yg[(size_t)(tok0 + tt) * (MAXF / 4) + f4];
        }
    }
    __syncthreads();

    {
        int colA = w * 8 + 2 * tig;
        int colB = (w + 8) * 8 + 2 * tig;
        float C0[4], C1[4];
        C0[0] = C0[2] = b1[SEG * MLPH + colA]; C0[1] = C0[3] = b1[SEG * MLPH + colA + 1];
        C1[0] = C1[2] = b1[SEG * MLPH + colB]; C1[1] = C1[3] = b1[SEG * MLPH + colB + 1];
        const uint2* w1a = g_w1hl + WOFF;
        #pragma unroll 2
        for (int ks = 0; ks < KS; ks++) {
            int k0 = ks * 8;
            unsigned ab[4], as[4];
            tf32split(sy[(gid)     * FP + k0 + tig],     ab[0], as[0]);
            tf32split(sy[(gid + 8) * FP + k0 + tig],     ab[1], as[1]);
            tf32split(sy[(gid)     * FP + k0 + tig + 4], ab[2], as[2]);
            tf32split(sy[(gid + 8) * FP + k0 + tig + 4], ab[3], as[3]);
            uint2 b0 = w1a[(w * 8 + gid) * F + k0 + tig];
            uint2 b1v = w1a[(w * 8 + gid) * F + k0 + tig + 4];
            mma_tf32(C0, ab, b0.x, b1v.x);
            mma_tf32(C0, ab, b0.y, b1v.y);
            mma_tf32(C0, as, b0.x, b1v.x);
            b0  = w1a[((w + 8) * 8 + gid) * F + k0 + tig];
            b1v = w1a[((w + 8) * 8 + gid) * F + k0 + tig + 4];
            mma_tf32(C1, ab, b0.x, b1v.x);
            mma_tf32(C1, ab, b0.y, b1v.y);
            mma_tf32(C1, as, b0.x, b1v.x);
        }
        sh[(gid)     * SHP + colA]     = tanhf(C0[0]);
        sh[(gid)     * SHP + colA + 1] = tanhf(C0[1]);
        sh[(gid + 8) * SHP + colA]     = tanhf(C0[2]);
        sh[(gid + 8) * SHP + colA + 1] = tanhf(C0[3]);
        sh[(gid)     * SHP + colB]     = tanhf(C1[0]);
        sh[(gid)     * SHP + colB + 1] = tanhf(C1[1]);
        sh[(gid + 8) * SHP + colB]     = tanhf(C1[2]);
        sh[(gid + 8) * SHP + colB + 1] = tanhf(C1[3]);
    }
    __syncthreads();

    {
        int rep = t >> 6, c = t & 63;
        const float4* wr = (const float4*)(w2 + ((size_t)SEG * HID + c) * MLPH);
        float bi = b2[SEG * HID + c];
        float acc[4];
        #pragma unroll
        for (int j = 0; j < 4; j++) acc[j] = bi;
        const float4* a = (const float4*)sh + (rep * 4) * (SHP / 4);
        #pragma unroll
        for (int k = 0; k < MLPH / 4; k++) {
            float4 wt = ldg4(wr + k);
            #pragma unroll
            for (int j = 0; j < 4; j++) acc[j] += dot4(a[j * (SHP / 4) + k], wt);
        }
        #pragma unroll
        for (int j = 0; j < 4; j++) {
            int tok = rep * 4 + j;
            sx[tok * HID + c] = acc[j];
            g_x[(size_t)(tok0 + tok) * HID + c] = acc[j];
        }
    }
    __syncthreads();

    if (t < 192) {
        const float4* wr = (const float4*)(qkv_w + (size_t)t * HID);
        float bi = qkv_b[t];
        float acc[16];
        #pragma unroll
        for (int j = 0; j < 16; j++) acc[j] = bi;
        const float4* a = (const float4*)sx;
        #pragma unroll
        for (int k = 0; k < HID / 4; k++) {
            float4 wt = ldg4(wr + k);
            #pragma unroll
            for (int j = 0; j < 16; j++) acc[j] += dot4(a[j * (HID / 4) + k], wt);
        }
        int kind = t >> 6, w_ = t & 63, h = w_ >> 4, d = w_ & 15;
        size_t base = (((size_t)b * NH + h) * NN + n0) * HD + d;
        if (kind == 0) {
            #pragma unroll
            for (int j = 0; j < 16; j++) g_q[base + (size_t)j * HD] = acc[j] * 0.25f;
        } else {
            uint2* dst = (kind == 1) ? g_khl : g_vhl;
            #pragma unroll
            for (int j = 0; j < 16; j++) {
                unsigned hi, lo;
                tf32split(acc[j], hi, lo);
                dst[base + (size_t)j * HD] = make_uint2(hi, lo);
            }
        }
    }
}

__global__ __launch_bounds__(256) void k_input_all(
        const float* __restrict__ y,
        const float* __restrict__ b1, const float* __restrict__ w2,
        const float* __restrict__ b2,
        const float* __restrict__ qkv_w, const float* __restrict__ qkv_b) {
    __shared__ __align__(16) float sy[16 * 516];   // max FP (seg3)
    __shared__ __align__(16) float sh[16 * SHP];
    __shared__ __align__(16) float sx[16 * HID];
    int tok0 = blockIdx.x * 16;
    int b = tok0 >> 10, n0 = tok0 & 1023;
    int seg = n0 >> 8;
    switch (seg) {
        case 0: input_body<0>(sy, sh, sx, tok0, b, n0, y, b1, w2, b2, qkv_w, qkv_b); break;
        case 1: input_body<1>(sy, sh, sx, tok0, b, n0, y, b1, w2, b2, qkv_w, qkv_b); break;
        case 2: input_body<2>(sy, sh, sx, tok0, b, n0, y, b1, w2, b2, qkv_w, qkv_b); break;
        default: input_body<3>(sy, sh, sx, tok0, b, n0, y, b1, w2, b2, qkv_w, qkv_b); break;
    }
}

// ============================================================
// 2. Tensor-core attention
// ============================================================
#define KVS 20
#define PS  68
__global__ __launch_bounds__(128) void k_attn() {
    __shared__ uint2    skhl[64 * KVS];
    __shared__ uint2    svhl[64 * KVS];
    __shared__ unsigned sp[4 * 16 * PS];
    int bh = blockIdx.x >> 4;
    int qc = blockIdx.x & 15;
    int t  = threadIdx.x;
    int w  = t >> 5, lane = t & 31;
    int gid = lane >> 2, tig = lane & 3;
    size_t base = (size_t)bh * NN * HD;
    int q0 = qc * 64 + w * 16;
    unsigned* spw = sp + w * 16 * PS;

    unsigned qb[8], qs[8];
    {
        const float* Qp = g_q + base + (size_t)q0 * HD;
        #pragma unroll
        for (int s = 0; s < 2; s++) {
            tf32split(Qp[(gid)     * HD + 8 * s + tig],     qb[s * 4 + 0], qs[s * 4 + 0]);
            tf32split(Qp[(gid + 8) * HD + 8 * s + tig],     qb[s * 4 + 1], qs[s * 4 + 1]);
            tf32split(Qp[(gid)     * HD + 8 * s + tig + 4], qb[s * 4 + 2], qs[s * 4 + 2]);
            tf32split(Qp[(gid + 8) * HD + 8 * s + tig + 4], qb[s * 4 + 3], qs[s * 4 + 3]);
        }
    }

    float O[2][4] = {{0.f,0.f,0.f,0.f},{0.f,0.f,0.f,0.f}};
    float ls1 = 0.f, ls2 = 0.f;

    for (int chunk = 0; chunk < 16; chunk++) {
        {
            const uint4* kg = (const uint4*)(g_khl + base + (size_t)chunk * 64 * HD);
            const uint4* vg = (const uint4*)(g_vhl + base + (size_t)chunk * 64 * HD);
            #pragma unroll
            for (int i = 0; i < 4; i++) {
                int idx4 = t + i * 128;
                int row = idx4 >> 3;
                int c = (idx4 & 7) * 2;
                *(uint4*)&skhl[row * KVS + c] = kg[idx4];
                *(uint4*)&svhl[row * KVS + c] = vg[idx4];
            }
        }
        __syncthreads();

        float S[8][4];
        #pragma unroll
        for (int nt = 0; nt < 8; nt++) {
            S[nt][0] = S[nt][1] = S[nt][2] = S[nt][3] = 0.f;
            #pragma unroll
            for (int s = 0; s < 2; s++) {
                uint2 b0 = skhl[(8 * nt + gid) * KVS + 8 * s + tig];
                uint2 b1 = skhl[(8 * nt + gid) * KVS + 8 * s + tig + 4];
                mma_tf32(S[nt], qb + s * 4, b0.x, b1.x);
                mma_tf32(S[nt], qb + s * 4, b0.y, b1.y);
                mma_tf32(S[nt], qs + s * 4, b0.x, b1.x);
            }
        }

        #pragma unroll
        for (int nt = 0; nt < 8; nt++) {
            float p0 = __expf(fminf(S[nt][0], 75.f));
            float p1 = __expf(fminf(S[nt][1], 75.f));
            float p2 = __expf(fminf(S[nt][2], 75.f));
            float p3 = __expf(fminf(S[nt][3], 75.f));
            ls1 += p0 + p1;
            ls2 += p2 + p3;
            int col = 8 * nt + 2 * tig;
            *(uint2*)(spw + (gid)     * PS + col) = make_uint2(f2tf32(p0), f2tf32(p1));
            *(uint2*)(spw + (gid + 8) * PS + col) = make_uint2(f2tf32(p2), f2tf32(p3));
        }
        __syncwarp();

        #pragma unroll
        for (int s = 0; s < 8; s++) {
            unsigned a[4];
            a[0] = spw[(gid)     * PS + 8 * s + tig];
            a[1] = spw[(gid + 8) * PS + 8 * s + tig];
            a[2] = spw[(gid)     * PS + 8 * s + tig + 4];
            a[3] = spw[(gid + 8) * PS + 8 * s + tig + 4];
            #pragma unroll
            for (int nt2 = 0; nt2 < 2; nt2++) {
                uint2 v0 = svhl[(8 * s + tig)     * KVS + 8 * nt2 + gid];
                uint2 v1 = svhl[(8 * s + tig + 4) * KVS + 8 * nt2 + gid];
                mma_tf32(O[nt2], a, v0.x, v1.x);
                mma_tf32(O[nt2], a, v0.y, v1.y);
            }
        }
        __syncthreads();
    }

    ls1 += __shfl_xor_sync(0xffffffff, ls1, 1);
    ls1 += __shfl_xor_sync(0xffffffff, ls1, 2);
    ls2 += __shfl_xor_sync(0xffffffff, ls2, 1);
    ls2 += __shfl_xor_sync(0xffffffff, ls2, 2);
    float i1 = 1.f / ls1, i2 = 1.f / ls2;

    #pragma unroll
    for (int nt2 = 0; nt2 < 2; nt2++) {
        int col = 8 * nt2 + 2 * tig;
        *(float2*)(g_o + base + (size_t)(q0 + gid)     * HD + col) =
            make_float2(O[nt2][0] * i1, O[nt2][1] * i1);
        *(float2*)(g_o + base + (size_t)(q0 + gid + 8) * HD + col) =
            make_float2(O[nt2][2] * i2, O[nt2][3] * i2);
    }
}

// ============================================================
// 3. Proj + LN1 + FFN + LN2 (+ next-layer QKV)
// ============================================================
__global__ __launch_bounds__(256) void k_pfq(int l, int do_qkv,
        const float* __restrict__ W,   const float* __restrict__ bias,
        const float* __restrict__ ln1w, const float* __restrict__ ln1b,
        const float* __restrict__ fw1, const float* __restrict__ fb1,
        const float* __restrict__ fw2, const float* __restrict__ fb2,
        const float* __restrict__ ln2w, const float* __restrict__ ln2b,
        const float* __restrict__ qkv_w, const float* __restrict__ qkv_b) {
    __shared__ __align__(16) float so[16 * HID];
    __shared__ __align__(16) float sx1[16 * HID];
    __shared__ __align__(16) float sh[16 * FF];
    __shared__ float sval[16 * 66];
    int tok0 = blockIdx.x * 16;
    int b = tok0 >> 10, n0 = tok0 & 1023;
    int t = threadIdx.x;
    int wid = t >> 5, lane = t & 31;

    for (int idx = t; idx < 16 * HID; idx += 256) {
        int tt = idx >> 6, c = idx & 63;
        so[idx] = g_o[(((size_t)b * NH + (c >> 4)) * NN + n0 + tt) * HD + (c & 15)];
    }
    __syncthreads();

    {
        int rep = t >> 6, c = t & 63;
        const float4* wr = (const float4*)(W + ((size_t)l * HID + c) * HID);
        float bi = bias[l * HID + c];
        float acc[4];
        #pragma unroll
        for (int j = 0; j < 4; j++) acc[j] = bi;
        const float4* a = (const float4*)so + (rep * 4) * (HID / 4);
        #pragma unroll
        for (int k = 0; k < HID / 4; k++) {
            float4 wt = ldg4(wr + k);
            #pragma unroll
            for (int j = 0; j < 4; j++) acc[j] += dot4(a[j * (HID / 4) + k], wt);
        }
        #pragma unroll
        for (int j = 0; j < 4; j++) {
            int tok = rep * 4 + j;
            sval[tok * 66 + c] = g_x[(size_t)(tok0 + tok) * HID + c] + acc[j];
        }
    }
    __syncthreads();

    {
        int tA = 2 * wid, tB = 2 * wid + 1;
        float a0 = sval[tA * 66 + lane],      a1 = sval[tA * 66 + lane + 32];
        float b0 = sval[tB * 66 + lane],      b1 = sval[tB * 66 + lane + 32];
        float sA1 = a0 + a1, sA2 = a0 * a0 + a1 * a1;
        float sB1 = b0 + b1, sB2 = b0 * b0 + b1 * b1;
        #pragma unroll
        for (int off = 16; off > 0; off >>= 1) {
            sA1 += __shfl_xor_sync(0xffffffff, sA1, off);
            sA2 += __shfl_xor_sync(0xffffffff, sA2, off);
            sB1 += __shfl_xor_sync(0xffffffff, sB1, off);
            sB2 += __shfl_xor_sync(0xffffffff, sB2, off);
        }
        float mA = sA1 * (1.f / 64.f), vA = sA2 * (1.f / 64.f) - mA * mA;
        float mB = sB1 * (1.f / 64.f), vB = sB2 * (1.f / 64.f) - mB * mB;
        float rA = rsqrtf(vA + LN_EPS), rB = rsqrtf(vB + LN_EPS);
        float w0 = ln1w[l * HID + lane],      w1v = ln1w[l * HID + lane + 32];
        float bb0 = ln1b[l * HID + lane],     bb1 = ln1b[l * HID + lane + 32];
        sx1[tA * HID + lane]      = (a0 - mA) * rA * w0  + bb0;
        sx1[tA * HID + lane + 32] = (a1 - mA) * rA * w1v + bb1;
        sx1[tB * HID + lane]      = (b0 - mB) * rB * w0  + bb0;
        sx1[tB * HID + lane + 32] = (b1 - mB) * rB * w1v + bb1;
    }
    __syncthreads();

    {
        const float4* wr = (const float4*)(fw1 + ((size_t)l * FF + t) * HID);
        float bi = fb1[l * FF + t];
        float acc[16];
        #pragma unroll
        for (int j = 0; j < 16; j++) acc[j] = bi;
        const float4* a = (const float4*)sx1;
        #pragma unroll
        for (int k = 0; k < HID / 4; k++) {
            float4 wt = ldg4(wr + k);
            #pragma unroll
            for (int j = 0; j < 16; j++) acc[j] += dot4(a[j * (HID / 4) + k], wt);
        }
        #pragma unroll
        for (int j = 0; j < 16; j++) sh[j * FF + t] = fmaxf(acc[j], 0.f);
    }
    __syncthreads();

    {
        int rep = t >> 6, c = t & 63;
        const float4* wr = (const float4*)(fw2 + ((size_t)l * HID + c) * FF);
        float bi = fb2[l * HID + c];
        float acc[4];
        #pragma unroll
        for (int j = 0; j < 4; j++) acc[j] = bi;
        const float4* a = (const float4*)sh + (rep * 4) * (FF / 4);
        #pragma unroll 8
        for (int k = 0; k < FF / 4; k++) {
            float4 wt = ldg4(wr + k);
            #pragma unroll
            for (int j = 0; j < 4; j++) acc[j] += dot4(a[j * (FF / 4) + k], wt);
        }
        #pragma unroll
        for (int j = 0; j < 4; j++) {
            int tok = rep * 4 + j;
            sval[tok * 66 + c] = sx1[tok * HID + c] + acc[j];
        }
    }
    __syncthreads();

    {
        int tA = 2 * wid, tB = 2 * wid + 1;
        float a0 = sval[tA * 66 + lane],      a1 = sval[tA * 66 + lane + 32];
        float b0 = sval[tB * 66 + lane],      b1 = sval[tB * 66 + lane + 32];
        float sA1 = a0 + a1, sA2 = a0 * a0 + a1 * a1;
        float sB1 = b0 + b1, sB2 = b0 * b0 + b1 * b1;
        #pragma unroll
        for (int off = 16; off > 0; off >>= 1) {
            sA1 += __shfl_xor_sync(0xffffffff, sA1, off);
            sA2 += __shfl_xor_sync(0xffffffff, sA2, off);
            sB1 += __shfl_xor_sync(0xffffffff, sB1, off);
            sB2 += __shfl_xor_sync(0xffffffff, sB2, off);
        }
        float mA = sA1 * (1.f / 64.f), vA = sA2 * (1.f / 64.f) - mA * mA;
        float mB = sB1 * (1.f / 64.f), vB = sB2 * (1.f / 64.f) - mB * mB;
        float rA = rsqrtf(vA + LN_EPS), rB = rsqrtf(vB + LN_EPS);
        float w0 = ln2w[l * HID + lane],      w1v = ln2w[l * HID + lane + 32];
        float bb0 = ln2b[l * HID + lane],     bb1 = ln2b[l * HID + lane + 32];
        float oA0 = (a0 - mA) * rA * w0  + bb0;
        float oA1 = (a1 - mA) * rA * w1v + bb1;
        float oB0 = (b0 - mB) * rB * w0  + bb0;
        float oB1 = (b1 - mB) * rB * w1v + bb1;
        sx1[tA * HID + lane]      = oA0;
        sx1[tA * HID + lane + 32] = oA1;
        sx1[tB * HID + lane]      = oB0;
        sx1[tB * HID + lane + 32] = oB1;
        size_t gb = (size_t)(tok0 + tA) * HID;
        g_x[gb + lane]            = oA0;
        g_x[gb + lane + 32]       = oA1;
        g_x[gb + HID + lane]      = oB0;
        g_x[gb + HID + lane + 32] = oB1;
    }
    __syncthreads();

    if (do_qkv && t < 192) {
        const float4* wr = (const float4*)(qkv_w + ((size_t)(l + 1) * 192 + t) * HID);
        float bi = qkv_b[(l + 1) * 192 + t];
        float acc[16];
        #pragma unroll
        for (int j = 0; j < 16; j++) acc[j] = bi;
        const float4* a = (const float4*)sx1;
        #pragma unroll
        for (int k = 0; k < HID / 4; k++) {
            float4 wt = ldg4(wr + k);
            #pragma unroll
            for (int j = 0; j < 16; j++) acc[j] += dot4(a[j * (HID / 4) + k], wt);
        }
        int kind = t >> 6, w_ = t & 63, h = w_ >> 4, d = w_ & 15;
        size_t base = (((size_t)b * NH + h) * NN + n0) * HD + d;
        if (kind == 0) {
            #pragma unroll
            for (int j = 0; j < 16; j++) g_q[base + (size_t)j * HD] = acc[j] * 0.25f;
        } else {
            uint2* dst = (kind == 1) ? g_khl : g_vhl;
            #pragma unroll
            for (int j = 0; j < 16; j++) {
                unsigned hi, lo;
                tf32split(acc[j], hi, lo);
                dst[base + (size_t)j * HD] = make_uint2(hi, lo);
            }
        }
    }
}

// ============================================================
// 4. Output head body (templated), merged kernel
// ============================================================
template<int SEG>
__device__ __forceinline__ void out_body(
        float* sx, float* sh, float (*red)[16],
        int tok0, float* __restrict__ out,
        const float* __restrict__ ow1, const float* __restrict__ ob1,
        const float* __restrict__ b2) {
    constexpr int F  = 64 << SEG;
    constexpr int NT = F / 64;
    constexpr int WOFF = (SEG == 0) ? 0 : (SEG == 1) ? 8192 : (SEG == 2) ? 24576 : 57344;
    int t = threadIdx.x;
    int w = t >> 5, lane = t & 31;
    int gid = lane >> 2, tig = lane & 3;

    for (int idx = t; idx < 16 * HID; idx += 256)
        sx[idx] = g_x[(size_t)tok0 * HID + idx];
    __syncthreads();

    {
        int rep = t >> 7, h = t & 127;
        const float4* wr = (const float4*)(ow1 + ((size_t)SEG * MLPH + h) * HID);
        float bi = ob1[SEG * MLPH + h];
        float acc[8];
        #pragma unroll
        for (int j = 0; j < 8; j++) acc[j] = bi;
        const float4* a = (const float4*)sx + (rep * 8) * (HID / 4);
        #pragma unroll
        for (int k = 0; k < HID / 4; k++) {
            float4 wt = ldg4(wr + k);
            #pragma unroll
            for (int j = 0; j < 8; j++) acc[j] += dot4(a[j * (HID / 4) + k], wt);
        }
        #pragma unroll
        for (int j = 0; j < 8; j++) sh[(rep * 8 + j) * SHP + h] = tanhf(acc[j]);
    }
    __syncthreads();

    {
        float C[NT][4];
        #pragma unroll
        for (int j = 0; j < NT; j++) {
            int col0 = (w + j * 8) * 8 + 2 * tig;
            C[j][0] = C[j][2] = b2[col0];
            C[j][1] = C[j][3] = b2[col0 + 1];
        }
        const uint2* w2a = g_w2hl + WOFF;
        #pragma unroll 2
        for (int ks = 0; ks < 16; ks++) {
            int k0 = ks * 8;
            unsigned ab[4], as[4];
            tf32split(sh[(gid)     * SHP + k0 + tig],     ab[0], as[0]);
            tf32split(sh[(gid + 8) * SHP + k0 + tig],     ab[1], as[1]);
            tf32split(sh[(gid)     * SHP + k0 + tig + 4], ab[2], as[2]);
            tf32split(sh[(gid + 8) * SHP + k0 + tig + 4], ab[3], as[3]);
            #pragma unroll
            for (int j = 0; j < NT; j++) {
                int nb = (w + j * 8) * 8 + gid;
                uint2 b0 = w2a[nb * MLPH + k0 + tig];
                uint2 b1 = w2a[nb * MLPH + k0 + tig + 4];
                mma_tf32(C[j], ab, b0.x, b1.x);
                mma_tf32(C[j], ab, b0.y, b1.y);
                mma_tf32(C[j], as, b0.x, b1.x);
            }
        }

        float sqA = 0.f, sqB = 0.f;
        #pragma unroll
        for (int j = 0; j < NT; j++) {
            int col0 = (w + j * 8) * 8 + 2 * tig;
            *(float2*)&out[(size_t)(tok0 + gid)     * MAXF + col0] = make_float2(C[j][0], C[j][1]);
            *(float2*)&out[(size_t)(tok0 + gid + 8) * MAXF + col0] = make_float2(C[j][2], C[j][3]);
            sqA += C[j][0] * C[j][0] + C[j][1] * C[j][1];
            sqB += C[j][2] * C[j][2] + C[j][3] * C[j][3];
        }
        sqA += __shfl_xor_sync(0xffffffff, sqA, 1);
        sqA += __shfl_xor_sync(0xffffffff, sqA, 2);
        sqB += __shfl_xor_sync(0xffffffff, sqB, 1);
        sqB += __shfl_xor_sync(0xffffffff, sqB, 2);
        if (tig == 0) { red[w][gid] = sqA; red[w][gid + 8] = sqB; }
    }

    if (SEG < 3) {
        constexpr int PADW = (MAXF - F) / 4;
        float4 z = make_float4(0.f, 0.f, 0.f, 0.f);
        for (int i = t; i < 16 * PADW; i += 256) {
            int r = i / PADW, c = i - r * PADW;
            *((float4*)&out[(size_t)(tok0 + r) * MAXF + F] + c) = z;
        }
    }
    __syncthreads();
    if (t < 16) {
        float s = 0.f;
        #pragma unroll
        for (int ww = 0; ww < 8; ww++) s += red[ww][t];
        g_esum[tok0 + t] = s;
    }
}

__global__ __launch_bounds__(256) void k_out_all(float* __restrict__ out,
        const float* __restrict__ ow1, const float* __restrict__ ob1,
        const float* __restrict__ b2_0, const float* __restrict__ b2_1,
        const float* __restrict__ b2_2, const float* __restrict__ b2_3) {
    __shared__ __align__(16) float sx[16 * HID];
    __shared__ __align__(16) float sh[16 * SHP];
    __shared__ float red[8][16];
    int tok0 = blockIdx.x * 16;
    int seg = (tok0 & 1023) >> 8;
    switch (seg) {
        case 0: out_body<0>(sx, sh, red, tok0, out, ow1, ob1, b2_0); break;
        case 1: out_body<1>(sx, sh, red, tok0, out, ow1, ob1, b2_1); break;
        case 2: out_body<2>(sx, sh, red, tok0, out, ow1, ob1, b2_2); break;
        default: out_body<3>(sx, sh, red, tok0, out, ow1, ob1, b2_3); break;
    }
}

// ============================================================
// 5. Energy reduce
// ============================================================
__global__ void k_energy(float* __restrict__ e) {
    __shared__ float red[4];
    int b = blockIdx.x;
    int t = threadIdx.x;
    float s = 0.f;
    for (int i = t; i < NN; i += 128) s += g_esum[b * NN + i];
    #pragma unroll
    for (int off = 16; off > 0; off >>= 1) s += __shfl_xor_sync(0xffffffff, s, off);
    if ((t & 31) == 0) red[t >> 5] = s;
    __syncthreads();
    if (t == 0) e[b] = 0.5f * (red[0] + red[1] + red[2] + red[3]);
}

// ============================================================
extern "C" void kernel_launch(void* const* d_in, const int* in_sizes, int n_in,
                              void* d_out, int out_size) {
    const float* y      = (const float*)d_in[1];
    const float* in_w1_0 = (const float*)d_in[3];
    const float* in_w1_1 = (const float*)d_in[4];
    const float* in_w1_2 = (const float*)d_in[5];
    const float* in_w1_3 = (const float*)d_in[6];
    const float* out_w2_0 = (const float*)d_in[7];
    const float* out_w2_1 = (const float*)d_in[8];
    const float* out_w2_2 = (const float*)d_in[9];
    const float* out_w2_3 = (const float*)d_in[10];
    const float* out_b2_0 = (const float*)d_in[11];
    const float* out_b2_1 = (const float*)d_in[12];
    const float* out_b2_2 = (const float*)d_in[13];
    const float* out_b2_3 = (const float*)d_in[14];
    const float* in_b1  = (const float*)d_in[15];
    const float* in_w2  = (const float*)d_in[16];
    const float* in_b2  = (const float*)d_in[17];
    const float* out_w1 = (const float*)d_in[18];
    const float* out_b1 = (const float*)d_in[19];
    const float* qkv_w  = (const float*)d_in[20];
    const float* qkv_b  = (const float*)d_in[21];
    const float* attn_out_w = (const float*)d_in[22];
    const float* attn_out_b = (const float*)d_in[23];
    const float* ln1_w  = (const float*)d_in[24];
    const float* ln1_b  = (const float*)d_in[25];
    const float* ffn_w1 = (const float*)d_in[26];
    const float* ffn_b1 = (const float*)d_in[27];
    const float* ffn_w2 = (const float*)d_in[28];
    const float* ffn_b2 = (const float*)d_in[29];
    const float* ln2_w  = (const float*)d_in[30];
    const float* ln2_b  = (const float*)d_in[31];

    float* out = (float*)d_out;
    float* energy = out + (size_t)BB * NN * MAXF;

    const int NB = (BB * NN) / 16;   // 1024

    k_presplit<<<480, 256>>>(in_w1_0, in_w1_1, in_w1_2, in_w1_3,
                             out_w2_0, out_w2_1, out_w2_2, out_w2_3);

    k_input_all<<<NB, 256>>>(y, in_b1, in_w2, in_b2, qkv_w, qkv_b);

    k_attn<<<BB * NH * 16, 128>>>();
    k_pfq<<<NB, 256>>>(0, 1, attn_out_w, attn_out_b, ln1_w, ln1_b,
                       ffn_w1, ffn_b1, ffn_w2, ffn_b2, ln2_w, ln2_b, qkv_w, qkv_b);
    k_attn<<<BB * NH * 16, 128>>>();
    k_pfq<<<NB, 256>>>(1, 0, attn_out_w, attn_out_b, ln1_w, ln1_b,
                       ffn_w1, ffn_b1, ffn_w2, ffn_b2, ln2_w, ln2_b, qkv_w, qkv_b);

    k_out_all<<<NB, 256>>>(out, out_w1, out_b1,
                           out_b2_0, out_b2_1, out_b2_2, out_b2_3);

    k_energy<<<BB, 128>>>(energy);
}

// round 12
// speedup vs baseline: 5.7576x; 1.2211x over previous
#include <cuda_runtime.h>
#include <cuda_bf16.h>
#include <math.h>
#include <stdint.h>

#define BB    16
#define NN    1024
#define HID   64
#define NH    4
#define HD    16
#define MLPH  128
#define FF    256
#define MAXF  512
#define LN_EPS 1e-5f
#define SHP   132                // stride for 128-wide smem tiles
#define FHP   260                // stride for 256-wide FFN hidden tile
#define XST   68                 // sx1 float stride

__device__ float g_x[BB * NN * HID];
__device__ float g_q[BB * NH * NN * HD];
__device__ uint2 g_khl[BB * NH * NN * HD];
__device__ uint2 g_vhl[BB * NH * NN * HD];
__device__ float g_o[BB * NH * NN * HD];
__device__ float g_esum[BB * NN];
__device__ uint2 g_w1hl[122880];
__device__ uint2 g_w2hl[122880];
__device__ uint2 g_fw1hl[2 * FF * HID];
__device__ uint2 g_fw2hl[2 * HID * FF];

__device__ __forceinline__ float dot4(float4 a, float4 b) {
    return a.x * b.x + a.y * b.y + a.z * b.z + a.w * b.w;
}
__device__ __forceinline__ float4 ldg4(const float4* p) { return __ldg(p); }

__device__ __forceinline__ unsigned f2tf32(float x) {
    unsigned r;
    asm("cvt.rna.tf32.f32 %0, %1;" : "=r"(r) : "f"(x));
    return r;
}
__device__ __forceinline__ void tf32split(float x, unsigned& hi, unsigned& lo) {
    unsigned h = f2tf32(x);
    float r = x - __uint_as_float(h);
    lo = f2tf32(r);
    hi = h;
}
__device__ __forceinline__ void mma_tf32(float* c, const unsigned* a, unsigned b0, unsigned b1) {
    asm volatile(
        "mma.sync.aligned.m16n8k8.row.col.f32.tf32.tf32.f32 "
        "{%0,%1,%2,%3}, {%4,%5,%6,%7}, {%8,%9}, {%0,%1,%2,%3};"
        : "+f"(c[0]), "+f"(c[1]), "+f"(c[2]), "+f"(c[3])
        : "r"(a[0]), "r"(a[1]), "r"(a[2]), "r"(a[3]), "r"(b0), "r"(b1));
}

// ============================================================
// 0a. Weight pre-split (in_w1, out_w2)
// ============================================================
__global__ __launch_bounds__(256) void k_presplit(
        const float* __restrict__ w1_0, const float* __restrict__ w1_1,
        const float* __restrict__ w1_2, const float* __restrict__ w1_3,
        const float* __restrict__ w2_0, const float* __restrict__ w2_1,
        const float* __restrict__ w2_2, const float* __restrict__ w2_3) {
    int i = blockIdx.x * 256 + threadIdx.x;
    if (i >= 122880) return;
    const float *s1, *s2;
    int off;
    if (i < 8192)       { s1 = w1_0; s2 = w2_0; off = i; }
    else if (i < 24576) { s1 = w1_1; s2 = w2_1; off = i - 8192; }
    else if (i < 57344) { s1 = w1_2; s2 = w2_2; off = i - 24576; }
    else                { s1 = w1_3; s2 = w2_3; off = i - 57344; }
    unsigned hi, lo;
    tf32split(s1[off], hi, lo);
    g_w1hl[i] = make_uint2(hi, lo);
    tf32split(s2[off], hi, lo);
    g_w2hl[i] = make_uint2(hi, lo);
}

// ============================================================
// 0b. Weight pre-split (ffn_w1, ffn_w2)
// ============================================================
__global__ __launch_bounds__(256) void k_presplit2(
        const float* __restrict__ fw1, const float* __restrict__ fw2) {
    int i = blockIdx.x * 256 + threadIdx.x;   // 0..32767
    unsigned hi, lo;
    tf32split(fw1[i], hi, lo);
    g_fw1hl[i] = make_uint2(hi, lo);
    tf32split(fw2[i], hi, lo);
    g_fw2hl[i] = make_uint2(hi, lo);
}

// ============================================================
// 1. Input MLP + QKV(layer 0) body (templated), merged kernel
// ============================================================
template<int SEG>
__device__ __forceinline__ void input_body(
        float* sy, float* sh, float* sx,
        int tok0, int b, int n0,
        const float* __restrict__ y,
        const float* __restrict__ b1, const float* __restrict__ w2,
        const float* __restrict__ b2,
        const float* __restrict__ qkv_w, const float* __restrict__ qkv_b) {
    constexpr int F   = 64 << SEG;
    constexpr int FP  = F + 4;
    constexpr int KS  = F / 8;
    constexpr int WOFF = (SEG == 0) ? 0 : (SEG == 1) ? 8192 : (SEG == 2) ? 24576 : 57344;
    int t = threadIdx.x;
    int w = t >> 5, lane = t & 31;
    int gid = lane >> 2, tig = lane & 3;

    {
        const float4* yg = (const float4*)y;
        float4* sy4 = (float4*)sy;
        for (int idx = t; idx < 16 * (F / 4); idx += 256) {
            int tt = idx / (F / 4), f4 = idx - tt * (F / 4);
            sy4[tt * (FP / 4) + f4] = yg[(size_t)(tok0 + tt) * (MAXF / 4) + f4];
        }
    }
    __syncthreads();

    {
        int colA = w * 8 + 2 * tig;
        int colB = (w + 8) * 8 + 2 * tig;
        float C0[4], C1[4];
        C0[0] = C0[2] = b1[SEG * MLPH + colA]; C0[1] = C0[3] = b1[SEG * MLPH + colA + 1];
        C1[0] = C1[2] = b1[SEG * MLPH + colB]; C1[1] = C1[3] = b1[SEG * MLPH + colB + 1];
        const uint2* w1a = g_w1hl + WOFF;
        #pragma unroll 2
        for (int ks = 0; ks < KS; ks++) {
            int k0 = ks * 8;
            unsigned ab[4], as[4];
            tf32split(sy[(gid)     * FP + k0 + tig],     ab[0], as[0]);
            tf32split(sy[(gid + 8) * FP + k0 + tig],     ab[1], as[1]);
            tf32split(sy[(gid)     * FP + k0 + tig + 4], ab[2], as[2]);
            tf32split(sy[(gid + 8) * FP + k0 + tig + 4], ab[3], as[3]);
            uint2 b0 = w1a[(w * 8 + gid) * F + k0 + tig];
            uint2 b1v = w1a[(w * 8 + gid) * F + k0 + tig + 4];
            mma_tf32(C0, ab, b0.x, b1v.x);
            mma_tf32(C0, ab, b0.y, b1v.y);
            mma_tf32(C0, as, b0.x, b1v.x);
            b0  = w1a[((w + 8) * 8 + gid) * F + k0 + tig];
            b1v = w1a[((w + 8) * 8 + gid) * F + k0 + tig + 4];
            mma_tf32(C1, ab, b0.x, b1v.x);
            mma_tf32(C1, ab, b0.y, b1v.y);
            mma_tf32(C1, as, b0.x, b1v.x);
        }
        sh[(gid)     * SHP + colA]     = tanhf(C0[0]);
        sh[(gid)     * SHP + colA + 1] = tanhf(C0[1]);
        sh[(gid + 8) * SHP + colA]     = tanhf(C0[2]);
        sh[(gid + 8) * SHP + colA + 1] = tanhf(C0[3]);
        sh[(gid)     * SHP + colB]     = tanhf(C1[0]);
        sh[(gid)     * SHP + colB + 1] = tanhf(C1[1]);
        sh[(gid + 8) * SHP + colB]     = tanhf(C1[2]);
        sh[(gid + 8) * SHP + colB + 1] = tanhf(C1[3]);
    }
    __syncthreads();

    {
        int rep = t >> 6, c = t & 63;
        const float4* wr = (const float4*)(w2 + ((size_t)SEG * HID + c) * MLPH);
        float bi = b2[SEG * HID + c];
        float acc[4];
        #pragma unroll
        for (int j = 0; j < 4; j++) acc[j] = bi;
        const float4* a = (const float4*)sh + (rep * 4) * (SHP / 4);
        #pragma unroll
        for (int k = 0; k < MLPH / 4; k++) {
            float4 wt = ldg4(wr + k);
            #pragma unroll
            for (int j = 0; j < 4; j++) acc[j] += dot4(a[j * (SHP / 4) + k], wt);
        }
        #pragma unroll
        for (int j = 0; j < 4; j++) {
            int tok = rep * 4 + j;
            sx[tok * HID + c] = acc[j];
            g_x[(size_t)(tok0 + tok) * HID + c] = acc[j];
        }
    }
    __syncthreads();

    if (t < 192) {
        const float4* wr = (const float4*)(qkv_w + (size_t)t * HID);
        float bi = qkv_b[t];
        float acc[16];
        #pragma unroll
        for (int j = 0; j < 16; j++) acc[j] = bi;
        const float4* a = (const float4*)sx;
        #pragma unroll
        for (int k = 0; k < HID / 4; k++) {
            float4 wt = ldg4(wr + k);
            #pragma unroll
            for (int j = 0; j < 16; j++) acc[j] += dot4(a[j * (HID / 4) + k], wt);
        }
        int kind = t >> 6, w_ = t & 63, h = w_ >> 4, d = w_ & 15;
        size_t base = (((size_t)b * NH + h) * NN + n0) * HD + d;
        if (kind == 0) {
            #pragma unroll
            for (int j = 0; j < 16; j++) g_q[base + (size_t)j * HD] = acc[j] * 0.25f;
        } else {
            uint2* dst = (kind == 1) ? g_khl : g_vhl;
            #pragma unroll
            for (int j = 0; j < 16; j++) {
                unsigned hi, lo;
                tf32split(acc[j], hi, lo);
                dst[base + (size_t)j * HD] = make_uint2(hi, lo);
            }
        }
    }
}

__global__ __launch_bounds__(256) void k_input_all(
        const float* __restrict__ y,
        const float* __restrict__ b1, const float* __restrict__ w2,
        const float* __restrict__ b2,
        const float* __restrict__ qkv_w, const float* __restrict__ qkv_b) {
    __shared__ __align__(16) float sy[16 * 516];
    __shared__ __align__(16) float sh[16 * SHP];
    __shared__ __align__(16) float sx[16 * HID];
    int tok0 = blockIdx.x * 16;
    int b = tok0 >> 10, n0 = tok0 & 1023;
    int seg = n0 >> 8;
    switch (seg) {
        case 0: input_body<0>(sy, sh, sx, tok0, b, n0, y, b1, w2, b2, qkv_w, qkv_b); break;
        case 1: input_body<1>(sy, sh, sx, tok0, b, n0, y, b1, w2, b2, qkv_w, qkv_b); break;
        case 2: input_body<2>(sy, sh, sx, tok0, b, n0, y, b1, w2, b2, qkv_w, qkv_b); break;
        default: input_body<3>(sy, sh, sx, tok0, b, n0, y, b1, w2, b2, qkv_w, qkv_b); break;
    }
}

// ============================================================
// 2. Tensor-core attention
// ============================================================
#define KVS 20
#define PS  68
__global__ __launch_bounds__(128) void k_attn() {
    __shared__ uint2    skhl[64 * KVS];
    __shared__ uint2    svhl[64 * KVS];
    __shared__ unsigned sp[4 * 16 * PS];
    int bh = blockIdx.x >> 4;
    int qc = blockIdx.x & 15;
    int t  = threadIdx.x;
    int w  = t >> 5, lane = t & 31;
    int gid = lane >> 2, tig = lane & 3;
    size_t base = (size_t)bh * NN * HD;
    int q0 = qc * 64 + w * 16;
    unsigned* spw = sp + w * 16 * PS;

    unsigned qb[8], qs[8];
    {
        const float* Qp = g_q + base + (size_t)q0 * HD;
        #pragma unroll
        for (int s = 0; s < 2; s++) {
            tf32split(Qp[(gid)     * HD + 8 * s + tig],     qb[s * 4 + 0], qs[s * 4 + 0]);
            tf32split(Qp[(gid + 8) * HD + 8 * s + tig],     qb[s * 4 + 1], qs[s * 4 + 1]);
            tf32split(Qp[(gid)     * HD + 8 * s + tig + 4], qb[s * 4 + 2], qs[s * 4 + 2]);
            tf32split(Qp[(gid + 8) * HD + 8 * s + tig + 4], qb[s * 4 + 3], qs[s * 4 + 3]);
        }
    }

    float O[2][4] = {{0.f,0.f,0.f,0.f},{0.f,0.f,0.f,0.f}};
    float ls1 = 0.f, ls2 = 0.f;

    for (int chunk = 0; chunk < 16; chunk++) {
        {
            const uint4* kg = (const uint4*)(g_khl + base + (size_t)chunk * 64 * HD);
            const uint4* vg = (const uint4*)(g_vhl + base + (size_t)chunk * 64 * HD);
            #pragma unroll
            for (int i = 0; i < 4; i++) {
                int idx4 = t + i * 128;
                int row = idx4 >> 3;
                int c = (idx4 & 7) * 2;
                *(uint4*)&skhl[row * KVS + c] = kg[idx4];
                *(uint4*)&svhl[row * KVS + c] = vg[idx4];
            }
        }
        __syncthreads();

        float S[8][4];
        #pragma unroll
        for (int nt = 0; nt < 8; nt++) {
            S[nt][0] = S[nt][1] = S[nt][2] = S[nt][3] = 0.f;
            #pragma unroll
            for (int s = 0; s < 2; s++) {
                uint2 b0 = skhl[(8 * nt + gid) * KVS + 8 * s + tig];
                uint2 b1 = skhl[(8 * nt + gid) * KVS + 8 * s + tig + 4];
                mma_tf32(S[nt], qb + s * 4, b0.x, b1.x);
                mma_tf32(S[nt], qb + s * 4, b0.y, b1.y);
                mma_tf32(S[nt], qs + s * 4, b0.x, b1.x);
            }
        }

        #pragma unroll
        for (int nt = 0; nt < 8; nt++) {
            float p0 = __expf(fminf(S[nt][0], 75.f));
            float p1 = __expf(fminf(S[nt][1], 75.f));
            float p2 = __expf(fminf(S[nt][2], 75.f));
            float p3 = __expf(fminf(S[nt][3], 75.f));
            ls1 += p0 + p1;
            ls2 += p2 + p3;
            int col = 8 * nt + 2 * tig;
            *(uint2*)(spw + (gid)     * PS + col) = make_uint2(f2tf32(p0), f2tf32(p1));
            *(uint2*)(spw + (gid + 8) * PS + col) = make_uint2(f2tf32(p2), f2tf32(p3));
        }
        __syncwarp();

        #pragma unroll
        for (int s = 0; s < 8; s++) {
            unsigned a[4];
            a[0] = spw[(gid)     * PS + 8 * s + tig];
            a[1] = spw[(gid + 8) * PS + 8 * s + tig];
            a[2] = spw[(gid)     * PS + 8 * s + tig + 4];
            a[3] = spw[(gid + 8) * PS + 8 * s + tig + 4];
            #pragma unroll
            for (int nt2 = 0; nt2 < 2; nt2++) {
                uint2 v0 = svhl[(8 * s + tig)     * KVS + 8 * nt2 + gid];
                uint2 v1 = svhl[(8 * s + tig + 4) * KVS + 8 * nt2 + gid];
                mma_tf32(O[nt2], a, v0.x, v1.x);
                mma_tf32(O[nt2], a, v0.y, v1.y);
            }
        }
        __syncthreads();
    }

    ls1 += __shfl_xor_sync(0xffffffff, ls1, 1);
    ls1 += __shfl_xor_sync(0xffffffff, ls1, 2);
    ls2 += __shfl_xor_sync(0xffffffff, ls2, 1);
    ls2 += __shfl_xor_sync(0xffffffff, ls2, 2);
    float i1 = 1.f / ls1, i2 = 1.f / ls2;

    #pragma unroll
    for (int nt2 = 0; nt2 < 2; nt2++) {
        int col = 8 * nt2 + 2 * tig;
        *(float2*)(g_o + base + (size_t)(q0 + gid)     * HD + col) =
            make_float2(O[nt2][0] * i1, O[nt2][1] * i1);
        *(float2*)(g_o + base + (size_t)(q0 + gid + 8) * HD + col) =
            make_float2(O[nt2][2] * i2, O[nt2][3] * i2);
    }
}

// ============================================================
// 3. Proj + LN1 + FFN(MMA) + LN2 (+ next-layer QKV)
// ============================================================
__global__ __launch_bounds__(256) void k_pfq(int l, int do_qkv,
        const float* __restrict__ W,   const float* __restrict__ bias,
        const float* __restrict__ ln1w, const float* __restrict__ ln1b,
        const float* __restrict__ fb1,
        const float* __restrict__ fb2,
        const float* __restrict__ ln2w, const float* __restrict__ ln2b,
        const float* __restrict__ qkv_w, const float* __restrict__ qkv_b) {
    __shared__ __align__(16) float so[16 * HID];
    __shared__ __align__(16) float sx1[16 * XST];
    __shared__ __align__(16) float sh[16 * FHP];     // 16 x 256 hidden, stride 260
    __shared__ float sval[16 * 66];
    int tok0 = blockIdx.x * 16;
    int b = tok0 >> 10, n0 = tok0 & 1023;
    int t = threadIdx.x;
    int wid = t >> 5, lane = t & 31;
    int gid = lane >> 2, tig = lane & 3;

    for (int idx = t; idx < 16 * HID; idx += 256) {
        int tt = idx >> 6, c = idx & 63;
        so[idx] = g_o[(((size_t)b * NH + (c >> 4)) * NN + n0 + tt) * HD + (c & 15)];
    }
    __syncthreads();

    // out-proj + residual (FFMA)
    {
        int rep = t >> 6, c = t & 63;
        const float4* wr = (const float4*)(W + ((size_t)l * HID + c) * HID);
        float bi = bias[l * HID + c];
        float acc[4];
        #pragma unroll
        for (int j = 0; j < 4; j++) acc[j] = bi;
        const float4* a = (const float4*)so + (rep * 4) * (HID / 4);
        #pragma unroll
        for (int k = 0; k < HID / 4; k++) {
            float4 wt = ldg4(wr + k);
            #pragma unroll
            for (int j = 0; j < 4; j++) acc[j] += dot4(a[j * (HID / 4) + k], wt);
        }
        #pragma unroll
        for (int j = 0; j < 4; j++) {
            int tok = rep * 4 + j;
            sval[tok * 66 + c] = g_x[(size_t)(tok0 + tok) * HID + c] + acc[j];
        }
    }
    __syncthreads();

    // LN1 -> sx1
    {
        int tA = 2 * wid, tB = 2 * wid + 1;
        float a0 = sval[tA * 66 + lane],      a1 = sval[tA * 66 + lane + 32];
        float b0 = sval[tB * 66 + lane],      b1 = sval[tB * 66 + lane + 32];
        float sA1 = a0 + a1, sA2 = a0 * a0 + a1 * a1;
        float sB1 = b0 + b1, sB2 = b0 * b0 + b1 * b1;
        #pragma unroll
        for (int off = 16; off > 0; off >>= 1) {
            sA1 += __shfl_xor_sync(0xffffffff, sA1, off);
            sA2 += __shfl_xor_sync(0xffffffff, sA2, off);
            sB1 += __shfl_xor_sync(0xffffffff, sB1, off);
            sB2 += __shfl_xor_sync(0xffffffff, sB2, off);
        }
        float mA = sA1 * (1.f / 64.f), vA = sA2 * (1.f / 64.f) - mA * mA;
        float mB = sB1 * (1.f / 64.f), vB = sB2 * (1.f / 64.f) - mB * mB;
        float rA = rsqrtf(vA + LN_EPS), rB = rsqrtf(vB + LN_EPS);
        float w0 = ln1w[l * HID + lane],      w1v = ln1w[l * HID + lane + 32];
        float bb0 = ln1b[l * HID + lane],     bb1 = ln1b[l * HID + lane + 32];
        sx1[tA * XST + lane]      = (a0 - mA) * rA * w0  + bb0;
        sx1[tA * XST + lane + 32] = (a1 - mA) * rA * w1v + bb1;
        sx1[tB * XST + lane]      = (b0 - mB) * rB * w0  + bb0;
        sx1[tB * XST + lane + 32] = (b1 - mB) * rB * w1v + bb1;
    }
    __syncthreads();

    // FFN phase 1 (MMA): h = relu(x @ fw1^T + b1); warp wid -> 4 n-tiles
    {
        float C[4][4];
        #pragma unroll
        for (int j = 0; j < 4; j++) {
            int col0 = (wid + j * 8) * 8 + 2 * tig;
            C[j][0] = C[j][2] = fb1[l * FF + col0];
            C[j][1] = C[j][3] = fb1[l * FF + col0 + 1];
        }
        const uint2* fw1a = g_fw1hl + (size_t)l * FF * HID;
        #pragma unroll 2
        for (int ks = 0; ks < 8; ks++) {
            int k0 = ks * 8;
            unsigned ab[4], as[4];
            tf32split(sx1[(gid)     * XST + k0 + tig],     ab[0], as[0]);
            tf32split(sx1[(gid + 8) * XST + k0 + tig],     ab[1], as[1]);
            tf32split(sx1[(gid)     * XST + k0 + tig + 4], ab[2], as[2]);
            tf32split(sx1[(gid + 8) * XST + k0 + tig + 4], ab[3], as[3]);
            #pragma unroll
            for (int j = 0; j < 4; j++) {
                int nb = (wid + j * 8) * 8 + gid;
                uint2 b0 = fw1a[nb * HID + k0 + tig];
                uint2 b1 = fw1a[nb * HID + k0 + tig + 4];
                mma_tf32(C[j], ab, b0.x, b1.x);
                mma_tf32(C[j], ab, b0.y, b1.y);
                mma_tf32(C[j], as, b0.x, b1.x);
            }
        }
        #pragma unroll
        for (int j = 0; j < 4; j++) {
            int col0 = (wid + j * 8) * 8 + 2 * tig;
            sh[(gid)     * FHP + col0]     = fmaxf(C[j][0], 0.f);
            sh[(gid)     * FHP + col0 + 1] = fmaxf(C[j][1], 0.f);
            sh[(gid + 8) * FHP + col0]     = fmaxf(C[j][2], 0.f);
            sh[(gid + 8) * FHP + col0 + 1] = fmaxf(C[j][3], 0.f);
        }
    }
    __syncthreads();

    // FFN phase 2 (MMA): warp wid -> n-tile wid (8 cols), K=256
    {
        float C2[4];
        int col0 = wid * 8 + 2 * tig;
        C2[0] = C2[2] = fb2[l * HID + col0];
        C2[1] = C2[3] = fb2[l * HID + col0 + 1];
        const uint2* fw2a = g_fw2hl + (size_t)l * HID * FF;
        #pragma unroll 4
        for (int ks = 0; ks < 32; ks++) {
            int k0 = ks * 8;
            unsigned ab[4], as[4];
            tf32split(sh[(gid)     * FHP + k0 + tig],     ab[0], as[0]);
            tf32split(sh[(gid + 8) * FHP + k0 + tig],     ab[1], as[1]);
            tf32split(sh[(gid)     * FHP + k0 + tig + 4], ab[2], as[2]);
            tf32split(sh[(gid + 8) * FHP + k0 + tig + 4], ab[3], as[3]);
            int nb = wid * 8 + gid;
            uint2 b0 = fw2a[nb * FF + k0 + tig];
            uint2 b1 = fw2a[nb * FF + k0 + tig + 4];
            mma_tf32(C2, ab, b0.x, b1.x);
            mma_tf32(C2, ab, b0.y, b1.y);
            mma_tf32(C2, as, b0.x, b1.x);
        }
        sval[(gid)     * 66 + col0]     = C2[0] + sx1[(gid)     * XST + col0];
        sval[(gid)     * 66 + col0 + 1] = C2[1] + sx1[(gid)     * XST + col0 + 1];
        sval[(gid + 8) * 66 + col0]     = C2[2] + sx1[(gid + 8) * XST + col0];
        sval[(gid + 8) * 66 + col0 + 1] = C2[3] + sx1[(gid + 8) * XST + col0 + 1];
    }
    __syncthreads();

    // LN2 -> g_x and sx1
    {
        int tA = 2 * wid, tB = 2 * wid + 1;
        float a0 = sval[tA * 66 + lane],      a1 = sval[tA * 66 + lane + 32];
        float b0 = sval[tB * 66 + lane],      b1 = sval[tB * 66 + lane + 32];
        float sA1 = a0 + a1, sA2 = a0 * a0 + a1 * a1;
        float sB1 = b0 + b1, sB2 = b0 * b0 + b1 * b1;
        #pragma unroll
        for (int off = 16; off > 0; off >>= 1) {
            sA1 += __shfl_xor_sync(0xffffffff, sA1, off);
            sA2 += __shfl_xor_sync(0xffffffff, sA2, off);
            sB1 += __shfl_xor_sync(0xffffffff, sB1, off);
            sB2 += __shfl_xor_sync(0xffffffff, sB2, off);
        }
        float mA = sA1 * (1.f / 64.f), vA = sA2 * (1.f / 64.f) - mA * mA;
        float mB = sB1 * (1.f / 64.f), vB = sB2 * (1.f / 64.f) - mB * mB;
        float rA = rsqrtf(vA + LN_EPS), rB = rsqrtf(vB + LN_EPS);
        float w0 = ln2w[l * HID + lane],      w1v = ln2w[l * HID + lane + 32];
        float bb0 = ln2b[l * HID + lane],     bb1 = ln2b[l * HID + lane + 32];
        float oA0 = (a0 - mA) * rA * w0  + bb0;
        float oA1 = (a1 - mA) * rA * w1v + bb1;
        float oB0 = (b0 - mB) * rB * w0  + bb0;
        float oB1 = (b1 - mB) * rB * w1v + bb1;
        sx1[tA * XST + lane]      = oA0;
        sx1[tA * XST + lane + 32] = oA1;
        sx1[tB * XST + lane]      = oB0;
        sx1[tB * XST + lane + 32] = oB1;
        size_t gb = (size_t)(tok0 + tA) * HID;
        g_x[gb + lane]            = oA0;
        g_x[gb + lane + 32]       = oA1;
        g_x[gb + HID + lane]      = oB0;
        g_x[gb + HID + lane + 32] = oB1;
    }
    __syncthreads();

    if (do_qkv && t < 192) {
        const float4* wr = (const float4*)(qkv_w + ((size_t)(l + 1) * 192 + t) * HID);
        float bi = qkv_b[(l + 1) * 192 + t];
        float acc[16];
        #pragma unroll
        for (int j = 0; j < 16; j++) acc[j] = bi;
        const float4* a = (const float4*)sx1;
        #pragma unroll
        for (int k = 0; k < HID / 4; k++) {
            float4 wt = ldg4(wr + k);
            #pragma unroll
            for (int j = 0; j < 16; j++) acc[j] += dot4(a[j * (XST / 4) + k], wt);
        }
        int kind = t >> 6, w_ = t & 63, h = w_ >> 4, d = w_ & 15;
        size_t base = (((size_t)b * NH + h) * NN + n0) * HD + d;
        if (kind == 0) {
            #pragma unroll
            for (int j = 0; j < 16; j++) g_q[base + (size_t)j * HD] = acc[j] * 0.25f;
        } else {
            uint2* dst = (kind == 1) ? g_khl : g_vhl;
            #pragma unroll
            for (int j = 0; j < 16; j++) {
                unsigned hi, lo;
                tf32split(acc[j], hi, lo);
                dst[base + (size_t)j * HD] = make_uint2(hi, lo);
            }
        }
    }
}

// ============================================================
// 4. Output head body (templated), merged kernel
// ============================================================
template<int SEG>
__device__ __forceinline__ void out_body(
        float* sx, float* sh, float (*red)[16],
        int tok0, float* __restrict__ out,
        const float* __restrict__ ow1, const float* __restrict__ ob1,
        const float* __restrict__ b2) {
    constexpr int F  = 64 << SEG;
    constexpr int NT = F / 64;
    constexpr int WOFF = (SEG == 0) ? 0 : (SEG == 1) ? 8192 : (SEG == 2) ? 24576 : 57344;
    int t = threadIdx.x;
    int w = t >> 5, lane = t & 31;
    int gid = lane >> 2, tig = lane & 3;

    for (int idx = t; idx < 16 * HID; idx += 256)
        sx[idx] = g_x[(size_t)tok0 * HID + idx];
    __syncthreads();

    {
        int rep = t >> 7, h = t & 127;
        const float4* wr = (const float4*)(ow1 + ((size_t)SEG * MLPH + h) * HID);
        float bi = ob1[SEG * MLPH + h];
        float acc[8];
        #pragma unroll
        for (int j = 0; j < 8; j++) acc[j] = bi;
        const float4* a = (const float4*)sx + (rep * 8) * (HID / 4);
        #pragma unroll
        for (int k = 0; k < HID / 4; k++) {
            float4 wt = ldg4(wr + k);
            #pragma unroll
            for (int j = 0; j < 8; j++) acc[j] += dot4(a[j * (HID / 4) + k], wt);
        }
        #pragma unroll
        for (int j = 0; j < 8; j++) sh[(rep * 8 + j) * SHP + h] = tanhf(acc[j]);
    }
    __syncthreads();

    {
        float C[NT][4];
        #pragma unroll
        for (int j = 0; j < NT; j++) {
            int col0 = (w + j * 8) * 8 + 2 * tig;
            C[j][0] = C[j][2] = b2[col0];
            C[j][1] = C[j][3] = b2[col0 + 1];
        }
        const uint2* w2a = g_w2hl + WOFF;
        #pragma unroll 2
        for (int ks = 0; ks < 16; ks++) {
            int k0 = ks * 8;
            unsigned ab[4], as[4];
            tf32split(sh[(gid)     * SHP + k0 + tig],     ab[0], as[0]);
            tf32split(sh[(gid + 8) * SHP + k0 + tig],     ab[1], as[1]);
            tf32split(sh[(gid)     * SHP + k0 + tig + 4], ab[2], as[2]);
            tf32split(sh[(gid + 8) * SHP + k0 + tig + 4], ab[3], as[3]);
            #pragma unroll
            for (int j = 0; j < NT; j++) {
                int nb = (w + j * 8) * 8 + gid;
                uint2 b0 = w2a[nb * MLPH + k0 + tig];
                uint2 b1 = w2a[nb * MLPH + k0 + tig + 4];
                mma_tf32(C[j], ab, b0.x, b1.x);
                mma_tf32(C[j], ab, b0.y, b1.y);
                mma_tf32(C[j], as, b0.x, b1.x);
            }
        }

        float sqA = 0.f, sqB = 0.f;
        #pragma unroll
        for (int j = 0; j < NT; j++) {
            int col0 = (w + j * 8) * 8 + 2 * tig;
            *(float2*)&out[(size_t)(tok0 + gid)     * MAXF + col0] = make_float2(C[j][0], C[j][1]);
            *(float2*)&out[(size_t)(tok0 + gid + 8) * MAXF + col0] = make_float2(C[j][2], C[j][3]);
            sqA += C[j][0] * C[j][0] + C[j][1] * C[j][1];
            sqB += C[j][2] * C[j][2] + C[j][3] * C[j][3];
        }
        sqA += __shfl_xor_sync(0xffffffff, sqA, 1);
        sqA += __shfl_xor_sync(0xffffffff, sqA, 2);
        sqB += __shfl_xor_sync(0xffffffff, sqB, 1);
        sqB += __shfl_xor_sync(0xffffffff, sqB, 2);
        if (tig == 0) { red[w][gid] = sqA; red[w][gid + 8] = sqB; }
    }

    if (SEG < 3) {
        constexpr int PADW = (MAXF - F) / 4;
        float4 z = make_float4(0.f, 0.f, 0.f, 0.f);
        for (int i = t; i < 16 * PADW; i += 256) {
            int r = i / PADW, c = i - r * PADW;
            *((float4*)&out[(size_t)(tok0 + r) * MAXF + F] + c) = z;
        }
    }
    __syncthreads();
    if (t < 16) {
        float s = 0.f;
        #pragma unroll
        for (int ww = 0; ww < 8; ww++) s += red[ww][t];
        g_esum[tok0 + t] = s;
    }
}

__global__ __launch_bounds__(256) void k_out_all(float* __restrict__ out,
        const float* __restrict__ ow1, const float* __restrict__ ob1,
        const float* __restrict__ b2_0, const float* __restrict__ b2_1,
        const float* __restrict__ b2_2, const float* __restrict__ b2_3) {
    __shared__ __align__(16) float sx[16 * HID];
    __shared__ __align__(16) float sh[16 * SHP];
    __shared__ float red[8][16];
    int tok0 = blockIdx.x * 16;
    int seg = (tok0 & 1023) >> 8;
    switch (seg) {
        case 0: out_body<0>(sx, sh, red, tok0, out, ow1, ob1, b2_0); break;
        case 1: out_body<1>(sx, sh, red, tok0, out, ow1, ob1, b2_1); break;
        case 2: out_body<2>(sx, sh, red, tok0, out, ow1, ob1, b2_2); break;
        default: out_body<3>(sx, sh, red, tok0, out, ow1, ob1, b2_3); break;
    }
}

// ============================================================
// 5. Energy reduce
// ============================================================
__global__ void k_energy(float* __restrict__ e) {
    __shared__ float red[4];
    int b = blockIdx.x;
    int t = threadIdx.x;
    float s = 0.f;
    for (int i = t; i < NN; i += 128) s += g_esum[b * NN + i];
    #pragma unroll
    for (int off = 16; off > 0; off >>= 1) s += __shfl_xor_sync(0xffffffff, s, off);
    if ((t & 31) == 0) red[t >> 5] = s;
    __syncthreads();
    if (t == 0) e[b] = 0.5f * (red[0] + red[1] + red[2] + red[3]);
}

// ============================================================
extern "C" void kernel_launch(void* const* d_in, const int* in_sizes, int n_in,
                              void* d_out, int out_size) {
    const float* y      = (const float*)d_in[1];
    const float* in_w1_0 = (const float*)d_in[3];
    const float* in_w1_1 = (const float*)d_in[4];
    const float* in_w1_2 = (const float*)d_in[5];
    const float* in_w1_3 = (const float*)d_in[6];
    const float* out_w2_0 = (const float*)d_in[7];
    const float* out_w2_1 = (const float*)d_in[8];
    const float* out_w2_2 = (const float*)d_in[9];
    const float* out_w2_3 = (const float*)d_in[10];
    const float* out_b2_0 = (const float*)d_in[11];
    const float* out_b2_1 = (const float*)d_in[12];
    const float* out_b2_2 = (const float*)d_in[13];
    const float* out_b2_3 = (const float*)d_in[14];
    const float* in_b1  = (const float*)d_in[15];
    const float* in_w2  = (const float*)d_in[16];
    const float* in_b2  = (const float*)d_in[17];
    const float* out_w1 = (const float*)d_in[18];
    const float* out_b1 = (const float*)d_in[19];
    const float* qkv_w  = (const float*)d_in[20];
    const float* qkv_b  = (const float*)d_in[21];
    const float* attn_out_w = (const float*)d_in[22];
    const float* attn_out_b = (const float*)d_in[23];
    const float* ln1_w  = (const float*)d_in[24];
    const float* ln1_b  = (const float*)d_in[25];
    const float* ffn_w1 = (const float*)d_in[26];
    const float* ffn_b1 = (const float*)d_in[27];
    const float* ffn_w2 = (const float*)d_in[28];
    const float* ffn_b2 = (const float*)d_in[29];
    const float* ln2_w  = (const float*)d_in[30];
    const float* ln2_b  = (const float*)d_in[31];

    float* out = (float*)d_out;
    float* energy = out + (size_t)BB * NN * MAXF;

    const int NB = (BB * NN) / 16;   // 1024

    k_presplit<<<480, 256>>>(in_w1_0, in_w1_1, in_w1_2, in_w1_3,
                             out_w2_0, out_w2_1, out_w2_2, out_w2_3);
    k_presplit2<<<128, 256>>>(ffn_w1, ffn_w2);

    k_input_all<<<NB, 256>>>(y, in_b1, in_w2, in_b2, qkv_w, qkv_b);

    k_attn<<<BB * NH * 16, 128>>>();
    k_pfq<<<NB, 256>>>(0, 1, attn_out_w, attn_out_b, ln1_w, ln1_b,
                       ffn_b1, ffn_b2, ln2_w, ln2_b, qkv_w, qkv_b);
    k_attn<<<BB * NH * 16, 128>>>();
    k_pfq<<<NB, 256>>>(1, 0, attn_out_w, attn_out_b, ln1_w, ln1_b,
                       ffn_b1, ffn_b2, ln2_w, ln2_b, qkv_w, qkv_b);

    k_out_all<<<NB, 256>>>(out, out_w1, out_b1,
                           out_b2_0, out_b2_1, out_b2_2, out_b2_3);

    k_energy<<<BB, 128>>>(energy);
}